// round 2
// baseline (speedup 1.0000x reference)
#include <cuda_runtime.h>
#include <math.h>

#define N_TOK  16384
#define IN_DIM 1024
#define HID    2048
#define NEXP   8

// Scratch (device globals: allocation-free per harness rules)
__device__ float g_h[(size_t)N_TOK * HID];   // encoded activations
__device__ float g_u[(size_t)N_TOK * HID];   // blended pre-decoder
__device__ int   g_perm[NEXP * N_TOK];       // token ids bucketed by expert
__device__ int   g_counts[NEXP];
__device__ float g_s0[N_TOK];                // coef0 * gate_prob
__device__ float g_s1[N_TOK];                // coef1

__global__ void zero_counts_kernel() {
    if (threadIdx.x < NEXP) g_counts[threadIdx.x] = 0;
}

// ---------------------------------------------------------------------------
// Generic 128x128x8 SIMT fp32 GEMM, 256 threads, 8x8 per thread.
// MODE 0: C = relu(A@B + bias)
// MODE 1: C = (A@B + bias) * rowscale[row]
// MODE 2: C = A@B + bias
// ---------------------------------------------------------------------------
template <int MODE>
__global__ __launch_bounds__(256)
void sgemm128(const float* __restrict__ A, const float* __restrict__ B,
              const float* __restrict__ bias, float* __restrict__ C,
              int M, int N, int K, const float* __restrict__ rowscale)
{
    const int BM = 128, BN = 128, BK = 8, TM = 8, TN = 8;
    __shared__ float As[BK][BM];
    __shared__ float Bs[BK][BN];

    const int tid = threadIdx.x;
    const int bx = blockIdx.x;   // N tile
    const int by = blockIdx.y;   // M tile

    const int threadCol = tid % (BN / TN);  // 0..15
    const int threadRow = tid / (BN / TN);  // 0..15

    const float* Ab = A + (size_t)by * BM * K;
    const float* Bb = B + (size_t)bx * BN;
    float*       Cb = C + (size_t)by * BM * N + (size_t)bx * BN;

    const int innerRowA = tid >> 1;          // 0..127
    const int innerColA = (tid & 1) * 4;     // 0 or 4
    const int innerRowB = tid >> 5;          // 0..7
    const int innerColB = (tid & 31) * 4;    // 0..124

    float acc[TM][TN] = {};
    float regM[TM], regN[TN];

    for (int kt = 0; kt < K; kt += BK) {
        float4 a4 = *(const float4*)(Ab + (size_t)innerRowA * K + kt + innerColA);
        As[innerColA + 0][innerRowA] = a4.x;
        As[innerColA + 1][innerRowA] = a4.y;
        As[innerColA + 2][innerRowA] = a4.z;
        As[innerColA + 3][innerRowA] = a4.w;
        *(float4*)(&Bs[innerRowB][innerColB]) =
            *(const float4*)(Bb + (size_t)(kt + innerRowB) * N + innerColB);
        __syncthreads();

        #pragma unroll
        for (int k = 0; k < BK; k++) {
            #pragma unroll
            for (int i = 0; i < TM; i++) regM[i] = As[k][threadRow * TM + i];
            #pragma unroll
            for (int j = 0; j < TN; j++) regN[j] = Bs[k][threadCol * TN + j];
            #pragma unroll
            for (int i = 0; i < TM; i++)
                #pragma unroll
                for (int j = 0; j < TN; j++)
                    acc[i][j] += regM[i] * regN[j];
        }
        __syncthreads();
    }

    #pragma unroll
    for (int i = 0; i < TM; i++) {
        const int row = threadRow * TM + i;
        float rs = 1.0f;
        if (MODE == 1) rs = rowscale[by * BM + row];
        #pragma unroll
        for (int j = 0; j < TN; j += 4) {
            const int col = threadCol * TN + j;
            float4 b4 = *(const float4*)(bias + (size_t)bx * BN + col);
            float4 v;
            v.x = acc[i][j + 0] + b4.x;
            v.y = acc[i][j + 1] + b4.y;
            v.z = acc[i][j + 2] + b4.z;
            v.w = acc[i][j + 3] + b4.w;
            if (MODE == 0) {
                v.x = fmaxf(v.x, 0.0f); v.y = fmaxf(v.y, 0.0f);
                v.z = fmaxf(v.z, 0.0f); v.w = fmaxf(v.w, 0.0f);
            }
            if (MODE == 1) { v.x *= rs; v.y *= rs; v.z *= rs; v.w *= rs; }
            *(float4*)(Cb + (size_t)row * N + col) = v;
        }
    }
}

// ---------------------------------------------------------------------------
// Grouped expert GEMM: rows gathered via g_perm bucket for expert blockIdx.z.
// C[tok] += (A[tok] @ W_e + b_e) * g_s0[tok]
// ---------------------------------------------------------------------------
__global__ __launch_bounds__(256)
void sgemm128_grouped(const float* __restrict__ A,      // g_h [N_TOK, HID]
                      const float* __restrict__ Wexp,   // [E, HID, HID]
                      const float* __restrict__ bexp,   // [E, HID]
                      float* __restrict__ C)            // g_u accumulate
{
    const int BM = 128, BN = 128, BK = 8, TM = 8, TN = 8;
    const int e   = blockIdx.z;
    const int cnt = g_counts[e];
    const int by  = blockIdx.y;
    const int rowBase = by * BM;
    if (rowBase >= cnt) return;

    __shared__ int   rowmap[BM];
    __shared__ float As[BK][BM];
    __shared__ float Bs[BK][BN];

    const int tid = threadIdx.x;
    const int bx  = blockIdx.x;

    if (tid < BM) {
        int i = rowBase + tid;
        if (i > cnt - 1) i = cnt - 1;      // clamp (stores guarded below)
        rowmap[tid] = g_perm[e * N_TOK + i];
    }
    __syncthreads();

    const int threadCol = tid % (BN / TN);
    const int threadRow = tid / (BN / TN);

    const float* Bb = Wexp + (size_t)e * HID * HID + (size_t)bx * BN;
    const float* bb = bexp + (size_t)e * HID + (size_t)bx * BN;

    const int innerRowA = tid >> 1;
    const int innerColA = (tid & 1) * 4;
    const int innerRowB = tid >> 5;
    const int innerColB = (tid & 31) * 4;

    const int aRow = rowmap[innerRowA];

    float acc[TM][TN] = {};
    float regM[TM], regN[TN];

    for (int kt = 0; kt < HID; kt += BK) {
        float4 a4 = *(const float4*)(A + (size_t)aRow * HID + kt + innerColA);
        As[innerColA + 0][innerRowA] = a4.x;
        As[innerColA + 1][innerRowA] = a4.y;
        As[innerColA + 2][innerRowA] = a4.z;
        As[innerColA + 3][innerRowA] = a4.w;
        *(float4*)(&Bs[innerRowB][innerColB]) =
            *(const float4*)(Bb + (size_t)(kt + innerRowB) * HID + innerColB);
        __syncthreads();

        #pragma unroll
        for (int k = 0; k < BK; k++) {
            #pragma unroll
            for (int i = 0; i < TM; i++) regM[i] = As[k][threadRow * TM + i];
            #pragma unroll
            for (int j = 0; j < TN; j++) regN[j] = Bs[k][threadCol * TN + j];
            #pragma unroll
            for (int i = 0; i < TM; i++)
                #pragma unroll
                for (int j = 0; j < TN; j++)
                    acc[i][j] += regM[i] * regN[j];
        }
        __syncthreads();
    }

    #pragma unroll
    for (int i = 0; i < TM; i++) {
        const int li = threadRow * TM + i;          // local row in tile
        if (rowBase + li >= cnt) continue;          // padding row: skip store
        const int tok = rowmap[li];
        const float rs = g_s0[tok];
        #pragma unroll
        for (int j = 0; j < TN; j += 4) {
            const int col = blockIdx.x * BN + threadCol * TN + j;
            float4 b4  = *(const float4*)(bb + threadCol * TN + j);
            float4 old = *(const float4*)(C + (size_t)tok * HID + col);
            float4 v;
            v.x = old.x + (acc[i][j + 0] + b4.x) * rs;
            v.y = old.y + (acc[i][j + 1] + b4.y) * rs;
            v.z = old.z + (acc[i][j + 2] + b4.z) * rs;
            v.w = old.w + (acc[i][j + 3] + b4.w) * rs;
            *(float4*)(C + (size_t)tok * HID + col) = v;
        }
    }
}

// ---------------------------------------------------------------------------
// Gating: per token, 10 dot products over HID (8 gate logits + 2 coef logits),
// softmax both, argmax expert (first-max like jnp.argmax), atomic bucket.
// ---------------------------------------------------------------------------
__global__ __launch_bounds__(128)
void gating_kernel(const float* __restrict__ h,
                   const float* __restrict__ gate_W,   // [HID, 8]
                   const float* __restrict__ coef_W,   // [HID, 2]
                   const float* __restrict__ coef_b)   // [2]
{
    const int n = blockIdx.x;
    const int t = threadIdx.x;
    float acc[10];
    #pragma unroll
    for (int j = 0; j < 10; j++) acc[j] = 0.0f;

    const float* hr = h + (size_t)n * HID;
    for (int k = t; k < HID; k += 128) {
        const float hv = hr[k];
        #pragma unroll
        for (int j = 0; j < 8; j++) acc[j] += hv * gate_W[k * 8 + j];
        acc[8] += hv * coef_W[k * 2 + 0];
        acc[9] += hv * coef_W[k * 2 + 1];
    }

    #pragma unroll
    for (int j = 0; j < 10; j++)
        #pragma unroll
        for (int o = 16; o > 0; o >>= 1)
            acc[j] += __shfl_down_sync(0xffffffffu, acc[j], o);

    __shared__ float red[4][10];
    const int warp = t >> 5, lane = t & 31;
    if (lane == 0) {
        #pragma unroll
        for (int j = 0; j < 10; j++) red[warp][j] = acc[j];
    }
    __syncthreads();

    if (t == 0) {
        float v[10];
        #pragma unroll
        for (int j = 0; j < 10; j++)
            v[j] = red[0][j] + red[1][j] + red[2][j] + red[3][j];

        // gate: argmax (first-max) + softmax prob of the max
        float lmax = v[0]; int idx = 0;
        #pragma unroll
        for (int j = 1; j < 8; j++)
            if (v[j] > lmax) { lmax = v[j]; idx = j; }
        float s = 0.0f;
        #pragma unroll
        for (int j = 0; j < 8; j++) s += expf(v[j] - lmax);
        const float gate = 1.0f / s;

        // 2-way coef softmax
        const float c0 = v[8] + coef_b[0];
        const float c1 = v[9] + coef_b[1];
        const float cm = fmaxf(c0, c1);
        const float e0 = expf(c0 - cm), e1 = expf(c1 - cm);
        const float inv = 1.0f / (e0 + e1);

        g_s0[n] = gate * e0 * inv;   // coef0 * gate
        g_s1[n] = e1 * inv;          // coef1

        const int pos = atomicAdd(&g_counts[idx], 1);
        g_perm[idx * N_TOK + pos] = n;
    }
}

// ---------------------------------------------------------------------------
extern "C" void kernel_launch(void* const* d_in, const int* in_sizes, int n_in,
                              void* d_out, int out_size)
{
    const float* x        = (const float*)d_in[0];
    const float* enc_W    = (const float*)d_in[1];
    const float* enc_b    = (const float*)d_in[2];
    const float* gate_W   = (const float*)d_in[3];
    const float* expert_W = (const float*)d_in[4];
    const float* expert_b = (const float*)d_in[5];
    const float* res_W    = (const float*)d_in[6];
    const float* res_b    = (const float*)d_in[7];
    const float* coef_W   = (const float*)d_in[8];
    const float* coef_b   = (const float*)d_in[9];
    const float* dec_W    = (const float*)d_in[10];
    const float* dec_b    = (const float*)d_in[11];
    float* out = (float*)d_out;

    float *hp, *up, *s1p;
    cudaGetSymbolAddress((void**)&hp,  g_h);
    cudaGetSymbolAddress((void**)&up,  g_u);
    cudaGetSymbolAddress((void**)&s1p, g_s1);

    zero_counts_kernel<<<1, 32>>>();

    // h = relu(x @ enc_W + enc_b)   [16384 x 2048]
    sgemm128<0><<<dim3(HID / 128, N_TOK / 128), 256>>>(
        x, enc_W, enc_b, hp, N_TOK, HID, IN_DIM, nullptr);

    // gating: idx, s0 = coef0*gate, s1 = coef1, expert buckets
    gating_kernel<<<N_TOK, 128>>>(hp, gate_W, coef_W, coef_b);

    // u = (h @ res_W + res_b) * s1
    sgemm128<1><<<dim3(HID / 128, N_TOK / 128), 256>>>(
        hp, res_W, res_b, up, N_TOK, HID, HID, s1p);

    // u += (h @ W_e + b_e) * s0   (grouped top-1 expert dispatch)
    sgemm128_grouped<<<dim3(HID / 128, N_TOK / 128, NEXP), 256>>>(
        hp, expert_W, expert_b, up);

    // out = u @ dec_W + dec_b     [16384 x 1024]
    sgemm128<2><<<dim3(IN_DIM / 128, N_TOK / 128), 256>>>(
        up, dec_W, dec_b, out, N_TOK, IN_DIM, HID, nullptr);
}

// round 5
// speedup vs baseline: 2.5925x; 2.5925x over previous
#include <cuda_runtime.h>
#include <cuda_fp16.h>
#include <cuda.h>
#include <cstdint>
#include <math.h>

#define N_TOK  16384
#define IN_DIM 1024
#define HID    2048
#define NEXP   8

// ---- device scratch (globals: allocation-free) ----
__device__ __align__(128) __half g_xhi[(size_t)N_TOK * IN_DIM];
__device__ __align__(128) __half g_xlo[(size_t)N_TOK * IN_DIM];
__device__ __align__(128) __half g_hhi[(size_t)N_TOK * HID];
__device__ __align__(128) __half g_hlo[(size_t)N_TOK * HID];
__device__ __align__(128) __half g_uhi[(size_t)N_TOK * HID];
__device__ __align__(128) __half g_ulo[(size_t)N_TOK * HID];
__device__ __align__(128) float  g_u[(size_t)N_TOK * HID];

#define W_ENC_OFF 0
#define W_RES_OFF (2048*1024)
#define W_EXP_OFF (W_RES_OFF + 2048*2048)
#define W_DEC_OFF (W_EXP_OFF + 8*2048*2048)
#define W_TOTAL   (W_DEC_OFF + 1024*2048)
__device__ __align__(128) __half g_Whi[(size_t)W_TOTAL];
__device__ __align__(128) __half g_Wlo[(size_t)W_TOTAL];

__device__ int   g_perm[NEXP * N_TOK];
__device__ int   g_counts[NEXP];
__device__ float g_s0[N_TOK];
__device__ float g_s1[N_TOK];

// ---- SMEM layout: 3 stages x (Ah,Al,Bh,Bl each 8KB) = 96KB, + rowmap ----
#define STG_BYTES 32768
#define OFF_AH 0
#define OFF_AL 8192
#define OFF_BH 16384
#define OFF_BL 24576
#define SM_RMAP (3 * STG_BYTES)
#define SMEM_TOT (3 * STG_BYTES + 512)

// ---- PTX helpers ----
__device__ __forceinline__ uint32_t smem_u32(const void* p) {
    uint32_t r;
    asm("{ .reg .u64 t; cvta.to.shared.u64 t, %1; cvt.u32.u64 %0, t; }" : "=r"(r) : "l"(p));
    return r;
}
__device__ __forceinline__ void cp16(uint32_t s, const void* g) {
    asm volatile("cp.async.cg.shared.global [%0], [%1], 16;" :: "r"(s), "l"(g));
}
#define CP_COMMIT() asm volatile("cp.async.commit_group;" ::: "memory")
#define CP_WAIT(n)  asm volatile("cp.async.wait_group %0;" :: "n"(n) : "memory")

__device__ __forceinline__ void ldsm4(uint32_t* r, uint32_t a) {
    asm volatile("ldmatrix.sync.aligned.m8n8.x4.shared.b16 {%0,%1,%2,%3}, [%4];"
                 : "=r"(r[0]), "=r"(r[1]), "=r"(r[2]), "=r"(r[3]) : "r"(a));
}
__device__ __forceinline__ void mma16816(float* c, const uint32_t* a, const uint32_t* b) {
    asm volatile(
        "mma.sync.aligned.m16n8k16.row.col.f32.f16.f16.f32 "
        "{%0,%1,%2,%3}, {%4,%5,%6,%7}, {%8,%9}, {%0,%1,%2,%3};"
        : "+f"(c[0]), "+f"(c[1]), "+f"(c[2]), "+f"(c[3])
        : "r"(a[0]), "r"(a[1]), "r"(a[2]), "r"(a[3]), "r"(b[0]), "r"(b[1]));
}

// conflict-free swizzle for 64B rows read via ldmatrix (16B chunks)
__device__ __forceinline__ uint32_t swz(int row, int chunk) {
    return (uint32_t)(row * 64 + ((chunk ^ ((row >> 1) & 3)) * 16));
}

__device__ __forceinline__ void splitf(float v, __half& h, __half& l) {
    h = __float2half_rn(v);
    l = __float2half_rn(v - __half2float(h));
}

// ---- small kernels ----
__global__ void zero_counts_kernel() {
    if (threadIdx.x < NEXP) g_counts[threadIdx.x] = 0;
}

__global__ __launch_bounds__(256) void conv_x_kernel(const float* __restrict__ x) {
    size_t i = ((size_t)blockIdx.x * 256 + threadIdx.x) * 4;
    float4 v = *(const float4*)(x + i);
    __half hb[4], lb[4];
    splitf(v.x, hb[0], lb[0]); splitf(v.y, hb[1], lb[1]);
    splitf(v.z, hb[2], lb[2]); splitf(v.w, hb[3], lb[3]);
    *(uint2*)(g_xhi + i) = *(uint2*)hb;
    *(uint2*)(g_xlo + i) = *(uint2*)lb;
}

// src [K,N] fp32 (batched over z) -> dst [N,K] fp16 hi/lo
__global__ __launch_bounds__(256)
void transpose_conv(const float* __restrict__ src, __half* __restrict__ dhi,
                    __half* __restrict__ dlo, int K, int N)
{
    __shared__ float t[32][33];
    const size_t zoff = (size_t)blockIdx.z * K * N;
    const int n0 = blockIdx.x * 32, k0 = blockIdx.y * 32;
    const int tx = threadIdx.x, ty = threadIdx.y;
    #pragma unroll
    for (int i = 0; i < 4; i++) {
        t[ty + i*8][tx] = src[zoff + (size_t)(k0 + ty + i*8) * N + n0 + tx];
    }
    __syncthreads();
    #pragma unroll
    for (int i = 0; i < 4; i++) {
        const int n = n0 + ty + i*8, k = k0 + tx;
        __half h, l;
        splitf(t[tx][ty + i*8], h, l);
        dhi[zoff + (size_t)n * K + k] = h;
        dlo[zoff + (size_t)n * K + k] = l;
    }
}

// ---- gating ----
__global__ __launch_bounds__(128)
void gating_kernel(const float* __restrict__ gate_W, const float* __restrict__ coef_W,
                   const float* __restrict__ coef_b)
{
    const int n = blockIdx.x;
    const int t = threadIdx.x;
    float acc[10];
    #pragma unroll
    for (int j = 0; j < 10; j++) { acc[j] = 0.0f; }

    const __half* hh = g_hhi + (size_t)n * HID;
    const __half* hl = g_hlo + (size_t)n * HID;
    for (int k = t; k < HID; k += 128) {
        const float hv = __half2float(hh[k]) + __half2float(hl[k]);
        #pragma unroll
        for (int j = 0; j < 8; j++) { acc[j] += hv * gate_W[k * 8 + j]; }
        acc[8] += hv * coef_W[k * 2 + 0];
        acc[9] += hv * coef_W[k * 2 + 1];
    }
    #pragma unroll
    for (int j = 0; j < 10; j++) {
        #pragma unroll
        for (int o = 16; o > 0; o >>= 1) {
            acc[j] += __shfl_down_sync(0xffffffffu, acc[j], o);
        }
    }

    __shared__ float red[4][10];
    const int warp = t >> 5, lane = t & 31;
    if (lane == 0) {
        #pragma unroll
        for (int j = 0; j < 10; j++) { red[warp][j] = acc[j]; }
    }
    __syncthreads();

    if (t == 0) {
        float v[10];
        #pragma unroll
        for (int j = 0; j < 10; j++) {
            v[j] = red[0][j] + red[1][j] + red[2][j] + red[3][j];
        }
        float lmax = v[0]; int idx = 0;
        #pragma unroll
        for (int j = 1; j < 8; j++) {
            if (v[j] > lmax) { lmax = v[j]; idx = j; }
        }
        float s = 0.0f;
        #pragma unroll
        for (int j = 0; j < 8; j++) { s += expf(v[j] - lmax); }
        const float gate = 1.0f / s;
        const float c0 = v[8] + coef_b[0];
        const float c1 = v[9] + coef_b[1];
        const float cm = fmaxf(c0, c1);
        const float e0 = expf(c0 - cm), e1 = expf(c1 - cm);
        const float inv = 1.0f / (e0 + e1);
        g_s0[n] = gate * e0 * inv;
        g_s1[n] = e1 * inv;
        const int pos = atomicAdd(&g_counts[idx], 1);
        g_perm[idx * N_TOK + pos] = n;
    }
}

// ---------------------------------------------------------------------------
// HMMA split-fp16 GEMM. CTA 128x128, BK=32, 8 warps (2x4), warp tile 64x32.
// 3 passes: Ah*Bh + Ah*Bl + Al*Bh. 3-stage cp.async pipeline.
// MODE 0: relu(acc+bias) -> split Chi/Clo ; MODE 1: (acc+bias)*rowscale -> Cf
// MODE 2: acc+bias -> Cf
// ---------------------------------------------------------------------------
template <int MODE>
__global__ __launch_bounds__(256, 1)
void hmma_gemm(const __half* __restrict__ Ahi, const __half* __restrict__ Alo,
               const __half* __restrict__ Bhi, const __half* __restrict__ Blo,
               const float* __restrict__ bias, int K, int Nn,
               __half* __restrict__ Chi, __half* __restrict__ Clo,
               float* __restrict__ Cf, const float* __restrict__ rowscale)
{
    extern __shared__ __align__(1024) char smem[];
    const uint32_t sb = smem_u32(smem);
    const int tid = threadIdx.x;
    const int lane = tid & 31, wid = tid >> 5;
    const int wm = wid >> 2, wn = wid & 3;           // 2 x 4 warp grid
    const int mrow0 = blockIdx.y * 128;
    const int ncol0 = blockIdx.x * 128;
    const int nt = K / 32;

    // per-thread load coords (2 chunks per array)
    const int r0 = tid >> 2, c0 = tid & 3;           // rows 0..63
    const int r1 = (tid + 256) >> 2, c1 = tid & 3;   // rows 64..127
    const uint32_t sw0 = swz(r0, c0), sw1 = swz(r1, c1);

    #define LOADT(s, kt) do {                                                    \
        const uint32_t st_ = sb + (uint32_t)(s) * STG_BYTES;                      \
        const size_t ka_ = (size_t)(kt) * 32 + c0 * 8;                           \
        const size_t kb_ = (size_t)(kt) * 32 + c1 * 8;                           \
        cp16(st_ + OFF_AH + sw0, Ahi + (size_t)(mrow0 + r0) * K + ka_);          \
        cp16(st_ + OFF_AH + sw1, Ahi + (size_t)(mrow0 + r1) * K + kb_);          \
        cp16(st_ + OFF_AL + sw0, Alo + (size_t)(mrow0 + r0) * K + ka_);          \
        cp16(st_ + OFF_AL + sw1, Alo + (size_t)(mrow0 + r1) * K + kb_);          \
        cp16(st_ + OFF_BH + sw0, Bhi + (size_t)(ncol0 + r0) * K + ka_);          \
        cp16(st_ + OFF_BH + sw1, Bhi + (size_t)(ncol0 + r1) * K + kb_);          \
        cp16(st_ + OFF_BL + sw0, Blo + (size_t)(ncol0 + r0) * K + ka_);          \
        cp16(st_ + OFF_BL + sw1, Blo + (size_t)(ncol0 + r1) * K + kb_);          \
        CP_COMMIT();                                                              \
    } while (0)

    LOADT(0, 0);
    LOADT(1, 1);

    float acc[4][4][4];
    #pragma unroll
    for (int i = 0; i < 4; i++) {
        #pragma unroll
        for (int j = 0; j < 4; j++) {
            #pragma unroll
            for (int q = 0; q < 4; q++) { acc[i][j][q] = 0.0f; }
        }
    }

    // ldmatrix per-lane coords
    const int arow = (lane & 7) | (((lane >> 3) & 1) << 3);
    const int ach  = lane >> 4;
    const int brow = (lane & 7) | (((lane >> 4) & 1) << 3);
    const int bch  = (lane >> 3) & 1;

    for (int kt = 0; kt < nt; kt++) {
        if (kt + 1 < nt) { CP_WAIT(1); } else { CP_WAIT(0); }
        __syncthreads();
        if (kt + 2 < nt) { LOADT((kt + 2) % 3, kt + 2); }

        const uint32_t st = sb + (uint32_t)(kt % 3) * STG_BYTES;
        #pragma unroll
        for (int s16 = 0; s16 < 2; s16++) {
            uint32_t ah[4][4], al[4][4], bh[2][4], bl[2][4];
            #pragma unroll
            for (int i = 0; i < 4; i++) {
                const uint32_t a = swz(wm * 64 + i * 16 + arow, s16 * 2 + ach);
                ldsm4(ah[i], st + OFF_AH + a);
                ldsm4(al[i], st + OFF_AL + a);
            }
            #pragma unroll
            for (int j = 0; j < 2; j++) {
                const uint32_t b = swz(wn * 32 + j * 16 + brow, s16 * 2 + bch);
                ldsm4(bh[j], st + OFF_BH + b);
                ldsm4(bl[j], st + OFF_BL + b);
            }
            #pragma unroll
            for (int i = 0; i < 4; i++) {
                #pragma unroll
                for (int j = 0; j < 4; j++) {
                    mma16816(acc[i][j], ah[i], &bh[j >> 1][(j & 1) * 2]);
                    mma16816(acc[i][j], ah[i], &bl[j >> 1][(j & 1) * 2]);
                    mma16816(acc[i][j], al[i], &bh[j >> 1][(j & 1) * 2]);
                }
            }
        }
    }

    // epilogue
    #pragma unroll
    for (int i = 0; i < 4; i++) {
        const int rb = mrow0 + wm * 64 + i * 16 + (lane >> 2);
        #pragma unroll
        for (int h = 0; h < 2; h++) {
            const int row = rb + h * 8;
            const float rs = (MODE == 1) ? rowscale[row] : 0.0f;
            #pragma unroll
            for (int j = 0; j < 4; j++) {
                const int col = ncol0 + wn * 32 + j * 8 + (lane & 3) * 2;
                float v0 = acc[i][j][h * 2 + 0] + bias[col];
                float v1 = acc[i][j][h * 2 + 1] + bias[col + 1];
                if (MODE == 0) {
                    v0 = fmaxf(v0, 0.0f); v1 = fmaxf(v1, 0.0f);
                    __half h0, l0, h1, l1;
                    splitf(v0, h0, l0); splitf(v1, h1, l1);
                    *(__half2*)(Chi + (size_t)row * Nn + col) = __halves2half2(h0, h1);
                    *(__half2*)(Clo + (size_t)row * Nn + col) = __halves2half2(l0, l1);
                } else if (MODE == 1) {
                    *(float2*)(Cf + (size_t)row * Nn + col) = make_float2(v0 * rs, v1 * rs);
                } else {
                    *(float2*)(Cf + (size_t)row * Nn + col) = make_float2(v0, v1);
                }
            }
        }
    }
    #undef LOADT
}

// ---------------------------------------------------------------------------
// Grouped expert GEMM: A rows gathered via g_perm; epilogue
// uhi/ulo = split(g_u[tok] + (acc + b_e) * s0[tok]).
// ---------------------------------------------------------------------------
__global__ __launch_bounds__(256, 1)
void hmma_gemm_grouped(const float* __restrict__ bexp)
{
    extern __shared__ __align__(1024) char smem[];
    const int e = blockIdx.z;
    const int cnt = g_counts[e];
    const int rowBase = blockIdx.y * 128;
    if (rowBase >= cnt) return;

    const uint32_t sb = smem_u32(smem);
    const int tid = threadIdx.x;
    const int lane = tid & 31, wid = tid >> 5;
    const int wm = wid >> 2, wn = wid & 3;
    const int ncol0 = blockIdx.x * 128;
    const int nt = HID / 32;
    int* rmap = (int*)(smem + SM_RMAP);

    if (tid < 128) {
        int i = rowBase + tid;
        if (i > cnt - 1) i = cnt - 1;
        rmap[tid] = g_perm[e * N_TOK + i];
    }
    __syncthreads();

    const __half* Bhi = g_Whi + W_EXP_OFF + (size_t)e * HID * HID;
    const __half* Blo = g_Wlo + W_EXP_OFF + (size_t)e * HID * HID;

    const int r0 = tid >> 2, c0 = tid & 3;
    const int r1 = (tid + 256) >> 2, c1 = tid & 3;
    const uint32_t sw0 = swz(r0, c0), sw1 = swz(r1, c1);
    const size_t ga0 = (size_t)rmap[r0] * HID;
    const size_t ga1 = (size_t)rmap[r1] * HID;

    #define LOADG(s, kt) do {                                                    \
        const uint32_t st_ = sb + (uint32_t)(s) * STG_BYTES;                      \
        const size_t ka_ = (size_t)(kt) * 32 + c0 * 8;                           \
        const size_t kb_ = (size_t)(kt) * 32 + c1 * 8;                           \
        cp16(st_ + OFF_AH + sw0, g_hhi + ga0 + ka_);                             \
        cp16(st_ + OFF_AH + sw1, g_hhi + ga1 + kb_);                             \
        cp16(st_ + OFF_AL + sw0, g_hlo + ga0 + ka_);                             \
        cp16(st_ + OFF_AL + sw1, g_hlo + ga1 + kb_);                             \
        cp16(st_ + OFF_BH + sw0, Bhi + (size_t)(ncol0 + r0) * HID + ka_);        \
        cp16(st_ + OFF_BH + sw1, Bhi + (size_t)(ncol0 + r1) * HID + kb_);        \
        cp16(st_ + OFF_BL + sw0, Blo + (size_t)(ncol0 + r0) * HID + ka_);        \
        cp16(st_ + OFF_BL + sw1, Blo + (size_t)(ncol0 + r1) * HID + kb_);        \
        CP_COMMIT();                                                              \
    } while (0)

    LOADG(0, 0);
    LOADG(1, 1);

    float acc[4][4][4];
    #pragma unroll
    for (int i = 0; i < 4; i++) {
        #pragma unroll
        for (int j = 0; j < 4; j++) {
            #pragma unroll
            for (int q = 0; q < 4; q++) { acc[i][j][q] = 0.0f; }
        }
    }

    const int arow = (lane & 7) | (((lane >> 3) & 1) << 3);
    const int ach  = lane >> 4;
    const int brow = (lane & 7) | (((lane >> 4) & 1) << 3);
    const int bch  = (lane >> 3) & 1;

    for (int kt = 0; kt < nt; kt++) {
        if (kt + 1 < nt) { CP_WAIT(1); } else { CP_WAIT(0); }
        __syncthreads();
        if (kt + 2 < nt) { LOADG((kt + 2) % 3, kt + 2); }

        const uint32_t st = sb + (uint32_t)(kt % 3) * STG_BYTES;
        #pragma unroll
        for (int s16 = 0; s16 < 2; s16++) {
            uint32_t ah[4][4], al[4][4], bh[2][4], bl[2][4];
            #pragma unroll
            for (int i = 0; i < 4; i++) {
                const uint32_t a = swz(wm * 64 + i * 16 + arow, s16 * 2 + ach);
                ldsm4(ah[i], st + OFF_AH + a);
                ldsm4(al[i], st + OFF_AL + a);
            }
            #pragma unroll
            for (int j = 0; j < 2; j++) {
                const uint32_t b = swz(wn * 32 + j * 16 + brow, s16 * 2 + bch);
                ldsm4(bh[j], st + OFF_BH + b);
                ldsm4(bl[j], st + OFF_BL + b);
            }
            #pragma unroll
            for (int i = 0; i < 4; i++) {
                #pragma unroll
                for (int j = 0; j < 4; j++) {
                    mma16816(acc[i][j], ah[i], &bh[j >> 1][(j & 1) * 2]);
                    mma16816(acc[i][j], ah[i], &bl[j >> 1][(j & 1) * 2]);
                    mma16816(acc[i][j], al[i], &bh[j >> 1][(j & 1) * 2]);
                }
            }
        }
    }

    #pragma unroll
    for (int i = 0; i < 4; i++) {
        const int lb = wm * 64 + i * 16 + (lane >> 2);
        #pragma unroll
        for (int h = 0; h < 2; h++) {
            const int li = lb + h * 8;
            if (rowBase + li >= cnt) continue;
            const int tok = rmap[li];
            const float s0 = g_s0[tok];
            #pragma unroll
            for (int j = 0; j < 4; j++) {
                const int col = ncol0 + wn * 32 + j * 8 + (lane & 3) * 2;
                float2 u2 = *(const float2*)(g_u + (size_t)tok * HID + col);
                float v0 = u2.x + (acc[i][j][h * 2 + 0] + bexp[e * HID + col]) * s0;
                float v1 = u2.y + (acc[i][j][h * 2 + 1] + bexp[e * HID + col + 1]) * s0;
                __half h0, l0, h1, l1;
                splitf(v0, h0, l0); splitf(v1, h1, l1);
                *(__half2*)(g_uhi + (size_t)tok * HID + col) = __halves2half2(h0, h1);
                *(__half2*)(g_ulo + (size_t)tok * HID + col) = __halves2half2(l0, l1);
            }
        }
    }
    #undef LOADG
}

// ---------------------------------------------------------------------------
extern "C" void kernel_launch(void* const* d_in, const int* in_sizes, int n_in,
                              void* d_out, int out_size)
{
    const float* x        = (const float*)d_in[0];
    const float* enc_W    = (const float*)d_in[1];
    const float* enc_b    = (const float*)d_in[2];
    const float* gate_W   = (const float*)d_in[3];
    const float* expert_W = (const float*)d_in[4];
    const float* expert_b = (const float*)d_in[5];
    const float* res_W    = (const float*)d_in[6];
    const float* res_b    = (const float*)d_in[7];
    const float* coef_W   = (const float*)d_in[8];
    const float* coef_b   = (const float*)d_in[9];
    const float* dec_W    = (const float*)d_in[10];
    const float* dec_b    = (const float*)d_in[11];
    float* out = (float*)d_out;

    __half *xhi, *xlo, *hhi, *hlo, *uhi, *ulo, *whi, *wlo;
    float *up, *s1p;
    cudaGetSymbolAddress((void**)&xhi, g_xhi);
    cudaGetSymbolAddress((void**)&xlo, g_xlo);
    cudaGetSymbolAddress((void**)&hhi, g_hhi);
    cudaGetSymbolAddress((void**)&hlo, g_hlo);
    cudaGetSymbolAddress((void**)&uhi, g_uhi);
    cudaGetSymbolAddress((void**)&ulo, g_ulo);
    cudaGetSymbolAddress((void**)&whi, g_Whi);
    cudaGetSymbolAddress((void**)&wlo, g_Wlo);
    cudaGetSymbolAddress((void**)&up,  g_u);
    cudaGetSymbolAddress((void**)&s1p, g_s1);

    cudaFuncSetAttribute(hmma_gemm<0>, cudaFuncAttributeMaxDynamicSharedMemorySize, SMEM_TOT);
    cudaFuncSetAttribute(hmma_gemm<1>, cudaFuncAttributeMaxDynamicSharedMemorySize, SMEM_TOT);
    cudaFuncSetAttribute(hmma_gemm<2>, cudaFuncAttributeMaxDynamicSharedMemorySize, SMEM_TOT);
    cudaFuncSetAttribute(hmma_gemm_grouped, cudaFuncAttributeMaxDynamicSharedMemorySize, SMEM_TOT);

    // ---- precompute: splits + weight transposes ([K,N] -> [N,K] hi/lo) ----
    conv_x_kernel<<<(N_TOK * IN_DIM) / 1024, 256>>>(x);
    transpose_conv<<<dim3(HID/32, IN_DIM/32, 1),  dim3(32, 8)>>>(enc_W,    whi + W_ENC_OFF, wlo + W_ENC_OFF, IN_DIM, HID);
    transpose_conv<<<dim3(HID/32, HID/32, 1),     dim3(32, 8)>>>(res_W,    whi + W_RES_OFF, wlo + W_RES_OFF, HID, HID);
    transpose_conv<<<dim3(HID/32, HID/32, NEXP),  dim3(32, 8)>>>(expert_W, whi + W_EXP_OFF, wlo + W_EXP_OFF, HID, HID);
    transpose_conv<<<dim3(IN_DIM/32, HID/32, 1),  dim3(32, 8)>>>(dec_W,    whi + W_DEC_OFF, wlo + W_DEC_OFF, HID, IN_DIM);
    zero_counts_kernel<<<1, 32>>>();

    // ---- h = relu(x @ enc_W + enc_b) ----
    hmma_gemm<0><<<dim3(HID/128, N_TOK/128), 256, SMEM_TOT>>>(
        xhi, xlo, whi + W_ENC_OFF, wlo + W_ENC_OFF,
        enc_b, IN_DIM, HID, hhi, hlo, nullptr, nullptr);

    // ---- gating ----
    gating_kernel<<<N_TOK, 128>>>(gate_W, coef_W, coef_b);

    // ---- u = (h @ res_W + res_b) * s1 ----
    hmma_gemm<1><<<dim3(HID/128, N_TOK/128), 256, SMEM_TOT>>>(
        hhi, hlo, whi + W_RES_OFF, wlo + W_RES_OFF,
        res_b, HID, HID, nullptr, nullptr, up, s1p);

    // ---- u += (h @ W_e + b_e) * s0 ; split -> uhi/ulo ----
    hmma_gemm_grouped<<<dim3(HID/128, N_TOK/128, NEXP), 256, SMEM_TOT>>>(expert_b);

    // ---- out = u @ dec_W + dec_b ----
    hmma_gemm<2><<<dim3(IN_DIM/128, N_TOK/128), 256, SMEM_TOT>>>(
        uhi, ulo, whi + W_DEC_OFF, wlo + W_DEC_OFF,
        dec_b, HID, IN_DIM, nullptr, nullptr, out, nullptr);
}

// round 6
// speedup vs baseline: 2.9587x; 1.1412x over previous
#include <cuda_runtime.h>
#include <cuda_fp16.h>
#include <cuda.h>
#include <cstdint>
#include <math.h>

#define N_TOK  16384
#define IN_DIM 1024
#define HID    2048
#define NEXP   8

// ---- device scratch (globals: allocation-free) ----
__device__ __align__(128) __half g_xhi[(size_t)N_TOK * IN_DIM];
__device__ __align__(128) __half g_xlo[(size_t)N_TOK * IN_DIM];
__device__ __align__(128) __half g_hhi[(size_t)N_TOK * HID];
__device__ __align__(128) __half g_hlo[(size_t)N_TOK * HID];
__device__ __align__(128) __half g_uhi[(size_t)N_TOK * HID];
__device__ __align__(128) __half g_ulo[(size_t)N_TOK * HID];
__device__ __align__(128) float  g_u[(size_t)N_TOK * HID];

#define W_ENC_OFF 0
#define W_RES_OFF (2048*1024)
#define W_EXP_OFF (W_RES_OFF + 2048*2048)
#define W_DEC_OFF (W_EXP_OFF + 8*2048*2048)
#define W_TOTAL   (W_DEC_OFF + 1024*2048)
__device__ __align__(128) __half g_Whi[(size_t)W_TOTAL];
__device__ __align__(128) __half g_Wlo[(size_t)W_TOTAL];

__device__ int   g_perm[NEXP * N_TOK];
__device__ int   g_counts[NEXP];
__device__ float g_s0[N_TOK];
__device__ float g_s1[N_TOK];

// ---- SMEM: 3 stages x (Ah,Al,Bh,Bl each 16KB: 128 rows x 128B) = 192KB ----
#define STG_BYTES 65536
#define OFF_AH 0
#define OFF_AL 16384
#define OFF_BH 32768
#define OFF_BL 49152
#define SM_RMAP (3 * STG_BYTES)
#define SMEM_TOT (3 * STG_BYTES + 512)

// ---- PTX helpers ----
__device__ __forceinline__ uint32_t smem_u32(const void* p) {
    uint32_t r;
    asm("{ .reg .u64 t; cvta.to.shared.u64 t, %1; cvt.u32.u64 %0, t; }" : "=r"(r) : "l"(p));
    return r;
}
__device__ __forceinline__ void cp16(uint32_t s, const void* g) {
    asm volatile("cp.async.cg.shared.global [%0], [%1], 16;" :: "r"(s), "l"(g));
}
#define CP_COMMIT() asm volatile("cp.async.commit_group;" ::: "memory")
#define CP_WAIT(n)  asm volatile("cp.async.wait_group %0;" :: "n"(n) : "memory")

__device__ __forceinline__ void ldsm4(uint32_t* r, uint32_t a) {
    asm volatile("ldmatrix.sync.aligned.m8n8.x4.shared.b16 {%0,%1,%2,%3}, [%4];"
                 : "=r"(r[0]), "=r"(r[1]), "=r"(r[2]), "=r"(r[3]) : "r"(a));
}
__device__ __forceinline__ void mma16816(float* c, const uint32_t* a, const uint32_t* b) {
    asm volatile(
        "mma.sync.aligned.m16n8k16.row.col.f32.f16.f16.f32 "
        "{%0,%1,%2,%3}, {%4,%5,%6,%7}, {%8,%9}, {%0,%1,%2,%3};"
        : "+f"(c[0]), "+f"(c[1]), "+f"(c[2]), "+f"(c[3])
        : "r"(a[0]), "r"(a[1]), "r"(a[2]), "r"(a[3]), "r"(b[0]), "r"(b[1]));
}

// 128B-row XOR swizzle: conflict-free for ldmatrix and coalesced stores
__device__ __forceinline__ uint32_t swz128(int row, int chunk) {
    return (uint32_t)(row * 128 + ((chunk ^ (row & 7)) * 16));
}

__device__ __forceinline__ void splitf(float v, __half& h, __half& l) {
    h = __float2half_rn(v);
    l = __float2half_rn(v - __half2float(h));
}

// ---- small kernels ----
__global__ void zero_counts_kernel() {
    if (threadIdx.x < NEXP) g_counts[threadIdx.x] = 0;
}

__global__ __launch_bounds__(256) void conv_x_kernel(const float* __restrict__ x) {
    size_t i = ((size_t)blockIdx.x * 256 + threadIdx.x) * 4;
    float4 v = *(const float4*)(x + i);
    __half hb[4], lb[4];
    splitf(v.x, hb[0], lb[0]); splitf(v.y, hb[1], lb[1]);
    splitf(v.z, hb[2], lb[2]); splitf(v.w, hb[3], lb[3]);
    *(uint2*)(g_xhi + i) = *(uint2*)hb;
    *(uint2*)(g_xlo + i) = *(uint2*)lb;
}

// src [K,N] fp32 (batched over z) -> dst [N,K] fp16 hi/lo
__global__ __launch_bounds__(256)
void transpose_conv(const float* __restrict__ src, __half* __restrict__ dhi,
                    __half* __restrict__ dlo, int K, int N)
{
    __shared__ float t[32][33];
    const size_t zoff = (size_t)blockIdx.z * K * N;
    const int n0 = blockIdx.x * 32, k0 = blockIdx.y * 32;
    const int tx = threadIdx.x, ty = threadIdx.y;
    #pragma unroll
    for (int i = 0; i < 4; i++) {
        t[ty + i*8][tx] = src[zoff + (size_t)(k0 + ty + i*8) * N + n0 + tx];
    }
    __syncthreads();
    #pragma unroll
    for (int i = 0; i < 4; i++) {
        const int n = n0 + ty + i*8, k = k0 + tx;
        __half h, l;
        splitf(t[tx][ty + i*8], h, l);
        dhi[zoff + (size_t)n * K + k] = h;
        dlo[zoff + (size_t)n * K + k] = l;
    }
}

// ---- gating ----
__global__ __launch_bounds__(128)
void gating_kernel(const float* __restrict__ gate_W, const float* __restrict__ coef_W,
                   const float* __restrict__ coef_b)
{
    const int n = blockIdx.x;
    const int t = threadIdx.x;
    float acc[10];
    #pragma unroll
    for (int j = 0; j < 10; j++) { acc[j] = 0.0f; }

    const __half* hh = g_hhi + (size_t)n * HID;
    const __half* hl = g_hlo + (size_t)n * HID;
    for (int k = t; k < HID; k += 128) {
        const float hv = __half2float(hh[k]) + __half2float(hl[k]);
        #pragma unroll
        for (int j = 0; j < 8; j++) { acc[j] += hv * gate_W[k * 8 + j]; }
        acc[8] += hv * coef_W[k * 2 + 0];
        acc[9] += hv * coef_W[k * 2 + 1];
    }
    #pragma unroll
    for (int j = 0; j < 10; j++) {
        #pragma unroll
        for (int o = 16; o > 0; o >>= 1) {
            acc[j] += __shfl_down_sync(0xffffffffu, acc[j], o);
        }
    }

    __shared__ float red[4][10];
    const int warp = t >> 5, lane = t & 31;
    if (lane == 0) {
        #pragma unroll
        for (int j = 0; j < 10; j++) { red[warp][j] = acc[j]; }
    }
    __syncthreads();

    if (t == 0) {
        float v[10];
        #pragma unroll
        for (int j = 0; j < 10; j++) {
            v[j] = red[0][j] + red[1][j] + red[2][j] + red[3][j];
        }
        float lmax = v[0]; int idx = 0;
        #pragma unroll
        for (int j = 1; j < 8; j++) {
            if (v[j] > lmax) { lmax = v[j]; idx = j; }
        }
        float s = 0.0f;
        #pragma unroll
        for (int j = 0; j < 8; j++) { s += expf(v[j] - lmax); }
        const float gate = 1.0f / s;
        const float c0 = v[8] + coef_b[0];
        const float c1 = v[9] + coef_b[1];
        const float cm = fmaxf(c0, c1);
        const float e0 = expf(c0 - cm), e1 = expf(c1 - cm);
        const float inv = 1.0f / (e0 + e1);
        g_s0[n] = gate * e0 * inv;
        g_s1[n] = e1 * inv;
        const int pos = atomicAdd(&g_counts[idx], 1);
        g_perm[idx * N_TOK + pos] = n;
    }
}

// ---------------------------------------------------------------------------
// HMMA split-fp16 GEMM. CTA 128x128, BK=64, 8 warps (2x4), warp tile 64x32.
// 3 passes: Ah*Bh + Ah*Bl + Al*Bh. 3-stage cp.async pipeline (192KB).
// MODE 0: relu(acc+bias) -> split Chi/Clo ; MODE 1: (acc+bias)*rowscale -> Cf
// MODE 2: acc+bias -> Cf
// ---------------------------------------------------------------------------
template <int MODE>
__global__ __launch_bounds__(256, 1)
void hmma_gemm(const __half* __restrict__ Ahi, const __half* __restrict__ Alo,
               const __half* __restrict__ Bhi, const __half* __restrict__ Blo,
               const float* __restrict__ bias, int K, int Nn,
               __half* __restrict__ Chi, __half* __restrict__ Clo,
               float* __restrict__ Cf, const float* __restrict__ rowscale)
{
    extern __shared__ __align__(1024) char smem[];
    const uint32_t sb = smem_u32(smem);
    const int tid = threadIdx.x;
    const int lane = tid & 31, wid = tid >> 5;
    const int wm = wid >> 2, wn = wid & 3;           // 2 x 4 warp grid
    const int mrow0 = blockIdx.y * 128;
    const int ncol0 = blockIdx.x * 128;
    const int nt = K / 64;

    // 4 load slots per array per thread: slot = tid + 256*i
    int lrow[4], lch[4];
    uint32_t lsw[4];
    #pragma unroll
    for (int i = 0; i < 4; i++) {
        const int slot = tid + 256 * i;
        lrow[i] = slot >> 3;
        lch[i]  = slot & 7;
        lsw[i]  = swz128(lrow[i], lch[i]);
    }

    #define LOADT(s, kt) do {                                                    \
        const uint32_t st_ = sb + (uint32_t)(s) * STG_BYTES;                      \
        _Pragma("unroll")                                                         \
        for (int i_ = 0; i_ < 4; i_++) {                                          \
            const size_t go_ = (size_t)(kt) * 64 + lch[i_] * 8;                   \
            cp16(st_ + OFF_AH + lsw[i_], Ahi + (size_t)(mrow0 + lrow[i_]) * K + go_); \
            cp16(st_ + OFF_AL + lsw[i_], Alo + (size_t)(mrow0 + lrow[i_]) * K + go_); \
            cp16(st_ + OFF_BH + lsw[i_], Bhi + (size_t)(ncol0 + lrow[i_]) * K + go_); \
            cp16(st_ + OFF_BL + lsw[i_], Blo + (size_t)(ncol0 + lrow[i_]) * K + go_); \
        }                                                                         \
        CP_COMMIT();                                                              \
    } while (0)

    LOADT(0, 0);
    if (nt > 1) { LOADT(1, 1); } else { CP_COMMIT(); }

    float acc[4][4][4];
    #pragma unroll
    for (int i = 0; i < 4; i++) {
        #pragma unroll
        for (int j = 0; j < 4; j++) {
            #pragma unroll
            for (int q = 0; q < 4; q++) { acc[i][j][q] = 0.0f; }
        }
    }

    // ldmatrix per-lane coords
    const int arow = (lane & 7) | (((lane >> 3) & 1) << 3);
    const int ach  = lane >> 4;
    const int brow = (lane & 7) | (((lane >> 4) & 1) << 3);
    const int bch  = (lane >> 3) & 1;

    for (int kt = 0; kt < nt; kt++) {
        if (kt + 1 < nt) { CP_WAIT(1); } else { CP_WAIT(0); }
        __syncthreads();
        if (kt + 2 < nt) { LOADT((kt + 2) % 3, kt + 2); }

        const uint32_t st = sb + (uint32_t)(kt % 3) * STG_BYTES;
        #pragma unroll
        for (int s16 = 0; s16 < 4; s16++) {
            uint32_t ah[4][4], al[4][4], bh[2][4], bl[2][4];
            #pragma unroll
            for (int i = 0; i < 4; i++) {
                const uint32_t a = swz128(wm * 64 + i * 16 + arow, s16 * 2 + ach);
                ldsm4(ah[i], st + OFF_AH + a);
                ldsm4(al[i], st + OFF_AL + a);
            }
            #pragma unroll
            for (int j = 0; j < 2; j++) {
                const uint32_t b = swz128(wn * 32 + j * 16 + brow, s16 * 2 + bch);
                ldsm4(bh[j], st + OFF_BH + b);
                ldsm4(bl[j], st + OFF_BL + b);
            }
            #pragma unroll
            for (int i = 0; i < 4; i++) {
                #pragma unroll
                for (int j = 0; j < 4; j++) {
                    mma16816(acc[i][j], ah[i], &bh[j >> 1][(j & 1) * 2]);
                    mma16816(acc[i][j], ah[i], &bl[j >> 1][(j & 1) * 2]);
                    mma16816(acc[i][j], al[i], &bh[j >> 1][(j & 1) * 2]);
                }
            }
        }
    }

    // epilogue
    #pragma unroll
    for (int i = 0; i < 4; i++) {
        const int rb = mrow0 + wm * 64 + i * 16 + (lane >> 2);
        #pragma unroll
        for (int h = 0; h < 2; h++) {
            const int row = rb + h * 8;
            const float rs = (MODE == 1) ? rowscale[row] : 0.0f;
            #pragma unroll
            for (int j = 0; j < 4; j++) {
                const int col = ncol0 + wn * 32 + j * 8 + (lane & 3) * 2;
                float v0 = acc[i][j][h * 2 + 0] + bias[col];
                float v1 = acc[i][j][h * 2 + 1] + bias[col + 1];
                if (MODE == 0) {
                    v0 = fmaxf(v0, 0.0f); v1 = fmaxf(v1, 0.0f);
                    __half h0, l0, h1, l1;
                    splitf(v0, h0, l0); splitf(v1, h1, l1);
                    *(__half2*)(Chi + (size_t)row * Nn + col) = __halves2half2(h0, h1);
                    *(__half2*)(Clo + (size_t)row * Nn + col) = __halves2half2(l0, l1);
                } else if (MODE == 1) {
                    *(float2*)(Cf + (size_t)row * Nn + col) = make_float2(v0 * rs, v1 * rs);
                } else {
                    *(float2*)(Cf + (size_t)row * Nn + col) = make_float2(v0, v1);
                }
            }
        }
    }
    #undef LOADT
}

// ---------------------------------------------------------------------------
// Grouped expert GEMM: A rows gathered via g_perm; epilogue
// uhi/ulo = split(g_u[tok] + (acc + b_e) * s0[tok]).
// ---------------------------------------------------------------------------
__global__ __launch_bounds__(256, 1)
void hmma_gemm_grouped(const float* __restrict__ bexp)
{
    extern __shared__ __align__(1024) char smem[];
    const int e = blockIdx.z;
    const int cnt = g_counts[e];
    const int rowBase = blockIdx.y * 128;
    if (rowBase >= cnt) return;

    const uint32_t sb = smem_u32(smem);
    const int tid = threadIdx.x;
    const int lane = tid & 31, wid = tid >> 5;
    const int wm = wid >> 2, wn = wid & 3;
    const int ncol0 = blockIdx.x * 128;
    const int nt = HID / 64;
    int* rmap = (int*)(smem + SM_RMAP);

    if (tid < 128) {
        int i = rowBase + tid;
        if (i > cnt - 1) i = cnt - 1;
        rmap[tid] = g_perm[e * N_TOK + i];
    }
    __syncthreads();

    const __half* Bhi = g_Whi + W_EXP_OFF + (size_t)e * HID * HID;
    const __half* Blo = g_Wlo + W_EXP_OFF + (size_t)e * HID * HID;

    int lrow[4], lch[4];
    uint32_t lsw[4];
    size_t ga[4];
    #pragma unroll
    for (int i = 0; i < 4; i++) {
        const int slot = tid + 256 * i;
        lrow[i] = slot >> 3;
        lch[i]  = slot & 7;
        lsw[i]  = swz128(lrow[i], lch[i]);
        ga[i]   = (size_t)rmap[lrow[i]] * HID;
    }

    #define LOADG(s, kt) do {                                                    \
        const uint32_t st_ = sb + (uint32_t)(s) * STG_BYTES;                      \
        _Pragma("unroll")                                                         \
        for (int i_ = 0; i_ < 4; i_++) {                                          \
            const size_t go_ = (size_t)(kt) * 64 + lch[i_] * 8;                   \
            cp16(st_ + OFF_AH + lsw[i_], g_hhi + ga[i_] + go_);                   \
            cp16(st_ + OFF_AL + lsw[i_], g_hlo + ga[i_] + go_);                   \
            cp16(st_ + OFF_BH + lsw[i_], Bhi + (size_t)(ncol0 + lrow[i_]) * HID + go_); \
            cp16(st_ + OFF_BL + lsw[i_], Blo + (size_t)(ncol0 + lrow[i_]) * HID + go_); \
        }                                                                         \
        CP_COMMIT();                                                              \
    } while (0)

    LOADG(0, 0);
    LOADG(1, 1);

    float acc[4][4][4];
    #pragma unroll
    for (int i = 0; i < 4; i++) {
        #pragma unroll
        for (int j = 0; j < 4; j++) {
            #pragma unroll
            for (int q = 0; q < 4; q++) { acc[i][j][q] = 0.0f; }
        }
    }

    const int arow = (lane & 7) | (((lane >> 3) & 1) << 3);
    const int ach  = lane >> 4;
    const int brow = (lane & 7) | (((lane >> 4) & 1) << 3);
    const int bch  = (lane >> 3) & 1;

    for (int kt = 0; kt < nt; kt++) {
        if (kt + 1 < nt) { CP_WAIT(1); } else { CP_WAIT(0); }
        __syncthreads();
        if (kt + 2 < nt) { LOADG((kt + 2) % 3, kt + 2); }

        const uint32_t st = sb + (uint32_t)(kt % 3) * STG_BYTES;
        #pragma unroll
        for (int s16 = 0; s16 < 4; s16++) {
            uint32_t ah[4][4], al[4][4], bh[2][4], bl[2][4];
            #pragma unroll
            for (int i = 0; i < 4; i++) {
                const uint32_t a = swz128(wm * 64 + i * 16 + arow, s16 * 2 + ach);
                ldsm4(ah[i], st + OFF_AH + a);
                ldsm4(al[i], st + OFF_AL + a);
            }
            #pragma unroll
            for (int j = 0; j < 2; j++) {
                const uint32_t b = swz128(wn * 32 + j * 16 + brow, s16 * 2 + bch);
                ldsm4(bh[j], st + OFF_BH + b);
                ldsm4(bl[j], st + OFF_BL + b);
            }
            #pragma unroll
            for (int i = 0; i < 4; i++) {
                #pragma unroll
                for (int j = 0; j < 4; j++) {
                    mma16816(acc[i][j], ah[i], &bh[j >> 1][(j & 1) * 2]);
                    mma16816(acc[i][j], ah[i], &bl[j >> 1][(j & 1) * 2]);
                    mma16816(acc[i][j], al[i], &bh[j >> 1][(j & 1) * 2]);
                }
            }
        }
    }

    #pragma unroll
    for (int i = 0; i < 4; i++) {
        const int lb = wm * 64 + i * 16 + (lane >> 2);
        #pragma unroll
        for (int h = 0; h < 2; h++) {
            const int li = lb + h * 8;
            if (rowBase + li >= cnt) continue;
            const int tok = rmap[li];
            const float s0 = g_s0[tok];
            #pragma unroll
            for (int j = 0; j < 4; j++) {
                const int col = ncol0 + wn * 32 + j * 8 + (lane & 3) * 2;
                float2 u2 = *(const float2*)(g_u + (size_t)tok * HID + col);
                float v0 = u2.x + (acc[i][j][h * 2 + 0] + bexp[e * HID + col]) * s0;
                float v1 = u2.y + (acc[i][j][h * 2 + 1] + bexp[e * HID + col + 1]) * s0;
                __half h0, l0, h1, l1;
                splitf(v0, h0, l0); splitf(v1, h1, l1);
                *(__half2*)(g_uhi + (size_t)tok * HID + col) = __halves2half2(h0, h1);
                *(__half2*)(g_ulo + (size_t)tok * HID + col) = __halves2half2(l0, l1);
            }
        }
    }
    #undef LOADG
}

// ---------------------------------------------------------------------------
extern "C" void kernel_launch(void* const* d_in, const int* in_sizes, int n_in,
                              void* d_out, int out_size)
{
    const float* x        = (const float*)d_in[0];
    const float* enc_W    = (const float*)d_in[1];
    const float* enc_b    = (const float*)d_in[2];
    const float* gate_W   = (const float*)d_in[3];
    const float* expert_W = (const float*)d_in[4];
    const float* expert_b = (const float*)d_in[5];
    const float* res_W    = (const float*)d_in[6];
    const float* res_b    = (const float*)d_in[7];
    const float* coef_W   = (const float*)d_in[8];
    const float* coef_b   = (const float*)d_in[9];
    const float* dec_W    = (const float*)d_in[10];
    const float* dec_b    = (const float*)d_in[11];
    float* out = (float*)d_out;

    __half *xhi, *xlo, *hhi, *hlo, *uhi, *ulo, *whi, *wlo;
    float *up, *s1p;
    cudaGetSymbolAddress((void**)&xhi, g_xhi);
    cudaGetSymbolAddress((void**)&xlo, g_xlo);
    cudaGetSymbolAddress((void**)&hhi, g_hhi);
    cudaGetSymbolAddress((void**)&hlo, g_hlo);
    cudaGetSymbolAddress((void**)&uhi, g_uhi);
    cudaGetSymbolAddress((void**)&ulo, g_ulo);
    cudaGetSymbolAddress((void**)&whi, g_Whi);
    cudaGetSymbolAddress((void**)&wlo, g_Wlo);
    cudaGetSymbolAddress((void**)&up,  g_u);
    cudaGetSymbolAddress((void**)&s1p, g_s1);

    cudaFuncSetAttribute(hmma_gemm<0>, cudaFuncAttributeMaxDynamicSharedMemorySize, SMEM_TOT);
    cudaFuncSetAttribute(hmma_gemm<1>, cudaFuncAttributeMaxDynamicSharedMemorySize, SMEM_TOT);
    cudaFuncSetAttribute(hmma_gemm<2>, cudaFuncAttributeMaxDynamicSharedMemorySize, SMEM_TOT);
    cudaFuncSetAttribute(hmma_gemm_grouped, cudaFuncAttributeMaxDynamicSharedMemorySize, SMEM_TOT);

    // ---- precompute: splits + weight transposes ([K,N] -> [N,K] hi/lo) ----
    conv_x_kernel<<<(N_TOK * IN_DIM) / 1024, 256>>>(x);
    transpose_conv<<<dim3(HID/32, IN_DIM/32, 1),  dim3(32, 8)>>>(enc_W,    whi + W_ENC_OFF, wlo + W_ENC_OFF, IN_DIM, HID);
    transpose_conv<<<dim3(HID/32, HID/32, 1),     dim3(32, 8)>>>(res_W,    whi + W_RES_OFF, wlo + W_RES_OFF, HID, HID);
    transpose_conv<<<dim3(HID/32, HID/32, NEXP),  dim3(32, 8)>>>(expert_W, whi + W_EXP_OFF, wlo + W_EXP_OFF, HID, HID);
    transpose_conv<<<dim3(IN_DIM/32, HID/32, 1),  dim3(32, 8)>>>(dec_W,    whi + W_DEC_OFF, wlo + W_DEC_OFF, HID, IN_DIM);
    zero_counts_kernel<<<1, 32>>>();

    // ---- h = relu(x @ enc_W + enc_b) ----
    hmma_gemm<0><<<dim3(HID/128, N_TOK/128), 256, SMEM_TOT>>>(
        xhi, xlo, whi + W_ENC_OFF, wlo + W_ENC_OFF,
        enc_b, IN_DIM, HID, hhi, hlo, nullptr, nullptr);

    // ---- gating ----
    gating_kernel<<<N_TOK, 128>>>(gate_W, coef_W, coef_b);

    // ---- u = (h @ res_W + res_b) * s1 ----
    hmma_gemm<1><<<dim3(HID/128, N_TOK/128), 256, SMEM_TOT>>>(
        hhi, hlo, whi + W_RES_OFF, wlo + W_RES_OFF,
        res_b, HID, HID, nullptr, nullptr, up, s1p);

    // ---- u += (h @ W_e + b_e) * s0 ; split -> uhi/ulo ----
    hmma_gemm_grouped<<<dim3(HID/128, N_TOK/128, NEXP), 256, SMEM_TOT>>>(expert_b);

    // ---- out = u @ dec_W + dec_b ----
    hmma_gemm<2><<<dim3(IN_DIM/128, N_TOK/128), 256, SMEM_TOT>>>(
        uhi, ulo, whi + W_DEC_OFF, wlo + W_DEC_OFF,
        dec_b, HID, IN_DIM, nullptr, nullptr, out, nullptr);
}

// round 7
// speedup vs baseline: 2.9672x; 1.0029x over previous
#include <cuda_runtime.h>
#include <cuda_fp16.h>
#include <cuda.h>
#include <cstdint>
#include <math.h>

#define N_TOK  16384
#define IN_DIM 1024
#define HID    2048
#define NEXP   8

// ---- device scratch (globals: allocation-free) ----
__device__ __align__(128) __half g_xhi[(size_t)N_TOK * IN_DIM];
__device__ __align__(128) __half g_xlo[(size_t)N_TOK * IN_DIM];
__device__ __align__(128) __half g_hhi[(size_t)N_TOK * HID];
__device__ __align__(128) __half g_hlo[(size_t)N_TOK * HID];
__device__ __align__(128) __half g_uhi[(size_t)N_TOK * HID];
__device__ __align__(128) __half g_ulo[(size_t)N_TOK * HID];
__device__ __align__(128) float  g_u[(size_t)N_TOK * HID];

#define W_ENC_OFF 0
#define W_RES_OFF (2048*1024)
#define W_EXP_OFF (W_RES_OFF + 2048*2048)
#define W_DEC_OFF (W_EXP_OFF + 8*2048*2048)
#define W_TOTAL   (W_DEC_OFF + 1024*2048)
__device__ __align__(128) __half g_Whi[(size_t)W_TOTAL];
__device__ __align__(128) __half g_Wlo[(size_t)W_TOTAL];

__device__ int   g_perm[NEXP * N_TOK];
__device__ int   g_counts[NEXP];
__device__ float g_s0[N_TOK];
__device__ float g_s1[N_TOK];

// ---- SMEM: 3 stages x (Ah,Al,Bh,Bl each 16KB: 128 rows x 128B) = 192KB ----
#define STG_BYTES 65536
#define OFF_AH 0
#define OFF_AL 16384
#define OFF_BH 32768
#define OFF_BL 49152
#define SM_RMAP (3 * STG_BYTES)
#define SMEM_TOT (3 * STG_BYTES + 512)

// ---- PTX helpers ----
__device__ __forceinline__ uint32_t smem_u32(const void* p) {
    uint32_t r;
    asm("{ .reg .u64 t; cvta.to.shared.u64 t, %1; cvt.u32.u64 %0, t; }" : "=r"(r) : "l"(p));
    return r;
}
__device__ __forceinline__ void cp16(uint32_t s, const void* g) {
    asm volatile("cp.async.cg.shared.global [%0], [%1], 16;" :: "r"(s), "l"(g));
}
#define CP_COMMIT() asm volatile("cp.async.commit_group;" ::: "memory")
#define CP_WAIT(n)  asm volatile("cp.async.wait_group %0;" :: "n"(n) : "memory")

__device__ __forceinline__ void ldsm4(uint32_t* r, uint32_t a) {
    asm volatile("ldmatrix.sync.aligned.m8n8.x4.shared.b16 {%0,%1,%2,%3}, [%4];"
                 : "=r"(r[0]), "=r"(r[1]), "=r"(r[2]), "=r"(r[3]) : "r"(a));
}
__device__ __forceinline__ void mma16816(float* c, const uint32_t* a, const uint32_t* b) {
    asm volatile(
        "mma.sync.aligned.m16n8k16.row.col.f32.f16.f16.f32 "
        "{%0,%1,%2,%3}, {%4,%5,%6,%7}, {%8,%9}, {%0,%1,%2,%3};"
        : "+f"(c[0]), "+f"(c[1]), "+f"(c[2]), "+f"(c[3])
        : "r"(a[0]), "r"(a[1]), "r"(a[2]), "r"(a[3]), "r"(b[0]), "r"(b[1]));
}

// 128B-row XOR swizzle: conflict-free for ldmatrix and coalesced stores
__device__ __forceinline__ uint32_t swz128(int row, int chunk) {
    return (uint32_t)(row * 128 + ((chunk ^ (row & 7)) * 16));
}

__device__ __forceinline__ void splitf(float v, __half& h, __half& l) {
    h = __float2half_rn(v);
    l = __float2half_rn(v - __half2float(h));
}

// ---- small kernels ----
__global__ void zero_counts_kernel() {
    if (threadIdx.x < NEXP) g_counts[threadIdx.x] = 0;
}

__global__ __launch_bounds__(256) void conv_x_kernel(const float* __restrict__ x) {
    size_t i = ((size_t)blockIdx.x * 256 + threadIdx.x) * 4;
    float4 v = *(const float4*)(x + i);
    __half hb[4], lb[4];
    splitf(v.x, hb[0], lb[0]); splitf(v.y, hb[1], lb[1]);
    splitf(v.z, hb[2], lb[2]); splitf(v.w, hb[3], lb[3]);
    *(uint2*)(g_xhi + i) = *(uint2*)hb;
    *(uint2*)(g_xlo + i) = *(uint2*)lb;
}

// src [K,N] fp32 (batched over z) -> dst [N,K] fp16 hi/lo
__global__ __launch_bounds__(256)
void transpose_conv(const float* __restrict__ src, __half* __restrict__ dhi,
                    __half* __restrict__ dlo, int K, int N)
{
    __shared__ float t[32][33];
    const size_t zoff = (size_t)blockIdx.z * K * N;
    const int n0 = blockIdx.x * 32, k0 = blockIdx.y * 32;
    const int tx = threadIdx.x, ty = threadIdx.y;
    #pragma unroll
    for (int i = 0; i < 4; i++) {
        t[ty + i*8][tx] = src[zoff + (size_t)(k0 + ty + i*8) * N + n0 + tx];
    }
    __syncthreads();
    #pragma unroll
    for (int i = 0; i < 4; i++) {
        const int n = n0 + ty + i*8, k = k0 + tx;
        __half h, l;
        splitf(t[tx][ty + i*8], h, l);
        dhi[zoff + (size_t)n * K + k] = h;
        dlo[zoff + (size_t)n * K + k] = l;
    }
}

// ---- gating ----
__global__ __launch_bounds__(128)
void gating_kernel(const float* __restrict__ gate_W, const float* __restrict__ coef_W,
                   const float* __restrict__ coef_b)
{
    const int n = blockIdx.x;
    const int t = threadIdx.x;
    float acc[10];
    #pragma unroll
    for (int j = 0; j < 10; j++) { acc[j] = 0.0f; }

    const __half* hh = g_hhi + (size_t)n * HID;
    const __half* hl = g_hlo + (size_t)n * HID;
    for (int k = t; k < HID; k += 128) {
        const float hv = __half2float(hh[k]) + __half2float(hl[k]);
        #pragma unroll
        for (int j = 0; j < 8; j++) { acc[j] += hv * gate_W[k * 8 + j]; }
        acc[8] += hv * coef_W[k * 2 + 0];
        acc[9] += hv * coef_W[k * 2 + 1];
    }
    #pragma unroll
    for (int j = 0; j < 10; j++) {
        #pragma unroll
        for (int o = 16; o > 0; o >>= 1) {
            acc[j] += __shfl_down_sync(0xffffffffu, acc[j], o);
        }
    }

    __shared__ float red[4][10];
    const int warp = t >> 5, lane = t & 31;
    if (lane == 0) {
        #pragma unroll
        for (int j = 0; j < 10; j++) { red[warp][j] = acc[j]; }
    }
    __syncthreads();

    if (t == 0) {
        float v[10];
        #pragma unroll
        for (int j = 0; j < 10; j++) {
            v[j] = red[0][j] + red[1][j] + red[2][j] + red[3][j];
        }
        float lmax = v[0]; int idx = 0;
        #pragma unroll
        for (int j = 1; j < 8; j++) {
            if (v[j] > lmax) { lmax = v[j]; idx = j; }
        }
        float s = 0.0f;
        #pragma unroll
        for (int j = 0; j < 8; j++) { s += expf(v[j] - lmax); }
        const float gate = 1.0f / s;
        const float c0 = v[8] + coef_b[0];
        const float c1 = v[9] + coef_b[1];
        const float cm = fmaxf(c0, c1);
        const float e0 = expf(c0 - cm), e1 = expf(c1 - cm);
        const float inv = 1.0f / (e0 + e1);
        g_s0[n] = gate * e0 * inv;
        g_s1[n] = e1 * inv;
        const int pos = atomicAdd(&g_counts[idx], 1);
        g_perm[idx * N_TOK + pos] = n;
    }
}

// ---- shared mainloop fragments (double-buffered) ----
#define LDFRAG(buf, st, s16) do {                                                \
    _Pragma("unroll")                                                             \
    for (int i_ = 0; i_ < 4; i_++) {                                              \
        const uint32_t a_ = swz128(wm * 64 + i_ * 16 + arow, (s16) * 2 + ach);    \
        ldsm4(ah[buf][i_], (st) + OFF_AH + a_);                                   \
        ldsm4(al[buf][i_], (st) + OFF_AL + a_);                                   \
    }                                                                             \
    _Pragma("unroll")                                                             \
    for (int j_ = 0; j_ < 2; j_++) {                                              \
        const uint32_t b_ = swz128(wn * 32 + j_ * 16 + brow, (s16) * 2 + bch);    \
        ldsm4(bh[buf][j_], (st) + OFF_BH + b_);                                   \
        ldsm4(bl[buf][j_], (st) + OFF_BL + b_);                                   \
    }                                                                             \
} while (0)

#define DOMMA(buf) do {                                                           \
    _Pragma("unroll")                                                             \
    for (int i_ = 0; i_ < 4; i_++) {                                              \
        _Pragma("unroll")                                                         \
        for (int j_ = 0; j_ < 4; j_++) {                                          \
            mma16816(acc[i_][j_], ah[buf][i_], &bh[buf][j_ >> 1][(j_ & 1) * 2]);  \
            mma16816(acc[i_][j_], ah[buf][i_], &bl[buf][j_ >> 1][(j_ & 1) * 2]);  \
            mma16816(acc[i_][j_], al[buf][i_], &bh[buf][j_ >> 1][(j_ & 1) * 2]);  \
        }                                                                         \
    }                                                                             \
} while (0)

// ---------------------------------------------------------------------------
// HMMA split-fp16 GEMM. CTA 128x128, BK=64, 8 warps (2x4), warp tile 64x32.
// 3 passes: Ah*Bh + Ah*Bl + Al*Bh. 3-stage cp.async pipeline (192KB).
// Double-buffered ldmatrix fragments hide LDSM latency behind MMA bursts.
// ---------------------------------------------------------------------------
template <int MODE>
__global__ __launch_bounds__(256, 1)
void hmma_gemm(const __half* __restrict__ Ahi, const __half* __restrict__ Alo,
               const __half* __restrict__ Bhi, const __half* __restrict__ Blo,
               const float* __restrict__ bias, int K, int Nn,
               __half* __restrict__ Chi, __half* __restrict__ Clo,
               float* __restrict__ Cf, const float* __restrict__ rowscale)
{
    extern __shared__ __align__(1024) char smem[];
    const uint32_t sb = smem_u32(smem);
    const int tid = threadIdx.x;
    const int lane = tid & 31, wid = tid >> 5;
    const int wm = wid >> 2, wn = wid & 3;           // 2 x 4 warp grid
    const int mrow0 = blockIdx.y * 128;
    const int ncol0 = blockIdx.x * 128;
    const int nt = K / 64;

    int lrow[4], lch[4];
    uint32_t lsw[4];
    #pragma unroll
    for (int i = 0; i < 4; i++) {
        const int slot = tid + 256 * i;
        lrow[i] = slot >> 3;
        lch[i]  = slot & 7;
        lsw[i]  = swz128(lrow[i], lch[i]);
    }

    #define LOADT(s, kt) do {                                                    \
        const uint32_t st_ = sb + (uint32_t)(s) * STG_BYTES;                      \
        _Pragma("unroll")                                                         \
        for (int i_ = 0; i_ < 4; i_++) {                                          \
            const size_t go_ = (size_t)(kt) * 64 + lch[i_] * 8;                   \
            cp16(st_ + OFF_AH + lsw[i_], Ahi + (size_t)(mrow0 + lrow[i_]) * K + go_); \
            cp16(st_ + OFF_AL + lsw[i_], Alo + (size_t)(mrow0 + lrow[i_]) * K + go_); \
            cp16(st_ + OFF_BH + lsw[i_], Bhi + (size_t)(ncol0 + lrow[i_]) * K + go_); \
            cp16(st_ + OFF_BL + lsw[i_], Blo + (size_t)(ncol0 + lrow[i_]) * K + go_); \
        }                                                                         \
        CP_COMMIT();                                                              \
    } while (0)

    LOADT(0, 0);
    if (nt > 1) { LOADT(1, 1); } else { CP_COMMIT(); }

    float acc[4][4][4];
    #pragma unroll
    for (int i = 0; i < 4; i++) {
        #pragma unroll
        for (int j = 0; j < 4; j++) {
            #pragma unroll
            for (int q = 0; q < 4; q++) { acc[i][j][q] = 0.0f; }
        }
    }

    const int arow = (lane & 7) | (((lane >> 3) & 1) << 3);
    const int ach  = lane >> 4;
    const int brow = (lane & 7) | (((lane >> 4) & 1) << 3);
    const int bch  = (lane >> 3) & 1;

    uint32_t ah[2][4][4], al[2][4][4], bh[2][2][4], bl[2][2][4];

    for (int kt = 0; kt < nt; kt++) {
        if (kt + 1 < nt) { CP_WAIT(1); } else { CP_WAIT(0); }
        __syncthreads();
        if (kt + 2 < nt) { LOADT((kt + 2) % 3, kt + 2); }

        const uint32_t st = sb + (uint32_t)(kt % 3) * STG_BYTES;
        LDFRAG(0, st, 0);
        LDFRAG(1, st, 1);
        DOMMA(0);
        LDFRAG(0, st, 2);
        DOMMA(1);
        LDFRAG(1, st, 3);
        DOMMA(0);
        DOMMA(1);
    }

    // epilogue
    #pragma unroll
    for (int i = 0; i < 4; i++) {
        const int rb = mrow0 + wm * 64 + i * 16 + (lane >> 2);
        #pragma unroll
        for (int h = 0; h < 2; h++) {
            const int row = rb + h * 8;
            const float rs = (MODE == 1) ? rowscale[row] : 0.0f;
            #pragma unroll
            for (int j = 0; j < 4; j++) {
                const int col = ncol0 + wn * 32 + j * 8 + (lane & 3) * 2;
                float v0 = acc[i][j][h * 2 + 0] + bias[col];
                float v1 = acc[i][j][h * 2 + 1] + bias[col + 1];
                if (MODE == 0) {
                    v0 = fmaxf(v0, 0.0f); v1 = fmaxf(v1, 0.0f);
                    __half h0, l0, h1, l1;
                    splitf(v0, h0, l0); splitf(v1, h1, l1);
                    *(__half2*)(Chi + (size_t)row * Nn + col) = __halves2half2(h0, h1);
                    *(__half2*)(Clo + (size_t)row * Nn + col) = __halves2half2(l0, l1);
                } else if (MODE == 1) {
                    *(float2*)(Cf + (size_t)row * Nn + col) = make_float2(v0 * rs, v1 * rs);
                } else {
                    *(float2*)(Cf + (size_t)row * Nn + col) = make_float2(v0, v1);
                }
            }
        }
    }
    #undef LOADT
}

// ---------------------------------------------------------------------------
// Grouped expert GEMM: A rows gathered via g_perm; epilogue
// uhi/ulo = split(g_u[tok] + (acc + b_e) * s0[tok]).
// ---------------------------------------------------------------------------
__global__ __launch_bounds__(256, 1)
void hmma_gemm_grouped(const float* __restrict__ bexp)
{
    extern __shared__ __align__(1024) char smem[];
    const int e = blockIdx.z;
    const int cnt = g_counts[e];
    const int rowBase = blockIdx.y * 128;
    if (rowBase >= cnt) return;

    const uint32_t sb = smem_u32(smem);
    const int tid = threadIdx.x;
    const int lane = tid & 31, wid = tid >> 5;
    const int wm = wid >> 2, wn = wid & 3;
    const int ncol0 = blockIdx.x * 128;
    const int nt = HID / 64;
    int* rmap = (int*)(smem + SM_RMAP);

    if (tid < 128) {
        int i = rowBase + tid;
        if (i > cnt - 1) i = cnt - 1;
        rmap[tid] = g_perm[e * N_TOK + i];
    }
    __syncthreads();

    const __half* Bhi = g_Whi + W_EXP_OFF + (size_t)e * HID * HID;
    const __half* Blo = g_Wlo + W_EXP_OFF + (size_t)e * HID * HID;

    int lrow[4], lch[4];
    uint32_t lsw[4];
    size_t ga[4];
    #pragma unroll
    for (int i = 0; i < 4; i++) {
        const int slot = tid + 256 * i;
        lrow[i] = slot >> 3;
        lch[i]  = slot & 7;
        lsw[i]  = swz128(lrow[i], lch[i]);
        ga[i]   = (size_t)rmap[lrow[i]] * HID;
    }

    #define LOADG(s, kt) do {                                                    \
        const uint32_t st_ = sb + (uint32_t)(s) * STG_BYTES;                      \
        _Pragma("unroll")                                                         \
        for (int i_ = 0; i_ < 4; i_++) {                                          \
            const size_t go_ = (size_t)(kt) * 64 + lch[i_] * 8;                   \
            cp16(st_ + OFF_AH + lsw[i_], g_hhi + ga[i_] + go_);                   \
            cp16(st_ + OFF_AL + lsw[i_], g_hlo + ga[i_] + go_);                   \
            cp16(st_ + OFF_BH + lsw[i_], Bhi + (size_t)(ncol0 + lrow[i_]) * HID + go_); \
            cp16(st_ + OFF_BL + lsw[i_], Blo + (size_t)(ncol0 + lrow[i_]) * HID + go_); \
        }                                                                         \
        CP_COMMIT();                                                              \
    } while (0)

    LOADG(0, 0);
    LOADG(1, 1);

    float acc[4][4][4];
    #pragma unroll
    for (int i = 0; i < 4; i++) {
        #pragma unroll
        for (int j = 0; j < 4; j++) {
            #pragma unroll
            for (int q = 0; q < 4; q++) { acc[i][j][q] = 0.0f; }
        }
    }

    const int arow = (lane & 7) | (((lane >> 3) & 1) << 3);
    const int ach  = lane >> 4;
    const int brow = (lane & 7) | (((lane >> 4) & 1) << 3);
    const int bch  = (lane >> 3) & 1;

    uint32_t ah[2][4][4], al[2][4][4], bh[2][2][4], bl[2][2][4];

    for (int kt = 0; kt < nt; kt++) {
        if (kt + 1 < nt) { CP_WAIT(1); } else { CP_WAIT(0); }
        __syncthreads();
        if (kt + 2 < nt) { LOADG((kt + 2) % 3, kt + 2); }

        const uint32_t st = sb + (uint32_t)(kt % 3) * STG_BYTES;
        LDFRAG(0, st, 0);
        LDFRAG(1, st, 1);
        DOMMA(0);
        LDFRAG(0, st, 2);
        DOMMA(1);
        LDFRAG(1, st, 3);
        DOMMA(0);
        DOMMA(1);
    }

    #pragma unroll
    for (int i = 0; i < 4; i++) {
        const int lb = wm * 64 + i * 16 + (lane >> 2);
        #pragma unroll
        for (int h = 0; h < 2; h++) {
            const int li = lb + h * 8;
            if (rowBase + li >= cnt) continue;
            const int tok = rmap[li];
            const float s0 = g_s0[tok];
            #pragma unroll
            for (int j = 0; j < 4; j++) {
                const int col = ncol0 + wn * 32 + j * 8 + (lane & 3) * 2;
                float2 u2 = *(const float2*)(g_u + (size_t)tok * HID + col);
                float v0 = u2.x + (acc[i][j][h * 2 + 0] + bexp[e * HID + col]) * s0;
                float v1 = u2.y + (acc[i][j][h * 2 + 1] + bexp[e * HID + col + 1]) * s0;
                __half h0, l0, h1, l1;
                splitf(v0, h0, l0); splitf(v1, h1, l1);
                *(__half2*)(g_uhi + (size_t)tok * HID + col) = __halves2half2(h0, h1);
                *(__half2*)(g_ulo + (size_t)tok * HID + col) = __halves2half2(l0, l1);
            }
        }
    }
    #undef LOADG
}

// ---------------------------------------------------------------------------
extern "C" void kernel_launch(void* const* d_in, const int* in_sizes, int n_in,
                              void* d_out, int out_size)
{
    const float* x        = (const float*)d_in[0];
    const float* enc_W    = (const float*)d_in[1];
    const float* enc_b    = (const float*)d_in[2];
    const float* gate_W   = (const float*)d_in[3];
    const float* expert_W = (const float*)d_in[4];
    const float* expert_b = (const float*)d_in[5];
    const float* res_W    = (const float*)d_in[6];
    const float* res_b    = (const float*)d_in[7];
    const float* coef_W   = (const float*)d_in[8];
    const float* coef_b   = (const float*)d_in[9];
    const float* dec_W    = (const float*)d_in[10];
    const float* dec_b    = (const float*)d_in[11];
    float* out = (float*)d_out;

    __half *xhi, *xlo, *hhi, *hlo, *uhi, *ulo, *whi, *wlo;
    float *up, *s1p;
    cudaGetSymbolAddress((void**)&xhi, g_xhi);
    cudaGetSymbolAddress((void**)&xlo, g_xlo);
    cudaGetSymbolAddress((void**)&hhi, g_hhi);
    cudaGetSymbolAddress((void**)&hlo, g_hlo);
    cudaGetSymbolAddress((void**)&uhi, g_uhi);
    cudaGetSymbolAddress((void**)&ulo, g_ulo);
    cudaGetSymbolAddress((void**)&whi, g_Whi);
    cudaGetSymbolAddress((void**)&wlo, g_Wlo);
    cudaGetSymbolAddress((void**)&up,  g_u);
    cudaGetSymbolAddress((void**)&s1p, g_s1);

    cudaFuncSetAttribute(hmma_gemm<0>, cudaFuncAttributeMaxDynamicSharedMemorySize, SMEM_TOT);
    cudaFuncSetAttribute(hmma_gemm<1>, cudaFuncAttributeMaxDynamicSharedMemorySize, SMEM_TOT);
    cudaFuncSetAttribute(hmma_gemm<2>, cudaFuncAttributeMaxDynamicSharedMemorySize, SMEM_TOT);
    cudaFuncSetAttribute(hmma_gemm_grouped, cudaFuncAttributeMaxDynamicSharedMemorySize, SMEM_TOT);

    // ---- precompute: splits + weight transposes ([K,N] -> [N,K] hi/lo) ----
    conv_x_kernel<<<(N_TOK * IN_DIM) / 1024, 256>>>(x);
    transpose_conv<<<dim3(HID/32, IN_DIM/32, 1),  dim3(32, 8)>>>(enc_W,    whi + W_ENC_OFF, wlo + W_ENC_OFF, IN_DIM, HID);
    transpose_conv<<<dim3(HID/32, HID/32, 1),     dim3(32, 8)>>>(res_W,    whi + W_RES_OFF, wlo + W_RES_OFF, HID, HID);
    transpose_conv<<<dim3(HID/32, HID/32, NEXP),  dim3(32, 8)>>>(expert_W, whi + W_EXP_OFF, wlo + W_EXP_OFF, HID, HID);
    transpose_conv<<<dim3(IN_DIM/32, HID/32, 1),  dim3(32, 8)>>>(dec_W,    whi + W_DEC_OFF, wlo + W_DEC_OFF, HID, IN_DIM);
    zero_counts_kernel<<<1, 32>>>();

    // ---- h = relu(x @ enc_W + enc_b) ----
    hmma_gemm<0><<<dim3(HID/128, N_TOK/128), 256, SMEM_TOT>>>(
        xhi, xlo, whi + W_ENC_OFF, wlo + W_ENC_OFF,
        enc_b, IN_DIM, HID, hhi, hlo, nullptr, nullptr);

    // ---- gating ----
    gating_kernel<<<N_TOK, 128>>>(gate_W, coef_W, coef_b);

    // ---- u = (h @ res_W + res_b) * s1 ----
    hmma_gemm<1><<<dim3(HID/128, N_TOK/128), 256, SMEM_TOT>>>(
        hhi, hlo, whi + W_RES_OFF, wlo + W_RES_OFF,
        res_b, HID, HID, nullptr, nullptr, up, s1p);

    // ---- u += (h @ W_e + b_e) * s0 ; split -> uhi/ulo ----
    hmma_gemm_grouped<<<dim3(HID/128, N_TOK/128, NEXP), 256, SMEM_TOT>>>(expert_b);

    // ---- out = u @ dec_W + dec_b ----
    hmma_gemm<2><<<dim3(IN_DIM/128, N_TOK/128), 256, SMEM_TOT>>>(
        uhi, ulo, whi + W_DEC_OFF, wlo + W_DEC_OFF,
        dec_b, HID, IN_DIM, nullptr, nullptr, out, nullptr);
}

// round 8
// speedup vs baseline: 3.7124x; 1.2511x over previous
#include <cuda_runtime.h>
#include <cuda_fp16.h>
#include <cuda.h>
#include <cstdint>
#include <math.h>

#define N_TOK  16384
#define IN_DIM 1024
#define HID    2048
#define NEXP   8

// ---- device scratch (globals: allocation-free) ----
__device__ __align__(128) __half g_xhi[(size_t)N_TOK * IN_DIM];
__device__ __align__(128) __half g_xlo[(size_t)N_TOK * IN_DIM];
__device__ __align__(128) __half g_hhi[(size_t)N_TOK * HID];
__device__ __align__(128) __half g_hlo[(size_t)N_TOK * HID];
__device__ __align__(128) __half g_uhi[(size_t)N_TOK * HID];
__device__ __align__(128) float  g_u[(size_t)N_TOK * HID];

#define W_ENC_OFF 0
#define W_RES_OFF (2048*1024)
#define W_EXP_OFF (W_RES_OFF + 2048*2048)
#define W_DEC_OFF (W_EXP_OFF + 8*2048*2048)
#define W_TOTAL   (W_DEC_OFF + 1024*2048)
__device__ __align__(128) __half g_Whi[(size_t)W_TOTAL];
__device__ __align__(128) __half g_Wlo[(size_t)W_TOTAL];

__device__ int   g_perm[NEXP * N_TOK];
__device__ int   g_counts[NEXP];
__device__ float g_s0[N_TOK];
__device__ float g_s1[N_TOK];

// ---- SMEM: 3 stages x (Ah,Al,Bh,Bl each 16KB: 128 rows x 128B) = 192KB ----
#define STG_BYTES 65536
#define OFF_AH 0
#define OFF_AL 16384
#define OFF_BH 32768
#define OFF_BL 49152
#define SM_RMAP (3 * STG_BYTES)
#define SMEM_TOT (3 * STG_BYTES + 512)

// ---- PTX helpers ----
__device__ __forceinline__ uint32_t smem_u32(const void* p) {
    uint32_t r;
    asm("{ .reg .u64 t; cvta.to.shared.u64 t, %1; cvt.u32.u64 %0, t; }" : "=r"(r) : "l"(p));
    return r;
}
__device__ __forceinline__ void cp16(uint32_t s, const void* g) {
    asm volatile("cp.async.cg.shared.global [%0], [%1], 16;" :: "r"(s), "l"(g));
}
#define CP_COMMIT() asm volatile("cp.async.commit_group;" ::: "memory")
#define CP_WAIT(n)  asm volatile("cp.async.wait_group %0;" :: "n"(n) : "memory")

__device__ __forceinline__ void ldsm4(uint32_t* r, uint32_t a) {
    asm volatile("ldmatrix.sync.aligned.m8n8.x4.shared.b16 {%0,%1,%2,%3}, [%4];"
                 : "=r"(r[0]), "=r"(r[1]), "=r"(r[2]), "=r"(r[3]) : "r"(a));
}
__device__ __forceinline__ void mma16816(float* c, const uint32_t* a, const uint32_t* b) {
    asm volatile(
        "mma.sync.aligned.m16n8k16.row.col.f32.f16.f16.f32 "
        "{%0,%1,%2,%3}, {%4,%5,%6,%7}, {%8,%9}, {%0,%1,%2,%3};"
        : "+f"(c[0]), "+f"(c[1]), "+f"(c[2]), "+f"(c[3])
        : "r"(a[0]), "r"(a[1]), "r"(a[2]), "r"(a[3]), "r"(b[0]), "r"(b[1]));
}

// 128B-row XOR swizzle: conflict-free for ldmatrix and coalesced stores
__device__ __forceinline__ uint32_t swz128(int row, int chunk) {
    return (uint32_t)(row * 128 + ((chunk ^ (row & 7)) * 16));
}

__device__ __forceinline__ void splitf(float v, __half& h, __half& l) {
    h = __float2half_rn(v);
    l = __float2half_rn(v - __half2float(h));
}

// ---- small kernels ----
__global__ void zero_counts_kernel() {
    if (threadIdx.x < NEXP) g_counts[threadIdx.x] = 0;
}

__global__ __launch_bounds__(256) void conv_x_kernel(const float* __restrict__ x) {
    size_t i = ((size_t)blockIdx.x * 256 + threadIdx.x) * 4;
    float4 v = *(const float4*)(x + i);
    __half hb[4], lb[4];
    splitf(v.x, hb[0], lb[0]); splitf(v.y, hb[1], lb[1]);
    splitf(v.z, hb[2], lb[2]); splitf(v.w, hb[3], lb[3]);
    *(uint2*)(g_xhi + i) = *(uint2*)hb;
    *(uint2*)(g_xlo + i) = *(uint2*)lb;
}

// src [K,N] fp32 (batched over z) -> dst [N,K] fp16 hi/lo
__global__ __launch_bounds__(256)
void transpose_conv(const float* __restrict__ src, __half* __restrict__ dhi,
                    __half* __restrict__ dlo, int K, int N)
{
    __shared__ float t[32][33];
    const size_t zoff = (size_t)blockIdx.z * K * N;
    const int n0 = blockIdx.x * 32, k0 = blockIdx.y * 32;
    const int tx = threadIdx.x, ty = threadIdx.y;
    #pragma unroll
    for (int i = 0; i < 4; i++) {
        t[ty + i*8][tx] = src[zoff + (size_t)(k0 + ty + i*8) * N + n0 + tx];
    }
    __syncthreads();
    #pragma unroll
    for (int i = 0; i < 4; i++) {
        const int n = n0 + ty + i*8, k = k0 + tx;
        __half h, l;
        splitf(t[tx][ty + i*8], h, l);
        dhi[zoff + (size_t)n * K + k] = h;
        dlo[zoff + (size_t)n * K + k] = l;
    }
}

// ---- gating ----
__global__ __launch_bounds__(128)
void gating_kernel(const float* __restrict__ gate_W, const float* __restrict__ coef_W,
                   const float* __restrict__ coef_b)
{
    const int n = blockIdx.x;
    const int t = threadIdx.x;
    float acc[10];
    #pragma unroll
    for (int j = 0; j < 10; j++) { acc[j] = 0.0f; }

    const __half* hh = g_hhi + (size_t)n * HID;
    const __half* hl = g_hlo + (size_t)n * HID;
    for (int k = t; k < HID; k += 128) {
        const float hv = __half2float(hh[k]) + __half2float(hl[k]);
        #pragma unroll
        for (int j = 0; j < 8; j++) { acc[j] += hv * gate_W[k * 8 + j]; }
        acc[8] += hv * coef_W[k * 2 + 0];
        acc[9] += hv * coef_W[k * 2 + 1];
    }
    #pragma unroll
    for (int j = 0; j < 10; j++) {
        #pragma unroll
        for (int o = 16; o > 0; o >>= 1) {
            acc[j] += __shfl_down_sync(0xffffffffu, acc[j], o);
        }
    }

    __shared__ float red[4][10];
    const int warp = t >> 5, lane = t & 31;
    if (lane == 0) {
        #pragma unroll
        for (int j = 0; j < 10; j++) { red[warp][j] = acc[j]; }
    }
    __syncthreads();

    if (t == 0) {
        float v[10];
        #pragma unroll
        for (int j = 0; j < 10; j++) {
            v[j] = red[0][j] + red[1][j] + red[2][j] + red[3][j];
        }
        float lmax = v[0]; int idx = 0;
        #pragma unroll
        for (int j = 1; j < 8; j++) {
            if (v[j] > lmax) { lmax = v[j]; idx = j; }
        }
        float s = 0.0f;
        #pragma unroll
        for (int j = 0; j < 8; j++) { s += expf(v[j] - lmax); }
        const float gate = 1.0f / s;
        const float c0 = v[8] + coef_b[0];
        const float c1 = v[9] + coef_b[1];
        const float cm = fmaxf(c0, c1);
        const float e0 = expf(c0 - cm), e1 = expf(c1 - cm);
        const float inv = 1.0f / (e0 + e1);
        g_s0[n] = gate * e0 * inv;
        g_s1[n] = e1 * inv;
        const int pos = atomicAdd(&g_counts[idx], 1);
        g_perm[idx * N_TOK + pos] = n;
    }
}

// ---- shared mainloop fragments (double-buffered; NPASS from scope) ----
#define LDFRAG(buf, st, s16) do {                                                \
    _Pragma("unroll")                                                             \
    for (int i_ = 0; i_ < 4; i_++) {                                              \
        const uint32_t a_ = swz128(wm * 64 + i_ * 16 + arow, (s16) * 2 + ach);    \
        ldsm4(ah[buf][i_], (st) + OFF_AH + a_);                                   \
        if (NPASS == 3) { ldsm4(al[buf][i_], (st) + OFF_AL + a_); }               \
    }                                                                             \
    _Pragma("unroll")                                                             \
    for (int j_ = 0; j_ < 2; j_++) {                                              \
        const uint32_t b_ = swz128(wn * 32 + j_ * 16 + brow, (s16) * 2 + bch);    \
        ldsm4(bh[buf][j_], (st) + OFF_BH + b_);                                   \
        ldsm4(bl[buf][j_], (st) + OFF_BL + b_);                                   \
    }                                                                             \
} while (0)

#define DOMMA(buf) do {                                                           \
    _Pragma("unroll")                                                             \
    for (int i_ = 0; i_ < 4; i_++) {                                              \
        _Pragma("unroll")                                                         \
        for (int j_ = 0; j_ < 4; j_++) {                                          \
            mma16816(acc[i_][j_], ah[buf][i_], &bh[buf][j_ >> 1][(j_ & 1) * 2]);  \
            mma16816(acc[i_][j_], ah[buf][i_], &bl[buf][j_ >> 1][(j_ & 1) * 2]);  \
            if (NPASS == 3) {                                                     \
                mma16816(acc[i_][j_], al[buf][i_], &bh[buf][j_ >> 1][(j_ & 1) * 2]); \
            }                                                                     \
        }                                                                         \
    }                                                                             \
} while (0)

// ---------------------------------------------------------------------------
// HMMA split-fp16 GEMM. CTA 128x128, BK=64, 8 warps (2x4), warp tile 64x32.
// NPASS=3: Ah*Bh + Ah*Bl + Al*Bh ; NPASS=2: Ah*Bh + Ah*Bl (A single fp16).
// 3-stage cp.async pipeline; double-buffered ldmatrix fragments.
// MODE 0: relu(acc+bias) -> split Chi/Clo ; MODE 1: (acc+bias)*rowscale -> Cf
// MODE 2: acc+bias -> Cf
// ---------------------------------------------------------------------------
template <int MODE, int NPASS>
__global__ __launch_bounds__(256, 1)
void hmma_gemm(const __half* __restrict__ Ahi, const __half* __restrict__ Alo,
               const __half* __restrict__ Bhi, const __half* __restrict__ Blo,
               const float* __restrict__ bias, int K, int Nn,
               __half* __restrict__ Chi, __half* __restrict__ Clo,
               float* __restrict__ Cf, const float* __restrict__ rowscale)
{
    extern __shared__ __align__(1024) char smem[];
    const uint32_t sb = smem_u32(smem);
    const int tid = threadIdx.x;
    const int lane = tid & 31, wid = tid >> 5;
    const int wm = wid >> 2, wn = wid & 3;           // 2 x 4 warp grid
    const int mrow0 = blockIdx.y * 128;
    const int ncol0 = blockIdx.x * 128;
    const int nt = K / 64;

    int lrow[4], lch[4];
    uint32_t lsw[4];
    #pragma unroll
    for (int i = 0; i < 4; i++) {
        const int slot = tid + 256 * i;
        lrow[i] = slot >> 3;
        lch[i]  = slot & 7;
        lsw[i]  = swz128(lrow[i], lch[i]);
    }

    #define LOADT(s, kt) do {                                                    \
        const uint32_t st_ = sb + (uint32_t)(s) * STG_BYTES;                      \
        _Pragma("unroll")                                                         \
        for (int i_ = 0; i_ < 4; i_++) {                                          \
            const size_t go_ = (size_t)(kt) * 64 + lch[i_] * 8;                   \
            cp16(st_ + OFF_AH + lsw[i_], Ahi + (size_t)(mrow0 + lrow[i_]) * K + go_); \
            if (NPASS == 3) {                                                     \
                cp16(st_ + OFF_AL + lsw[i_], Alo + (size_t)(mrow0 + lrow[i_]) * K + go_); \
            }                                                                     \
            cp16(st_ + OFF_BH + lsw[i_], Bhi + (size_t)(ncol0 + lrow[i_]) * K + go_); \
            cp16(st_ + OFF_BL + lsw[i_], Blo + (size_t)(ncol0 + lrow[i_]) * K + go_); \
        }                                                                         \
        CP_COMMIT();                                                              \
    } while (0)

    LOADT(0, 0);
    if (nt > 1) { LOADT(1, 1); } else { CP_COMMIT(); }

    float acc[4][4][4];
    #pragma unroll
    for (int i = 0; i < 4; i++) {
        #pragma unroll
        for (int j = 0; j < 4; j++) {
            #pragma unroll
            for (int q = 0; q < 4; q++) { acc[i][j][q] = 0.0f; }
        }
    }

    const int arow = (lane & 7) | (((lane >> 3) & 1) << 3);
    const int ach  = lane >> 4;
    const int brow = (lane & 7) | (((lane >> 4) & 1) << 3);
    const int bch  = (lane >> 3) & 1;

    uint32_t ah[2][4][4], al[2][4][4], bh[2][2][4], bl[2][2][4];

    for (int kt = 0; kt < nt; kt++) {
        if (kt + 1 < nt) { CP_WAIT(1); } else { CP_WAIT(0); }
        __syncthreads();
        if (kt + 2 < nt) { LOADT((kt + 2) % 3, kt + 2); }

        const uint32_t st = sb + (uint32_t)(kt % 3) * STG_BYTES;
        LDFRAG(0, st, 0);
        LDFRAG(1, st, 1);
        DOMMA(0);
        LDFRAG(0, st, 2);
        DOMMA(1);
        LDFRAG(1, st, 3);
        DOMMA(0);
        DOMMA(1);
    }

    // epilogue
    #pragma unroll
    for (int i = 0; i < 4; i++) {
        const int rb = mrow0 + wm * 64 + i * 16 + (lane >> 2);
        #pragma unroll
        for (int h = 0; h < 2; h++) {
            const int row = rb + h * 8;
            const float rs = (MODE == 1) ? rowscale[row] : 0.0f;
            #pragma unroll
            for (int j = 0; j < 4; j++) {
                const int col = ncol0 + wn * 32 + j * 8 + (lane & 3) * 2;
                float v0 = acc[i][j][h * 2 + 0] + bias[col];
                float v1 = acc[i][j][h * 2 + 1] + bias[col + 1];
                if (MODE == 0) {
                    v0 = fmaxf(v0, 0.0f); v1 = fmaxf(v1, 0.0f);
                    __half h0, l0, h1, l1;
                    splitf(v0, h0, l0); splitf(v1, h1, l1);
                    *(__half2*)(Chi + (size_t)row * Nn + col) = __halves2half2(h0, h1);
                    *(__half2*)(Clo + (size_t)row * Nn + col) = __halves2half2(l0, l1);
                } else if (MODE == 1) {
                    *(float2*)(Cf + (size_t)row * Nn + col) = make_float2(v0 * rs, v1 * rs);
                } else {
                    *(float2*)(Cf + (size_t)row * Nn + col) = make_float2(v0, v1);
                }
            }
        }
    }
    #undef LOADT
}

// ---------------------------------------------------------------------------
// Grouped expert GEMM (2-pass): A = hhi rows gathered via g_perm; epilogue
// uhi = fp16(g_u[tok] + (acc + b_e) * s0[tok]).
// ---------------------------------------------------------------------------
__global__ __launch_bounds__(256, 1)
void hmma_gemm_grouped(const float* __restrict__ bexp)
{
    constexpr int NPASS = 2;
    extern __shared__ __align__(1024) char smem[];
    const int e = blockIdx.z;
    const int cnt = g_counts[e];
    const int rowBase = blockIdx.y * 128;
    if (rowBase >= cnt) return;

    const uint32_t sb = smem_u32(smem);
    const int tid = threadIdx.x;
    const int lane = tid & 31, wid = tid >> 5;
    const int wm = wid >> 2, wn = wid & 3;
    const int ncol0 = blockIdx.x * 128;
    const int nt = HID / 64;
    int* rmap = (int*)(smem + SM_RMAP);

    if (tid < 128) {
        int i = rowBase + tid;
        if (i > cnt - 1) i = cnt - 1;
        rmap[tid] = g_perm[e * N_TOK + i];
    }
    __syncthreads();

    const __half* Bhi = g_Whi + W_EXP_OFF + (size_t)e * HID * HID;
    const __half* Blo = g_Wlo + W_EXP_OFF + (size_t)e * HID * HID;

    int lrow[4], lch[4];
    uint32_t lsw[4];
    size_t ga[4];
    #pragma unroll
    for (int i = 0; i < 4; i++) {
        const int slot = tid + 256 * i;
        lrow[i] = slot >> 3;
        lch[i]  = slot & 7;
        lsw[i]  = swz128(lrow[i], lch[i]);
        ga[i]   = (size_t)rmap[lrow[i]] * HID;
    }

    #define LOADG(s, kt) do {                                                    \
        const uint32_t st_ = sb + (uint32_t)(s) * STG_BYTES;                      \
        _Pragma("unroll")                                                         \
        for (int i_ = 0; i_ < 4; i_++) {                                          \
            const size_t go_ = (size_t)(kt) * 64 + lch[i_] * 8;                   \
            cp16(st_ + OFF_AH + lsw[i_], g_hhi + ga[i_] + go_);                   \
            cp16(st_ + OFF_BH + lsw[i_], Bhi + (size_t)(ncol0 + lrow[i_]) * HID + go_); \
            cp16(st_ + OFF_BL + lsw[i_], Blo + (size_t)(ncol0 + lrow[i_]) * HID + go_); \
        }                                                                         \
        CP_COMMIT();                                                              \
    } while (0)

    LOADG(0, 0);
    LOADG(1, 1);

    float acc[4][4][4];
    #pragma unroll
    for (int i = 0; i < 4; i++) {
        #pragma unroll
        for (int j = 0; j < 4; j++) {
            #pragma unroll
            for (int q = 0; q < 4; q++) { acc[i][j][q] = 0.0f; }
        }
    }

    const int arow = (lane & 7) | (((lane >> 3) & 1) << 3);
    const int ach  = lane >> 4;
    const int brow = (lane & 7) | (((lane >> 4) & 1) << 3);
    const int bch  = (lane >> 3) & 1;

    uint32_t ah[2][4][4], al[2][4][4], bh[2][2][4], bl[2][2][4];
    (void)al;

    for (int kt = 0; kt < nt; kt++) {
        if (kt + 1 < nt) { CP_WAIT(1); } else { CP_WAIT(0); }
        __syncthreads();
        if (kt + 2 < nt) { LOADG((kt + 2) % 3, kt + 2); }

        const uint32_t st = sb + (uint32_t)(kt % 3) * STG_BYTES;
        LDFRAG(0, st, 0);
        LDFRAG(1, st, 1);
        DOMMA(0);
        LDFRAG(0, st, 2);
        DOMMA(1);
        LDFRAG(1, st, 3);
        DOMMA(0);
        DOMMA(1);
    }

    #pragma unroll
    for (int i = 0; i < 4; i++) {
        const int lb = wm * 64 + i * 16 + (lane >> 2);
        #pragma unroll
        for (int h = 0; h < 2; h++) {
            const int li = lb + h * 8;
            if (rowBase + li >= cnt) continue;
            const int tok = rmap[li];
            const float s0 = g_s0[tok];
            #pragma unroll
            for (int j = 0; j < 4; j++) {
                const int col = ncol0 + wn * 32 + j * 8 + (lane & 3) * 2;
                float2 u2 = *(const float2*)(g_u + (size_t)tok * HID + col);
                float v0 = u2.x + (acc[i][j][h * 2 + 0] + bexp[e * HID + col]) * s0;
                float v1 = u2.y + (acc[i][j][h * 2 + 1] + bexp[e * HID + col + 1]) * s0;
                *(__half2*)(g_uhi + (size_t)tok * HID + col) =
                    __halves2half2(__float2half_rn(v0), __float2half_rn(v1));
            }
        }
    }
    #undef LOADG
}

// ---------------------------------------------------------------------------
extern "C" void kernel_launch(void* const* d_in, const int* in_sizes, int n_in,
                              void* d_out, int out_size)
{
    const float* x        = (const float*)d_in[0];
    const float* enc_W    = (const float*)d_in[1];
    const float* enc_b    = (const float*)d_in[2];
    const float* gate_W   = (const float*)d_in[3];
    const float* expert_W = (const float*)d_in[4];
    const float* expert_b = (const float*)d_in[5];
    const float* res_W    = (const float*)d_in[6];
    const float* res_b    = (const float*)d_in[7];
    const float* coef_W   = (const float*)d_in[8];
    const float* coef_b   = (const float*)d_in[9];
    const float* dec_W    = (const float*)d_in[10];
    const float* dec_b    = (const float*)d_in[11];
    float* out = (float*)d_out;

    __half *xhi, *xlo, *hhi, *hlo, *uhi, *whi, *wlo;
    float *up, *s1p;
    cudaGetSymbolAddress((void**)&xhi, g_xhi);
    cudaGetSymbolAddress((void**)&xlo, g_xlo);
    cudaGetSymbolAddress((void**)&hhi, g_hhi);
    cudaGetSymbolAddress((void**)&hlo, g_hlo);
    cudaGetSymbolAddress((void**)&uhi, g_uhi);
    cudaGetSymbolAddress((void**)&whi, g_Whi);
    cudaGetSymbolAddress((void**)&wlo, g_Wlo);
    cudaGetSymbolAddress((void**)&up,  g_u);
    cudaGetSymbolAddress((void**)&s1p, g_s1);

    cudaFuncSetAttribute((const void*)hmma_gemm<0,3>, cudaFuncAttributeMaxDynamicSharedMemorySize, SMEM_TOT);
    cudaFuncSetAttribute((const void*)hmma_gemm<1,2>, cudaFuncAttributeMaxDynamicSharedMemorySize, SMEM_TOT);
    cudaFuncSetAttribute((const void*)hmma_gemm<2,2>, cudaFuncAttributeMaxDynamicSharedMemorySize, SMEM_TOT);
    cudaFuncSetAttribute((const void*)hmma_gemm_grouped, cudaFuncAttributeMaxDynamicSharedMemorySize, SMEM_TOT);

    // ---- precompute: splits + weight transposes ([K,N] -> [N,K] hi/lo) ----
    conv_x_kernel<<<(N_TOK * IN_DIM) / 1024, 256>>>(x);
    transpose_conv<<<dim3(HID/32, IN_DIM/32, 1),  dim3(32, 8)>>>(enc_W,    whi + W_ENC_OFF, wlo + W_ENC_OFF, IN_DIM, HID);
    transpose_conv<<<dim3(HID/32, HID/32, 1),     dim3(32, 8)>>>(res_W,    whi + W_RES_OFF, wlo + W_RES_OFF, HID, HID);
    transpose_conv<<<dim3(HID/32, HID/32, NEXP),  dim3(32, 8)>>>(expert_W, whi + W_EXP_OFF, wlo + W_EXP_OFF, HID, HID);
    transpose_conv<<<dim3(IN_DIM/32, HID/32, 1),  dim3(32, 8)>>>(dec_W,    whi + W_DEC_OFF, wlo + W_DEC_OFF, HID, IN_DIM);
    zero_counts_kernel<<<1, 32>>>();

    // ---- h = relu(x @ enc_W + enc_b) : 3-pass (protects gating argmax) ----
    hmma_gemm<0,3><<<dim3(HID/128, N_TOK/128), 256, SMEM_TOT>>>(
        xhi, xlo, whi + W_ENC_OFF, wlo + W_ENC_OFF,
        enc_b, IN_DIM, HID, hhi, hlo, nullptr, nullptr);

    // ---- gating ----
    gating_kernel<<<N_TOK, 128>>>(gate_W, coef_W, coef_b);

    // ---- u = (h @ res_W + res_b) * s1 : 2-pass ----
    hmma_gemm<1,2><<<dim3(HID/128, N_TOK/128), 256, SMEM_TOT>>>(
        hhi, nullptr, whi + W_RES_OFF, wlo + W_RES_OFF,
        res_b, HID, HID, nullptr, nullptr, up, s1p);

    // ---- u += (h @ W_e + b_e) * s0 : 2-pass grouped ----
    hmma_gemm_grouped<<<dim3(HID/128, N_TOK/128, NEXP), 256, SMEM_TOT>>>(expert_b);

    // ---- out = u @ dec_W + dec_b : 2-pass ----
    hmma_gemm<2,2><<<dim3(IN_DIM/128, N_TOK/128), 256, SMEM_TOT>>>(
        uhi, nullptr, whi + W_DEC_OFF, wlo + W_DEC_OFF,
        dec_b, HID, IN_DIM, nullptr, nullptr, out, nullptr);
}

// round 9
// speedup vs baseline: 4.8831x; 1.3153x over previous
#include <cuda_runtime.h>
#include <cuda_fp16.h>
#include <cuda.h>
#include <cstdint>
#include <math.h>

#define N_TOK  16384
#define IN_DIM 1024
#define HID    2048
#define NEXP   8

// ---- device scratch (globals: allocation-free) ----
__device__ __align__(128) __half g_xhi[(size_t)N_TOK * IN_DIM];
__device__ __align__(128) __half g_xlo[(size_t)N_TOK * IN_DIM];
__device__ __align__(128) __half g_hhi[(size_t)N_TOK * HID];
__device__ __align__(128) __half g_hlo[(size_t)N_TOK * HID];
__device__ __align__(128) __half g_uhi[(size_t)N_TOK * HID];
__device__ __align__(128) float  g_u[(size_t)N_TOK * HID];

#define W_ENC_OFF 0
#define W_RES_OFF (2048*1024)
#define W_EXP_OFF (W_RES_OFF + 2048*2048)
#define W_DEC_OFF (W_EXP_OFF + 8*2048*2048)
#define W_TOTAL   (W_DEC_OFF + 1024*2048)
__device__ __align__(128) __half g_Whi[(size_t)W_TOTAL];
__device__ __align__(128) __half g_Wlo[(size_t)W_TOTAL];   // only enc's lo is used now

__device__ int   g_perm[NEXP * N_TOK];
__device__ int   g_counts[NEXP];
__device__ float g_s0[N_TOK];
__device__ float g_s1[N_TOK];

// ---- SMEM: 3 stages x (Ah,Al,Bh,Bl each 16KB: 128 rows x 128B) = 192KB ----
#define STG_BYTES 65536
#define OFF_AH 0
#define OFF_AL 16384
#define OFF_BH 32768
#define OFF_BL 49152
#define SM_RMAP (3 * STG_BYTES)
#define SMEM_TOT (3 * STG_BYTES + 512)

// ---- PTX helpers ----
__device__ __forceinline__ uint32_t smem_u32(const void* p) {
    uint32_t r;
    asm("{ .reg .u64 t; cvta.to.shared.u64 t, %1; cvt.u32.u64 %0, t; }" : "=r"(r) : "l"(p));
    return r;
}
__device__ __forceinline__ void cp16(uint32_t s, const void* g) {
    asm volatile("cp.async.cg.shared.global [%0], [%1], 16;" :: "r"(s), "l"(g));
}
#define CP_COMMIT() asm volatile("cp.async.commit_group;" ::: "memory")
#define CP_WAIT(n)  asm volatile("cp.async.wait_group %0;" :: "n"(n) : "memory")

__device__ __forceinline__ void ldsm4(uint32_t* r, uint32_t a) {
    asm volatile("ldmatrix.sync.aligned.m8n8.x4.shared.b16 {%0,%1,%2,%3}, [%4];"
                 : "=r"(r[0]), "=r"(r[1]), "=r"(r[2]), "=r"(r[3]) : "r"(a));
}
__device__ __forceinline__ void mma16816(float* c, const uint32_t* a, const uint32_t* b) {
    asm volatile(
        "mma.sync.aligned.m16n8k16.row.col.f32.f16.f16.f32 "
        "{%0,%1,%2,%3}, {%4,%5,%6,%7}, {%8,%9}, {%0,%1,%2,%3};"
        : "+f"(c[0]), "+f"(c[1]), "+f"(c[2]), "+f"(c[3])
        : "r"(a[0]), "r"(a[1]), "r"(a[2]), "r"(a[3]), "r"(b[0]), "r"(b[1]));
}

// 128B-row XOR swizzle: conflict-free for ldmatrix and coalesced stores
__device__ __forceinline__ uint32_t swz128(int row, int chunk) {
    return (uint32_t)(row * 128 + ((chunk ^ (row & 7)) * 16));
}

__device__ __forceinline__ void splitf(float v, __half& h, __half& l) {
    h = __float2half_rn(v);
    l = __float2half_rn(v - __half2float(h));
}

// ---- small kernels ----
__global__ void zero_counts_kernel() {
    if (threadIdx.x < NEXP) g_counts[threadIdx.x] = 0;
}

__global__ __launch_bounds__(256) void conv_x_kernel(const float* __restrict__ x) {
    size_t i = ((size_t)blockIdx.x * 256 + threadIdx.x) * 4;
    float4 v = *(const float4*)(x + i);
    __half hb[4], lb[4];
    splitf(v.x, hb[0], lb[0]); splitf(v.y, hb[1], lb[1]);
    splitf(v.z, hb[2], lb[2]); splitf(v.w, hb[3], lb[3]);
    *(uint2*)(g_xhi + i) = *(uint2*)hb;
    *(uint2*)(g_xlo + i) = *(uint2*)lb;
}

// src [K,N] fp32 (batched over z) -> dst [N,K] fp16 hi (+lo if dlo != null)
__global__ __launch_bounds__(256)
void transpose_conv(const float* __restrict__ src, __half* __restrict__ dhi,
                    __half* __restrict__ dlo, int K, int N)
{
    __shared__ float t[32][33];
    const size_t zoff = (size_t)blockIdx.z * K * N;
    const int n0 = blockIdx.x * 32, k0 = blockIdx.y * 32;
    const int tx = threadIdx.x, ty = threadIdx.y;
    #pragma unroll
    for (int i = 0; i < 4; i++) {
        t[ty + i*8][tx] = src[zoff + (size_t)(k0 + ty + i*8) * N + n0 + tx];
    }
    __syncthreads();
    #pragma unroll
    for (int i = 0; i < 4; i++) {
        const int n = n0 + ty + i*8, k = k0 + tx;
        __half h, l;
        splitf(t[tx][ty + i*8], h, l);
        dhi[zoff + (size_t)n * K + k] = h;
        if (dlo) { dlo[zoff + (size_t)n * K + k] = l; }
    }
}

// ---- gating ----
__global__ __launch_bounds__(128)
void gating_kernel(const float* __restrict__ gate_W, const float* __restrict__ coef_W,
                   const float* __restrict__ coef_b)
{
    const int n = blockIdx.x;
    const int t = threadIdx.x;
    float acc[10];
    #pragma unroll
    for (int j = 0; j < 10; j++) { acc[j] = 0.0f; }

    const __half* hh = g_hhi + (size_t)n * HID;
    const __half* hl = g_hlo + (size_t)n * HID;
    for (int k = t; k < HID; k += 128) {
        const float hv = __half2float(hh[k]) + __half2float(hl[k]);
        #pragma unroll
        for (int j = 0; j < 8; j++) { acc[j] += hv * gate_W[k * 8 + j]; }
        acc[8] += hv * coef_W[k * 2 + 0];
        acc[9] += hv * coef_W[k * 2 + 1];
    }
    #pragma unroll
    for (int j = 0; j < 10; j++) {
        #pragma unroll
        for (int o = 16; o > 0; o >>= 1) {
            acc[j] += __shfl_down_sync(0xffffffffu, acc[j], o);
        }
    }

    __shared__ float red[4][10];
    const int warp = t >> 5, lane = t & 31;
    if (lane == 0) {
        #pragma unroll
        for (int j = 0; j < 10; j++) { red[warp][j] = acc[j]; }
    }
    __syncthreads();

    if (t == 0) {
        float v[10];
        #pragma unroll
        for (int j = 0; j < 10; j++) {
            v[j] = red[0][j] + red[1][j] + red[2][j] + red[3][j];
        }
        float lmax = v[0]; int idx = 0;
        #pragma unroll
        for (int j = 1; j < 8; j++) {
            if (v[j] > lmax) { lmax = v[j]; idx = j; }
        }
        float s = 0.0f;
        #pragma unroll
        for (int j = 0; j < 8; j++) { s += expf(v[j] - lmax); }
        const float gate = 1.0f / s;
        const float c0 = v[8] + coef_b[0];
        const float c1 = v[9] + coef_b[1];
        const float cm = fmaxf(c0, c1);
        const float e0 = expf(c0 - cm), e1 = expf(c1 - cm);
        const float inv = 1.0f / (e0 + e1);
        g_s0[n] = gate * e0 * inv;
        g_s1[n] = e1 * inv;
        const int pos = atomicAdd(&g_counts[idx], 1);
        g_perm[idx * N_TOK + pos] = n;
    }
}

// ---- shared mainloop fragments (double-buffered; NPASS from scope) ----
// NPASS==1: Ah*Bh ; NPASS==3: Ah*Bh + Ah*Bl + Al*Bh
#define LDFRAG(buf, st, s16) do {                                                \
    _Pragma("unroll")                                                             \
    for (int i_ = 0; i_ < 4; i_++) {                                              \
        const uint32_t a_ = swz128(wm * 64 + i_ * 16 + arow, (s16) * 2 + ach);    \
        ldsm4(ah[buf][i_], (st) + OFF_AH + a_);                                   \
        if (NPASS == 3) { ldsm4(al[buf][i_], (st) + OFF_AL + a_); }               \
    }                                                                             \
    _Pragma("unroll")                                                             \
    for (int j_ = 0; j_ < 2; j_++) {                                              \
        const uint32_t b_ = swz128(wn * 32 + j_ * 16 + brow, (s16) * 2 + bch);    \
        ldsm4(bh[buf][j_], (st) + OFF_BH + b_);                                   \
        if (NPASS >= 2) { ldsm4(bl[buf][j_], (st) + OFF_BL + b_); }               \
    }                                                                             \
} while (0)

#define DOMMA(buf) do {                                                           \
    _Pragma("unroll")                                                             \
    for (int i_ = 0; i_ < 4; i_++) {                                              \
        _Pragma("unroll")                                                         \
        for (int j_ = 0; j_ < 4; j_++) {                                          \
            mma16816(acc[i_][j_], ah[buf][i_], &bh[buf][j_ >> 1][(j_ & 1) * 2]);  \
            if (NPASS >= 2) {                                                     \
                mma16816(acc[i_][j_], ah[buf][i_], &bl[buf][j_ >> 1][(j_ & 1) * 2]); \
            }                                                                     \
            if (NPASS == 3) {                                                     \
                mma16816(acc[i_][j_], al[buf][i_], &bh[buf][j_ >> 1][(j_ & 1) * 2]); \
            }                                                                     \
        }                                                                         \
    }                                                                             \
} while (0)

// ---------------------------------------------------------------------------
// HMMA GEMM. CTA 128x128, BK=64, 8 warps (2x4), warp tile 64x32.
// 3-stage cp.async pipeline; double-buffered ldmatrix fragments.
// MODE 0: relu(acc+bias) -> split Chi/Clo ; MODE 1: (acc+bias)*rowscale -> Cf
// MODE 2: acc+bias -> Cf
// ---------------------------------------------------------------------------
template <int MODE, int NPASS>
__global__ __launch_bounds__(256, 1)
void hmma_gemm(const __half* __restrict__ Ahi, const __half* __restrict__ Alo,
               const __half* __restrict__ Bhi, const __half* __restrict__ Blo,
               const float* __restrict__ bias, int K, int Nn,
               __half* __restrict__ Chi, __half* __restrict__ Clo,
               float* __restrict__ Cf, const float* __restrict__ rowscale)
{
    extern __shared__ __align__(1024) char smem[];
    const uint32_t sb = smem_u32(smem);
    const int tid = threadIdx.x;
    const int lane = tid & 31, wid = tid >> 5;
    const int wm = wid >> 2, wn = wid & 3;           // 2 x 4 warp grid
    const int mrow0 = blockIdx.y * 128;
    const int ncol0 = blockIdx.x * 128;
    const int nt = K / 64;

    int lrow[4], lch[4];
    uint32_t lsw[4];
    #pragma unroll
    for (int i = 0; i < 4; i++) {
        const int slot = tid + 256 * i;
        lrow[i] = slot >> 3;
        lch[i]  = slot & 7;
        lsw[i]  = swz128(lrow[i], lch[i]);
    }

    #define LOADT(s, kt) do {                                                    \
        const uint32_t st_ = sb + (uint32_t)(s) * STG_BYTES;                      \
        _Pragma("unroll")                                                         \
        for (int i_ = 0; i_ < 4; i_++) {                                          \
            const size_t go_ = (size_t)(kt) * 64 + lch[i_] * 8;                   \
            cp16(st_ + OFF_AH + lsw[i_], Ahi + (size_t)(mrow0 + lrow[i_]) * K + go_); \
            if (NPASS == 3) {                                                     \
                cp16(st_ + OFF_AL + lsw[i_], Alo + (size_t)(mrow0 + lrow[i_]) * K + go_); \
            }                                                                     \
            cp16(st_ + OFF_BH + lsw[i_], Bhi + (size_t)(ncol0 + lrow[i_]) * K + go_); \
            if (NPASS >= 2) {                                                     \
                cp16(st_ + OFF_BL + lsw[i_], Blo + (size_t)(ncol0 + lrow[i_]) * K + go_); \
            }                                                                     \
        }                                                                         \
        CP_COMMIT();                                                              \
    } while (0)

    LOADT(0, 0);
    if (nt > 1) { LOADT(1, 1); } else { CP_COMMIT(); }

    float acc[4][4][4];
    #pragma unroll
    for (int i = 0; i < 4; i++) {
        #pragma unroll
        for (int j = 0; j < 4; j++) {
            #pragma unroll
            for (int q = 0; q < 4; q++) { acc[i][j][q] = 0.0f; }
        }
    }

    const int arow = (lane & 7) | (((lane >> 3) & 1) << 3);
    const int ach  = lane >> 4;
    const int brow = (lane & 7) | (((lane >> 4) & 1) << 3);
    const int bch  = (lane >> 3) & 1;

    uint32_t ah[2][4][4], al[2][4][4], bh[2][2][4], bl[2][2][4];

    for (int kt = 0; kt < nt; kt++) {
        if (kt + 1 < nt) { CP_WAIT(1); } else { CP_WAIT(0); }
        __syncthreads();
        if (kt + 2 < nt) { LOADT((kt + 2) % 3, kt + 2); }

        const uint32_t st = sb + (uint32_t)(kt % 3) * STG_BYTES;
        LDFRAG(0, st, 0);
        LDFRAG(1, st, 1);
        DOMMA(0);
        LDFRAG(0, st, 2);
        DOMMA(1);
        LDFRAG(1, st, 3);
        DOMMA(0);
        DOMMA(1);
    }

    // epilogue
    #pragma unroll
    for (int i = 0; i < 4; i++) {
        const int rb = mrow0 + wm * 64 + i * 16 + (lane >> 2);
        #pragma unroll
        for (int h = 0; h < 2; h++) {
            const int row = rb + h * 8;
            const float rs = (MODE == 1) ? rowscale[row] : 0.0f;
            #pragma unroll
            for (int j = 0; j < 4; j++) {
                const int col = ncol0 + wn * 32 + j * 8 + (lane & 3) * 2;
                float v0 = acc[i][j][h * 2 + 0] + bias[col];
                float v1 = acc[i][j][h * 2 + 1] + bias[col + 1];
                if (MODE == 0) {
                    v0 = fmaxf(v0, 0.0f); v1 = fmaxf(v1, 0.0f);
                    __half h0, l0, h1, l1;
                    splitf(v0, h0, l0); splitf(v1, h1, l1);
                    *(__half2*)(Chi + (size_t)row * Nn + col) = __halves2half2(h0, h1);
                    *(__half2*)(Clo + (size_t)row * Nn + col) = __halves2half2(l0, l1);
                } else if (MODE == 1) {
                    *(float2*)(Cf + (size_t)row * Nn + col) = make_float2(v0 * rs, v1 * rs);
                } else {
                    *(float2*)(Cf + (size_t)row * Nn + col) = make_float2(v0, v1);
                }
            }
        }
    }
    #undef LOADT
}

// ---------------------------------------------------------------------------
// Grouped expert GEMM (1-pass): A = hhi rows gathered via g_perm; epilogue
// uhi = fp16(g_u[tok] + (acc + b_e) * s0[tok]).
// ---------------------------------------------------------------------------
__global__ __launch_bounds__(256, 1)
void hmma_gemm_grouped(const float* __restrict__ bexp)
{
    constexpr int NPASS = 1;
    extern __shared__ __align__(1024) char smem[];
    const int e = blockIdx.z;
    const int cnt = g_counts[e];
    const int rowBase = blockIdx.y * 128;
    if (rowBase >= cnt) return;

    const uint32_t sb = smem_u32(smem);
    const int tid = threadIdx.x;
    const int lane = tid & 31, wid = tid >> 5;
    const int wm = wid >> 2, wn = wid & 3;
    const int ncol0 = blockIdx.x * 128;
    const int nt = HID / 64;
    int* rmap = (int*)(smem + SM_RMAP);

    if (tid < 128) {
        int i = rowBase + tid;
        if (i > cnt - 1) i = cnt - 1;
        rmap[tid] = g_perm[e * N_TOK + i];
    }
    __syncthreads();

    const __half* Bhi = g_Whi + W_EXP_OFF + (size_t)e * HID * HID;

    int lrow[4], lch[4];
    uint32_t lsw[4];
    size_t ga[4];
    #pragma unroll
    for (int i = 0; i < 4; i++) {
        const int slot = tid + 256 * i;
        lrow[i] = slot >> 3;
        lch[i]  = slot & 7;
        lsw[i]  = swz128(lrow[i], lch[i]);
        ga[i]   = (size_t)rmap[lrow[i]] * HID;
    }

    #define LOADG(s, kt) do {                                                    \
        const uint32_t st_ = sb + (uint32_t)(s) * STG_BYTES;                      \
        _Pragma("unroll")                                                         \
        for (int i_ = 0; i_ < 4; i_++) {                                          \
            const size_t go_ = (size_t)(kt) * 64 + lch[i_] * 8;                   \
            cp16(st_ + OFF_AH + lsw[i_], g_hhi + ga[i_] + go_);                   \
            cp16(st_ + OFF_BH + lsw[i_], Bhi + (size_t)(ncol0 + lrow[i_]) * HID + go_); \
        }                                                                         \
        CP_COMMIT();                                                              \
    } while (0)

    LOADG(0, 0);
    LOADG(1, 1);

    float acc[4][4][4];
    #pragma unroll
    for (int i = 0; i < 4; i++) {
        #pragma unroll
        for (int j = 0; j < 4; j++) {
            #pragma unroll
            for (int q = 0; q < 4; q++) { acc[i][j][q] = 0.0f; }
        }
    }

    const int arow = (lane & 7) | (((lane >> 3) & 1) << 3);
    const int ach  = lane >> 4;
    const int brow = (lane & 7) | (((lane >> 4) & 1) << 3);
    const int bch  = (lane >> 3) & 1;

    uint32_t ah[2][4][4], al[2][4][4], bh[2][2][4], bl[2][2][4];
    (void)al; (void)bl;

    for (int kt = 0; kt < nt; kt++) {
        if (kt + 1 < nt) { CP_WAIT(1); } else { CP_WAIT(0); }
        __syncthreads();
        if (kt + 2 < nt) { LOADG((kt + 2) % 3, kt + 2); }

        const uint32_t st = sb + (uint32_t)(kt % 3) * STG_BYTES;
        LDFRAG(0, st, 0);
        LDFRAG(1, st, 1);
        DOMMA(0);
        LDFRAG(0, st, 2);
        DOMMA(1);
        LDFRAG(1, st, 3);
        DOMMA(0);
        DOMMA(1);
    }

    #pragma unroll
    for (int i = 0; i < 4; i++) {
        const int lb = wm * 64 + i * 16 + (lane >> 2);
        #pragma unroll
        for (int h = 0; h < 2; h++) {
            const int li = lb + h * 8;
            if (rowBase + li >= cnt) continue;
            const int tok = rmap[li];
            const float s0 = g_s0[tok];
            #pragma unroll
            for (int j = 0; j < 4; j++) {
                const int col = ncol0 + wn * 32 + j * 8 + (lane & 3) * 2;
                float2 u2 = *(const float2*)(g_u + (size_t)tok * HID + col);
                float v0 = u2.x + (acc[i][j][h * 2 + 0] + bexp[e * HID + col]) * s0;
                float v1 = u2.y + (acc[i][j][h * 2 + 1] + bexp[e * HID + col + 1]) * s0;
                *(__half2*)(g_uhi + (size_t)tok * HID + col) =
                    __halves2half2(__float2half_rn(v0), __float2half_rn(v1));
            }
        }
    }
    #undef LOADG
}

// ---------------------------------------------------------------------------
extern "C" void kernel_launch(void* const* d_in, const int* in_sizes, int n_in,
                              void* d_out, int out_size)
{
    const float* x        = (const float*)d_in[0];
    const float* enc_W    = (const float*)d_in[1];
    const float* enc_b    = (const float*)d_in[2];
    const float* gate_W   = (const float*)d_in[3];
    const float* expert_W = (const float*)d_in[4];
    const float* expert_b = (const float*)d_in[5];
    const float* res_W    = (const float*)d_in[6];
    const float* res_b    = (const float*)d_in[7];
    const float* coef_W   = (const float*)d_in[8];
    const float* coef_b   = (const float*)d_in[9];
    const float* dec_W    = (const float*)d_in[10];
    const float* dec_b    = (const float*)d_in[11];
    float* out = (float*)d_out;

    __half *xhi, *xlo, *hhi, *hlo, *uhi, *whi, *wlo;
    float *up, *s1p;
    cudaGetSymbolAddress((void**)&xhi, g_xhi);
    cudaGetSymbolAddress((void**)&xlo, g_xlo);
    cudaGetSymbolAddress((void**)&hhi, g_hhi);
    cudaGetSymbolAddress((void**)&hlo, g_hlo);
    cudaGetSymbolAddress((void**)&uhi, g_uhi);
    cudaGetSymbolAddress((void**)&whi, g_Whi);
    cudaGetSymbolAddress((void**)&wlo, g_Wlo);
    cudaGetSymbolAddress((void**)&up,  g_u);
    cudaGetSymbolAddress((void**)&s1p, g_s1);

    cudaFuncSetAttribute((const void*)hmma_gemm<0,3>, cudaFuncAttributeMaxDynamicSharedMemorySize, SMEM_TOT);
    cudaFuncSetAttribute((const void*)hmma_gemm<1,1>, cudaFuncAttributeMaxDynamicSharedMemorySize, SMEM_TOT);
    cudaFuncSetAttribute((const void*)hmma_gemm<2,1>, cudaFuncAttributeMaxDynamicSharedMemorySize, SMEM_TOT);
    cudaFuncSetAttribute((const void*)hmma_gemm_grouped, cudaFuncAttributeMaxDynamicSharedMemorySize, SMEM_TOT);

    // ---- precompute: splits + weight transposes ([K,N] -> [N,K]) ----
    conv_x_kernel<<<(N_TOK * IN_DIM) / 1024, 256>>>(x);
    transpose_conv<<<dim3(HID/32, IN_DIM/32, 1),  dim3(32, 8)>>>(enc_W,    whi + W_ENC_OFF, wlo + W_ENC_OFF, IN_DIM, HID);
    transpose_conv<<<dim3(HID/32, HID/32, 1),     dim3(32, 8)>>>(res_W,    whi + W_RES_OFF, nullptr, HID, HID);
    transpose_conv<<<dim3(HID/32, HID/32, NEXP),  dim3(32, 8)>>>(expert_W, whi + W_EXP_OFF, nullptr, HID, HID);
    transpose_conv<<<dim3(IN_DIM/32, HID/32, 1),  dim3(32, 8)>>>(dec_W,    whi + W_DEC_OFF, nullptr, HID, IN_DIM);
    zero_counts_kernel<<<1, 32>>>();

    // ---- h = relu(x @ enc_W + enc_b) : 3-pass (protects gating argmax) ----
    hmma_gemm<0,3><<<dim3(HID/128, N_TOK/128), 256, SMEM_TOT>>>(
        xhi, xlo, whi + W_ENC_OFF, wlo + W_ENC_OFF,
        enc_b, IN_DIM, HID, hhi, hlo, nullptr, nullptr);

    // ---- gating ----
    gating_kernel<<<N_TOK, 128>>>(gate_W, coef_W, coef_b);

    // ---- u = (h @ res_W + res_b) * s1 : 1-pass ----
    hmma_gemm<1,1><<<dim3(HID/128, N_TOK/128), 256, SMEM_TOT>>>(
        hhi, nullptr, whi + W_RES_OFF, nullptr,
        res_b, HID, HID, nullptr, nullptr, up, s1p);

    // ---- u += (h @ W_e + b_e) * s0 : 1-pass grouped ----
    hmma_gemm_grouped<<<dim3(HID/128, N_TOK/128, NEXP), 256, SMEM_TOT>>>(expert_b);

    // ---- out = u @ dec_W + dec_b : 1-pass ----
    hmma_gemm<2,1><<<dim3(IN_DIM/128, N_TOK/128), 256, SMEM_TOT>>>(
        uhi, nullptr, whi + W_DEC_OFF, nullptr,
        dec_b, HID, IN_DIM, nullptr, nullptr, out, nullptr);
}

// round 10
// speedup vs baseline: 5.0929x; 1.0430x over previous
#include <cuda_runtime.h>
#include <cuda_fp16.h>
#include <cuda.h>
#include <cstdint>
#include <math.h>

#define N_TOK  16384
#define IN_DIM 1024
#define HID    2048
#define NEXP   8

// ---- device scratch (globals: allocation-free) ----
__device__ __align__(128) __half g_xhi[(size_t)N_TOK * IN_DIM];
__device__ __align__(128) __half g_xlo[(size_t)N_TOK * IN_DIM];
__device__ __align__(128) __half g_hhi[(size_t)N_TOK * HID];
__device__ __align__(128) __half g_hlo[(size_t)N_TOK * HID];
__device__ __align__(128) __half g_uhi[(size_t)N_TOK * HID];
__device__ __align__(128) float  g_u[(size_t)N_TOK * HID];

#define W_ENC_OFF 0
#define W_RES_OFF (2048*1024)
#define W_EXP_OFF (W_RES_OFF + 2048*2048)
#define W_DEC_OFF (W_EXP_OFF + 8*2048*2048)
#define W_TOTAL   (W_DEC_OFF + 1024*2048)
__device__ __align__(128) __half g_Whi[(size_t)W_TOTAL];
__device__ __align__(128) __half g_Wlo[(size_t)W_TOTAL];   // only enc's lo used

__device__ int   g_perm[NEXP * N_TOK];
__device__ int   g_counts[NEXP];
__device__ float g_s0[N_TOK];
__device__ float g_s1[N_TOK];

// ---- enc kernel SMEM: 3 stages x (Ah,Al,Bh,Bl each 16KB) = 192KB ----
#define STG_BYTES 65536
#define OFF_AH 0
#define OFF_AL 16384
#define OFF_BH 32768
#define OFF_BL 49152
#define SMEM_TOT (3 * STG_BYTES + 512)

// ---- big-tile (256x128, 1-pass) SMEM: 3 stages x (A 32KB + B 16KB) ----
#define BSTG 49152
#define BOFF_A 0
#define BOFF_B 32768
#define BSM_RMAP (3 * BSTG)
#define BSMEM_TOT (3 * BSTG + 1152)

// ---- PTX helpers ----
__device__ __forceinline__ uint32_t smem_u32(const void* p) {
    uint32_t r;
    asm("{ .reg .u64 t; cvta.to.shared.u64 t, %1; cvt.u32.u64 %0, t; }" : "=r"(r) : "l"(p));
    return r;
}
__device__ __forceinline__ void cp16(uint32_t s, const void* g) {
    asm volatile("cp.async.cg.shared.global [%0], [%1], 16;" :: "r"(s), "l"(g));
}
#define CP_COMMIT() asm volatile("cp.async.commit_group;" ::: "memory")
#define CP_WAIT(n)  asm volatile("cp.async.wait_group %0;" :: "n"(n) : "memory")

__device__ __forceinline__ void ldsm4(uint32_t* r, uint32_t a) {
    asm volatile("ldmatrix.sync.aligned.m8n8.x4.shared.b16 {%0,%1,%2,%3}, [%4];"
                 : "=r"(r[0]), "=r"(r[1]), "=r"(r[2]), "=r"(r[3]) : "r"(a));
}
__device__ __forceinline__ void mma16816(float* c, const uint32_t* a, const uint32_t* b) {
    asm volatile(
        "mma.sync.aligned.m16n8k16.row.col.f32.f16.f16.f32 "
        "{%0,%1,%2,%3}, {%4,%5,%6,%7}, {%8,%9}, {%0,%1,%2,%3};"
        : "+f"(c[0]), "+f"(c[1]), "+f"(c[2]), "+f"(c[3])
        : "r"(a[0]), "r"(a[1]), "r"(a[2]), "r"(a[3]), "r"(b[0]), "r"(b[1]));
}

// 128B-row XOR swizzle: conflict-free for ldmatrix and coalesced stores
__device__ __forceinline__ uint32_t swz128(int row, int chunk) {
    return (uint32_t)(row * 128 + ((chunk ^ (row & 7)) * 16));
}

__device__ __forceinline__ void splitf(float v, __half& h, __half& l) {
    h = __float2half_rn(v);
    l = __float2half_rn(v - __half2float(h));
}

// ---- small kernels ----
__global__ void zero_counts_kernel() {
    if (threadIdx.x < NEXP) g_counts[threadIdx.x] = 0;
}

__global__ __launch_bounds__(256) void conv_x_kernel(const float* __restrict__ x) {
    size_t i = ((size_t)blockIdx.x * 256 + threadIdx.x) * 4;
    float4 v = *(const float4*)(x + i);
    __half hb[4], lb[4];
    splitf(v.x, hb[0], lb[0]); splitf(v.y, hb[1], lb[1]);
    splitf(v.z, hb[2], lb[2]); splitf(v.w, hb[3], lb[3]);
    *(uint2*)(g_xhi + i) = *(uint2*)hb;
    *(uint2*)(g_xlo + i) = *(uint2*)lb;
}

// src [K,N] fp32 (batched over z) -> dst [N,K] fp16 hi (+lo if dlo != null)
__global__ __launch_bounds__(256)
void transpose_conv(const float* __restrict__ src, __half* __restrict__ dhi,
                    __half* __restrict__ dlo, int K, int N)
{
    __shared__ float t[32][33];
    const size_t zoff = (size_t)blockIdx.z * K * N;
    const int n0 = blockIdx.x * 32, k0 = blockIdx.y * 32;
    const int tx = threadIdx.x, ty = threadIdx.y;
    #pragma unroll
    for (int i = 0; i < 4; i++) {
        t[ty + i*8][tx] = src[zoff + (size_t)(k0 + ty + i*8) * N + n0 + tx];
    }
    __syncthreads();
    #pragma unroll
    for (int i = 0; i < 4; i++) {
        const int n = n0 + ty + i*8, k = k0 + tx;
        __half h, l;
        splitf(t[tx][ty + i*8], h, l);
        dhi[zoff + (size_t)n * K + k] = h;
        if (dlo) { dlo[zoff + (size_t)n * K + k] = l; }
    }
}

// ---- gating ----
__global__ __launch_bounds__(128)
void gating_kernel(const float* __restrict__ gate_W, const float* __restrict__ coef_W,
                   const float* __restrict__ coef_b)
{
    const int n = blockIdx.x;
    const int t = threadIdx.x;
    float acc[10];
    #pragma unroll
    for (int j = 0; j < 10; j++) { acc[j] = 0.0f; }

    const __half* hh = g_hhi + (size_t)n * HID;
    const __half* hl = g_hlo + (size_t)n * HID;
    for (int k = t; k < HID; k += 128) {
        const float hv = __half2float(hh[k]) + __half2float(hl[k]);
        #pragma unroll
        for (int j = 0; j < 8; j++) { acc[j] += hv * gate_W[k * 8 + j]; }
        acc[8] += hv * coef_W[k * 2 + 0];
        acc[9] += hv * coef_W[k * 2 + 1];
    }
    #pragma unroll
    for (int j = 0; j < 10; j++) {
        #pragma unroll
        for (int o = 16; o > 0; o >>= 1) {
            acc[j] += __shfl_down_sync(0xffffffffu, acc[j], o);
        }
    }

    __shared__ float red[4][10];
    const int warp = t >> 5, lane = t & 31;
    if (lane == 0) {
        #pragma unroll
        for (int j = 0; j < 10; j++) { red[warp][j] = acc[j]; }
    }
    __syncthreads();

    if (t == 0) {
        float v[10];
        #pragma unroll
        for (int j = 0; j < 10; j++) {
            v[j] = red[0][j] + red[1][j] + red[2][j] + red[3][j];
        }
        float lmax = v[0]; int idx = 0;
        #pragma unroll
        for (int j = 1; j < 8; j++) {
            if (v[j] > lmax) { lmax = v[j]; idx = j; }
        }
        float s = 0.0f;
        #pragma unroll
        for (int j = 0; j < 8; j++) { s += expf(v[j] - lmax); }
        const float gate = 1.0f / s;
        const float c0 = v[8] + coef_b[0];
        const float c1 = v[9] + coef_b[1];
        const float cm = fmaxf(c0, c1);
        const float e0 = expf(c0 - cm), e1 = expf(c1 - cm);
        const float inv = 1.0f / (e0 + e1);
        g_s0[n] = gate * e0 * inv;
        g_s1[n] = e1 * inv;
        const int pos = atomicAdd(&g_counts[idx], 1);
        g_perm[idx * N_TOK + pos] = n;
    }
}

// ===========================================================================
// ENC kernel: 128x128, 3-pass split-fp16 (unchanged from round 9, NPASS=3)
// ===========================================================================
__global__ __launch_bounds__(256, 1)
void hmma_gemm_enc(const __half* __restrict__ Ahi, const __half* __restrict__ Alo,
                   const __half* __restrict__ Bhi, const __half* __restrict__ Blo,
                   const float* __restrict__ bias, int K, int Nn,
                   __half* __restrict__ Chi, __half* __restrict__ Clo)
{
    extern __shared__ __align__(1024) char smem[];
    const uint32_t sb = smem_u32(smem);
    const int tid = threadIdx.x;
    const int lane = tid & 31, wid = tid >> 5;
    const int wm = wid >> 2, wn = wid & 3;           // 2 x 4 warp grid
    const int mrow0 = blockIdx.y * 128;
    const int ncol0 = blockIdx.x * 128;
    const int nt = K / 64;

    int lrow[4], lch[4];
    uint32_t lsw[4];
    #pragma unroll
    for (int i = 0; i < 4; i++) {
        const int slot = tid + 256 * i;
        lrow[i] = slot >> 3;
        lch[i]  = slot & 7;
        lsw[i]  = swz128(lrow[i], lch[i]);
    }

    #define LOADE(s, kt) do {                                                    \
        const uint32_t st_ = sb + (uint32_t)(s) * STG_BYTES;                      \
        _Pragma("unroll")                                                         \
        for (int i_ = 0; i_ < 4; i_++) {                                          \
            const size_t go_ = (size_t)(kt) * 64 + lch[i_] * 8;                   \
            cp16(st_ + OFF_AH + lsw[i_], Ahi + (size_t)(mrow0 + lrow[i_]) * K + go_); \
            cp16(st_ + OFF_AL + lsw[i_], Alo + (size_t)(mrow0 + lrow[i_]) * K + go_); \
            cp16(st_ + OFF_BH + lsw[i_], Bhi + (size_t)(ncol0 + lrow[i_]) * K + go_); \
            cp16(st_ + OFF_BL + lsw[i_], Blo + (size_t)(ncol0 + lrow[i_]) * K + go_); \
        }                                                                         \
        CP_COMMIT();                                                              \
    } while (0)

    LOADE(0, 0);
    LOADE(1, 1);

    float acc[4][4][4];
    #pragma unroll
    for (int i = 0; i < 4; i++) {
        #pragma unroll
        for (int j = 0; j < 4; j++) {
            #pragma unroll
            for (int q = 0; q < 4; q++) { acc[i][j][q] = 0.0f; }
        }
    }

    const int arow = (lane & 7) | (((lane >> 3) & 1) << 3);
    const int ach  = lane >> 4;
    const int brow = (lane & 7) | (((lane >> 4) & 1) << 3);
    const int bch  = (lane >> 3) & 1;

    uint32_t ah[4][4], al[4][4], bh[2][4], bl[2][4];

    for (int kt = 0; kt < nt; kt++) {
        if (kt + 1 < nt) { CP_WAIT(1); } else { CP_WAIT(0); }
        __syncthreads();
        if (kt + 2 < nt) { LOADE((kt + 2) % 3, kt + 2); }

        const uint32_t st = sb + (uint32_t)(kt % 3) * STG_BYTES;
        #pragma unroll
        for (int s16 = 0; s16 < 4; s16++) {
            #pragma unroll
            for (int i = 0; i < 4; i++) {
                const uint32_t a = swz128(wm * 64 + i * 16 + arow, s16 * 2 + ach);
                ldsm4(ah[i], st + OFF_AH + a);
                ldsm4(al[i], st + OFF_AL + a);
            }
            #pragma unroll
            for (int j = 0; j < 2; j++) {
                const uint32_t b = swz128(wn * 32 + j * 16 + brow, s16 * 2 + bch);
                ldsm4(bh[j], st + OFF_BH + b);
                ldsm4(bl[j], st + OFF_BL + b);
            }
            #pragma unroll
            for (int i = 0; i < 4; i++) {
                #pragma unroll
                for (int j = 0; j < 4; j++) {
                    mma16816(acc[i][j], ah[i], &bh[j >> 1][(j & 1) * 2]);
                    mma16816(acc[i][j], ah[i], &bl[j >> 1][(j & 1) * 2]);
                    mma16816(acc[i][j], al[i], &bh[j >> 1][(j & 1) * 2]);
                }
            }
        }
    }

    // epilogue: relu + split -> Chi/Clo
    #pragma unroll
    for (int i = 0; i < 4; i++) {
        const int rb = mrow0 + wm * 64 + i * 16 + (lane >> 2);
        #pragma unroll
        for (int h = 0; h < 2; h++) {
            const int row = rb + h * 8;
            #pragma unroll
            for (int j = 0; j < 4; j++) {
                const int col = ncol0 + wn * 32 + j * 8 + (lane & 3) * 2;
                float v0 = fmaxf(acc[i][j][h * 2 + 0] + bias[col], 0.0f);
                float v1 = fmaxf(acc[i][j][h * 2 + 1] + bias[col + 1], 0.0f);
                __half h0, l0, h1, l1;
                splitf(v0, h0, l0); splitf(v1, h1, l1);
                *(__half2*)(Chi + (size_t)row * Nn + col) = __halves2half2(h0, h1);
                *(__half2*)(Clo + (size_t)row * Nn + col) = __halves2half2(l0, l1);
            }
        }
    }
    #undef LOADE
}

// ===========================================================================
// Big-tile 1-pass GEMM: CTA 256x128, BK=64, 8 warps (4x2), warp tile 64x64.
// MODE 1: (acc+bias)*rowscale -> Cf ; MODE 2: acc+bias -> Cf
// ===========================================================================
#define BLDFRAG(st, s16) do {                                                    \
    _Pragma("unroll")                                                             \
    for (int i_ = 0; i_ < 4; i_++) {                                              \
        ldsm4(ah[i_], (st) + BOFF_A + swz128(wm * 64 + i_ * 16 + arow, (s16) * 2 + ach)); \
    }                                                                             \
    _Pragma("unroll")                                                             \
    for (int j_ = 0; j_ < 4; j_++) {                                              \
        ldsm4(bh[j_], (st) + BOFF_B + swz128(wn * 64 + j_ * 16 + brow, (s16) * 2 + bch)); \
    }                                                                             \
} while (0)

#define BDOMMA() do {                                                             \
    _Pragma("unroll")                                                             \
    for (int i_ = 0; i_ < 4; i_++) {                                              \
        _Pragma("unroll")                                                         \
        for (int j_ = 0; j_ < 8; j_++) {                                          \
            mma16816(acc[i_][j_], ah[i_], &bh[j_ >> 1][(j_ & 1) * 2]);            \
        }                                                                         \
    }                                                                             \
} while (0)

template <int MODE>
__global__ __launch_bounds__(256, 1)
void hmma_gemm_big(const __half* __restrict__ A, const __half* __restrict__ B,
                   const float* __restrict__ bias, int K, int Nn,
                   float* __restrict__ Cf, const float* __restrict__ rowscale)
{
    extern __shared__ __align__(1024) char smem[];
    const uint32_t sb = smem_u32(smem);
    const int tid = threadIdx.x;
    const int lane = tid & 31, wid = tid >> 5;
    const int wm = wid >> 1, wn = wid & 1;           // 4 x 2 warp grid
    const int mrow0 = blockIdx.y * 256;
    const int ncol0 = blockIdx.x * 128;
    const int nt = K / 64;

    #define BLOADT(s, kt) do {                                                   \
        const uint32_t st_ = sb + (uint32_t)(s) * BSTG;                           \
        _Pragma("unroll")                                                         \
        for (int i_ = 0; i_ < 8; i_++) {                                          \
            const int slot_ = tid + 256 * i_;                                     \
            const int row_ = slot_ >> 3, ch_ = slot_ & 7;                         \
            cp16(st_ + BOFF_A + swz128(row_, ch_),                                \
                 A + (size_t)(mrow0 + row_) * K + (size_t)(kt) * 64 + ch_ * 8);   \
        }                                                                         \
        _Pragma("unroll")                                                         \
        for (int i_ = 0; i_ < 4; i_++) {                                          \
            const int slot_ = tid + 256 * i_;                                     \
            const int row_ = slot_ >> 3, ch_ = slot_ & 7;                         \
            cp16(st_ + BOFF_B + swz128(row_, ch_),                                \
                 B + (size_t)(ncol0 + row_) * K + (size_t)(kt) * 64 + ch_ * 8);   \
        }                                                                         \
        CP_COMMIT();                                                              \
    } while (0)

    BLOADT(0, 0);
    BLOADT(1, 1);

    float acc[4][8][4];
    #pragma unroll
    for (int i = 0; i < 4; i++) {
        #pragma unroll
        for (int j = 0; j < 8; j++) {
            #pragma unroll
            for (int q = 0; q < 4; q++) { acc[i][j][q] = 0.0f; }
        }
    }

    const int arow = (lane & 7) | (((lane >> 3) & 1) << 3);
    const int ach  = lane >> 4;
    const int brow = (lane & 7) | (((lane >> 4) & 1) << 3);
    const int bch  = (lane >> 3) & 1;

    uint32_t ah[4][4], bh[4][4];

    for (int kt = 0; kt < nt; kt++) {
        if (kt + 1 < nt) { CP_WAIT(1); } else { CP_WAIT(0); }
        __syncthreads();
        if (kt + 2 < nt) { BLOADT((kt + 2) % 3, kt + 2); }

        const uint32_t st = sb + (uint32_t)(kt % 3) * BSTG;
        #pragma unroll
        for (int s16 = 0; s16 < 4; s16++) {
            BLDFRAG(st, s16);
            BDOMMA();
        }
    }

    // epilogue
    #pragma unroll
    for (int i = 0; i < 4; i++) {
        const int rb = mrow0 + wm * 64 + i * 16 + (lane >> 2);
        #pragma unroll
        for (int h = 0; h < 2; h++) {
            const int row = rb + h * 8;
            const float rs = (MODE == 1) ? rowscale[row] : 0.0f;
            #pragma unroll
            for (int j = 0; j < 8; j++) {
                const int col = ncol0 + wn * 64 + j * 8 + (lane & 3) * 2;
                float v0 = acc[i][j][h * 2 + 0] + bias[col];
                float v1 = acc[i][j][h * 2 + 1] + bias[col + 1];
                if (MODE == 1) {
                    *(float2*)(Cf + (size_t)row * Nn + col) = make_float2(v0 * rs, v1 * rs);
                } else {
                    *(float2*)(Cf + (size_t)row * Nn + col) = make_float2(v0, v1);
                }
            }
        }
    }
    #undef BLOADT
}

// ===========================================================================
// Grouped expert GEMM (1-pass, big tile 256x128): A rows via g_perm;
// epilogue: uhi = fp16(g_u[tok] + (acc + b_e) * s0[tok]).
// ===========================================================================
__global__ __launch_bounds__(256, 1)
void hmma_gemm_grouped_big(const float* __restrict__ bexp)
{
    extern __shared__ __align__(1024) char smem[];
    const int e = blockIdx.z;
    const int cnt = g_counts[e];
    const int rowBase = blockIdx.y * 256;
    if (rowBase >= cnt) return;

    const uint32_t sb = smem_u32(smem);
    const int tid = threadIdx.x;
    const int lane = tid & 31, wid = tid >> 5;
    const int wm = wid >> 1, wn = wid & 1;
    const int ncol0 = blockIdx.x * 128;
    const int nt = HID / 64;
    int* rmap = (int*)(smem + BSM_RMAP);

    {
        int i = rowBase + tid;
        if (i > cnt - 1) i = cnt - 1;
        rmap[tid] = g_perm[e * N_TOK + i];
    }
    __syncthreads();

    const __half* B = g_Whi + W_EXP_OFF + (size_t)e * HID * HID;

    size_t ga[8];
    #pragma unroll
    for (int i = 0; i < 8; i++) {
        ga[i] = (size_t)rmap[(tid + 256 * i) >> 3] * HID;
    }

    #define GLOADT(s, kt) do {                                                   \
        const uint32_t st_ = sb + (uint32_t)(s) * BSTG;                           \
        _Pragma("unroll")                                                         \
        for (int i_ = 0; i_ < 8; i_++) {                                          \
            const int slot_ = tid + 256 * i_;                                     \
            const int row_ = slot_ >> 3, ch_ = slot_ & 7;                         \
            cp16(st_ + BOFF_A + swz128(row_, ch_),                                \
                 g_hhi + ga[i_] + (size_t)(kt) * 64 + ch_ * 8);                   \
        }                                                                         \
        _Pragma("unroll")                                                         \
        for (int i_ = 0; i_ < 4; i_++) {                                          \
            const int slot_ = tid + 256 * i_;                                     \
            const int row_ = slot_ >> 3, ch_ = slot_ & 7;                         \
            cp16(st_ + BOFF_B + swz128(row_, ch_),                                \
                 B + (size_t)(ncol0 + row_) * HID + (size_t)(kt) * 64 + ch_ * 8); \
        }                                                                         \
        CP_COMMIT();                                                              \
    } while (0)

    GLOADT(0, 0);
    GLOADT(1, 1);

    float acc[4][8][4];
    #pragma unroll
    for (int i = 0; i < 4; i++) {
        #pragma unroll
        for (int j = 0; j < 8; j++) {
            #pragma unroll
            for (int q = 0; q < 4; q++) { acc[i][j][q] = 0.0f; }
        }
    }

    const int arow = (lane & 7) | (((lane >> 3) & 1) << 3);
    const int ach  = lane >> 4;
    const int brow = (lane & 7) | (((lane >> 4) & 1) << 3);
    const int bch  = (lane >> 3) & 1;

    uint32_t ah[4][4], bh[4][4];

    for (int kt = 0; kt < nt; kt++) {
        if (kt + 1 < nt) { CP_WAIT(1); } else { CP_WAIT(0); }
        __syncthreads();
        if (kt + 2 < nt) { GLOADT((kt + 2) % 3, kt + 2); }

        const uint32_t st = sb + (uint32_t)(kt % 3) * BSTG;
        #pragma unroll
        for (int s16 = 0; s16 < 4; s16++) {
            BLDFRAG(st, s16);
            BDOMMA();
        }
    }

    #pragma unroll
    for (int i = 0; i < 4; i++) {
        const int lb = wm * 64 + i * 16 + (lane >> 2);
        #pragma unroll
        for (int h = 0; h < 2; h++) {
            const int li = lb + h * 8;
            if (rowBase + li >= cnt) continue;
            const int tok = rmap[li];
            const float s0 = g_s0[tok];
            #pragma unroll
            for (int j = 0; j < 8; j++) {
                const int col = ncol0 + wn * 64 + j * 8 + (lane & 3) * 2;
                float2 u2 = *(const float2*)(g_u + (size_t)tok * HID + col);
                float v0 = u2.x + (acc[i][j][h * 2 + 0] + bexp[e * HID + col]) * s0;
                float v1 = u2.y + (acc[i][j][h * 2 + 1] + bexp[e * HID + col + 1]) * s0;
                *(__half2*)(g_uhi + (size_t)tok * HID + col) =
                    __halves2half2(__float2half_rn(v0), __float2half_rn(v1));
            }
        }
    }
    #undef GLOADT
}

// ---------------------------------------------------------------------------
extern "C" void kernel_launch(void* const* d_in, const int* in_sizes, int n_in,
                              void* d_out, int out_size)
{
    const float* x        = (const float*)d_in[0];
    const float* enc_W    = (const float*)d_in[1];
    const float* enc_b    = (const float*)d_in[2];
    const float* gate_W   = (const float*)d_in[3];
    const float* expert_W = (const float*)d_in[4];
    const float* expert_b = (const float*)d_in[5];
    const float* res_W    = (const float*)d_in[6];
    const float* res_b    = (const float*)d_in[7];
    const float* coef_W   = (const float*)d_in[8];
    const float* coef_b   = (const float*)d_in[9];
    const float* dec_W    = (const float*)d_in[10];
    const float* dec_b    = (const float*)d_in[11];
    float* out = (float*)d_out;

    __half *xhi, *xlo, *hhi, *hlo, *uhi, *whi, *wlo;
    float *up, *s1p;
    cudaGetSymbolAddress((void**)&xhi, g_xhi);
    cudaGetSymbolAddress((void**)&xlo, g_xlo);
    cudaGetSymbolAddress((void**)&hhi, g_hhi);
    cudaGetSymbolAddress((void**)&hlo, g_hlo);
    cudaGetSymbolAddress((void**)&uhi, g_uhi);
    cudaGetSymbolAddress((void**)&whi, g_Whi);
    cudaGetSymbolAddress((void**)&wlo, g_Wlo);
    cudaGetSymbolAddress((void**)&up,  g_u);
    cudaGetSymbolAddress((void**)&s1p, g_s1);

    cudaFuncSetAttribute((const void*)hmma_gemm_enc,         cudaFuncAttributeMaxDynamicSharedMemorySize, SMEM_TOT);
    cudaFuncSetAttribute((const void*)hmma_gemm_big<1>,      cudaFuncAttributeMaxDynamicSharedMemorySize, BSMEM_TOT);
    cudaFuncSetAttribute((const void*)hmma_gemm_big<2>,      cudaFuncAttributeMaxDynamicSharedMemorySize, BSMEM_TOT);
    cudaFuncSetAttribute((const void*)hmma_gemm_grouped_big, cudaFuncAttributeMaxDynamicSharedMemorySize, BSMEM_TOT);

    // ---- precompute: splits + weight transposes ([K,N] -> [N,K]) ----
    conv_x_kernel<<<(N_TOK * IN_DIM) / 1024, 256>>>(x);
    transpose_conv<<<dim3(HID/32, IN_DIM/32, 1),  dim3(32, 8)>>>(enc_W,    whi + W_ENC_OFF, wlo + W_ENC_OFF, IN_DIM, HID);
    transpose_conv<<<dim3(HID/32, HID/32, 1),     dim3(32, 8)>>>(res_W,    whi + W_RES_OFF, nullptr, HID, HID);
    transpose_conv<<<dim3(HID/32, HID/32, NEXP),  dim3(32, 8)>>>(expert_W, whi + W_EXP_OFF, nullptr, HID, HID);
    transpose_conv<<<dim3(IN_DIM/32, HID/32, 1),  dim3(32, 8)>>>(dec_W,    whi + W_DEC_OFF, nullptr, HID, IN_DIM);
    zero_counts_kernel<<<1, 32>>>();

    // ---- h = relu(x @ enc_W + enc_b) : 3-pass 128x128 (protects argmax) ----
    hmma_gemm_enc<<<dim3(HID/128, N_TOK/128), 256, SMEM_TOT>>>(
        xhi, xlo, whi + W_ENC_OFF, wlo + W_ENC_OFF,
        enc_b, IN_DIM, HID, hhi, hlo);

    // ---- gating ----
    gating_kernel<<<N_TOK, 128>>>(gate_W, coef_W, coef_b);

    // ---- u = (h @ res_W + res_b) * s1 : 1-pass 256x128 ----
    hmma_gemm_big<1><<<dim3(HID/128, N_TOK/256), 256, BSMEM_TOT>>>(
        hhi, whi + W_RES_OFF, res_b, HID, HID, up, s1p);

    // ---- u += (h @ W_e + b_e) * s0 : 1-pass 256x128 grouped ----
    hmma_gemm_grouped_big<<<dim3(HID/128, N_TOK/256, NEXP), 256, BSMEM_TOT>>>(expert_b);

    // ---- out = u @ dec_W + dec_b : 1-pass 256x128 ----
    hmma_gemm_big<2><<<dim3(IN_DIM/128, N_TOK/256), 256, BSMEM_TOT>>>(
        uhi, whi + W_DEC_OFF, dec_b, HID, IN_DIM, out, nullptr);
}

// round 11
// speedup vs baseline: 5.4736x; 1.0747x over previous
#include <cuda_runtime.h>
#include <cuda_fp16.h>
#include <cuda.h>
#include <cstdint>
#include <math.h>

#define N_TOK  16384
#define IN_DIM 1024
#define HID    2048
#define NEXP   8

// ---- device scratch (globals: allocation-free) ----
__device__ __align__(128) __half g_xhi[(size_t)N_TOK * IN_DIM];
__device__ __align__(128) __half g_xlo[(size_t)N_TOK * IN_DIM];
__device__ __align__(128) __half g_hhi[(size_t)N_TOK * HID];
__device__ __align__(128) __half g_hlo[(size_t)N_TOK * HID];
__device__ __align__(128) __half g_uh[(size_t)N_TOK * HID];

#define W_ENC_OFF 0
#define W_RES_OFF (2048*1024)
#define W_EXP_OFF (W_RES_OFF + 2048*2048)
#define W_DEC_OFF (W_EXP_OFF + 8*2048*2048)
#define W_TOTAL   (W_DEC_OFF + 1024*2048)
__device__ __align__(128) __half g_Whi[(size_t)W_TOTAL];
__device__ __align__(128) __half g_Wlo[(size_t)IN_DIM * HID];  // enc lo only

__device__ int   g_perm[NEXP * N_TOK];
__device__ int   g_counts[NEXP];
__device__ float g_s0[N_TOK];
__device__ float g_s1[N_TOK];

// ---- enc kernel SMEM: 3 stages x (Ah,Al,Bh,Bl each 16KB) = 192KB ----
#define STG_BYTES 65536
#define OFF_AH 0
#define OFF_AL 16384
#define OFF_BH 32768
#define OFF_BL 49152
#define SMEM_TOT (3 * STG_BYTES + 512)

// ---- big-tile (256x128, 1-pass) SMEM: 3 stages x (A 32KB + B 16KB) ----
#define BSTG 49152
#define BOFF_A 0
#define BOFF_B 32768
#define BSM_RMAP (3 * BSTG)
#define BSMEM_TOT (3 * BSTG + 1152)

// ---- PTX helpers ----
__device__ __forceinline__ uint32_t smem_u32(const void* p) {
    uint32_t r;
    asm("{ .reg .u64 t; cvta.to.shared.u64 t, %1; cvt.u32.u64 %0, t; }" : "=r"(r) : "l"(p));
    return r;
}
__device__ __forceinline__ void cp16(uint32_t s, const void* g) {
    asm volatile("cp.async.cg.shared.global [%0], [%1], 16;" :: "r"(s), "l"(g));
}
#define CP_COMMIT() asm volatile("cp.async.commit_group;" ::: "memory")
#define CP_WAIT(n)  asm volatile("cp.async.wait_group %0;" :: "n"(n) : "memory")

__device__ __forceinline__ void ldsm4(uint32_t* r, uint32_t a) {
    asm volatile("ldmatrix.sync.aligned.m8n8.x4.shared.b16 {%0,%1,%2,%3}, [%4];"
                 : "=r"(r[0]), "=r"(r[1]), "=r"(r[2]), "=r"(r[3]) : "r"(a));
}
__device__ __forceinline__ void mma16816(float* c, const uint32_t* a, const uint32_t* b) {
    asm volatile(
        "mma.sync.aligned.m16n8k16.row.col.f32.f16.f16.f32 "
        "{%0,%1,%2,%3}, {%4,%5,%6,%7}, {%8,%9}, {%0,%1,%2,%3};"
        : "+f"(c[0]), "+f"(c[1]), "+f"(c[2]), "+f"(c[3])
        : "r"(a[0]), "r"(a[1]), "r"(a[2]), "r"(a[3]), "r"(b[0]), "r"(b[1]));
}

// 128B-row XOR swizzle: conflict-free for ldmatrix and coalesced stores
__device__ __forceinline__ uint32_t swz128(int row, int chunk) {
    return (uint32_t)(row * 128 + ((chunk ^ (row & 7)) * 16));
}

__device__ __forceinline__ void splitf(float v, __half& h, __half& l) {
    h = __float2half_rn(v);
    l = __float2half_rn(v - __half2float(h));
}

// ---- small kernels ----
__global__ void zero_counts_kernel() {
    if (threadIdx.x < NEXP) g_counts[threadIdx.x] = 0;
}

__global__ __launch_bounds__(256) void conv_x_kernel(const float* __restrict__ x) {
    size_t i = ((size_t)blockIdx.x * 256 + threadIdx.x) * 4;
    float4 v = *(const float4*)(x + i);
    __half hb[4], lb[4];
    splitf(v.x, hb[0], lb[0]); splitf(v.y, hb[1], lb[1]);
    splitf(v.z, hb[2], lb[2]); splitf(v.w, hb[3], lb[3]);
    *(uint2*)(g_xhi + i) = *(uint2*)hb;
    *(uint2*)(g_xlo + i) = *(uint2*)lb;
}

// src [K,N] fp32 (batched over z) -> dst [N,K] fp16 hi (+lo), vectorized stores
__global__ __launch_bounds__(256)
void transpose_conv(const float* __restrict__ src, __half* __restrict__ dhi,
                    __half* __restrict__ dlo, int K, int N)
{
    __shared__ float t[32][33];
    const size_t zoff = (size_t)blockIdx.z * K * N;
    const int n0 = blockIdx.x * 32, k0 = blockIdx.y * 32;
    const int tx = threadIdx.x, ty = threadIdx.y;
    #pragma unroll
    for (int i = 0; i < 4; i++) {
        t[ty + i*8][tx] = src[zoff + (size_t)(k0 + ty + i*8) * N + n0 + tx];
    }
    __syncthreads();
    // vectorized write: each thread emits 4 consecutive k as one uint2 (8B)
    const int tid = ty * 32 + tx;
    const int nl = tid >> 3;              // 0..31
    const int kl = (tid & 7) * 4;         // 0,4,..28
    __half h4[4], l4[4];
    #pragma unroll
    for (int q = 0; q < 4; q++) {
        splitf(t[kl + q][nl], h4[q], l4[q]);
    }
    const size_t di = zoff + (size_t)(n0 + nl) * K + k0 + kl;
    *(uint2*)(dhi + di) = *(uint2*)h4;
    if (dlo) { *(uint2*)(dlo + di) = *(uint2*)l4; }
}

// ---- gating ----
__global__ __launch_bounds__(128)
void gating_kernel(const float* __restrict__ gate_W, const float* __restrict__ coef_W,
                   const float* __restrict__ coef_b)
{
    const int n = blockIdx.x;
    const int t = threadIdx.x;
    float acc[10];
    #pragma unroll
    for (int j = 0; j < 10; j++) { acc[j] = 0.0f; }

    const __half* hh = g_hhi + (size_t)n * HID;
    const __half* hl = g_hlo + (size_t)n * HID;
    for (int k = t; k < HID; k += 128) {
        const float hv = __half2float(hh[k]) + __half2float(hl[k]);
        #pragma unroll
        for (int j = 0; j < 8; j++) { acc[j] += hv * gate_W[k * 8 + j]; }
        acc[8] += hv * coef_W[k * 2 + 0];
        acc[9] += hv * coef_W[k * 2 + 1];
    }
    #pragma unroll
    for (int j = 0; j < 10; j++) {
        #pragma unroll
        for (int o = 16; o > 0; o >>= 1) {
            acc[j] += __shfl_down_sync(0xffffffffu, acc[j], o);
        }
    }

    __shared__ float red[4][10];
    const int warp = t >> 5, lane = t & 31;
    if (lane == 0) {
        #pragma unroll
        for (int j = 0; j < 10; j++) { red[warp][j] = acc[j]; }
    }
    __syncthreads();

    if (t == 0) {
        float v[10];
        #pragma unroll
        for (int j = 0; j < 10; j++) {
            v[j] = red[0][j] + red[1][j] + red[2][j] + red[3][j];
        }
        float lmax = v[0]; int idx = 0;
        #pragma unroll
        for (int j = 1; j < 8; j++) {
            if (v[j] > lmax) { lmax = v[j]; idx = j; }
        }
        float s = 0.0f;
        #pragma unroll
        for (int j = 0; j < 8; j++) { s += expf(v[j] - lmax); }
        const float gate = 1.0f / s;
        const float c0 = v[8] + coef_b[0];
        const float c1 = v[9] + coef_b[1];
        const float cm = fmaxf(c0, c1);
        const float e0 = expf(c0 - cm), e1 = expf(c1 - cm);
        const float inv = 1.0f / (e0 + e1);
        g_s0[n] = gate * e0 * inv;
        g_s1[n] = e1 * inv;
        const int pos = atomicAdd(&g_counts[idx], 1);
        g_perm[idx * N_TOK + pos] = n;
    }
}

// ===========================================================================
// ENC kernel: 128x128, 3-pass split-fp16 (protects gating argmax)
// ===========================================================================
__global__ __launch_bounds__(256, 1)
void hmma_gemm_enc(const __half* __restrict__ Ahi, const __half* __restrict__ Alo,
                   const __half* __restrict__ Bhi, const __half* __restrict__ Blo,
                   const float* __restrict__ bias, int K, int Nn,
                   __half* __restrict__ Chi, __half* __restrict__ Clo)
{
    extern __shared__ __align__(1024) char smem[];
    const uint32_t sb = smem_u32(smem);
    const int tid = threadIdx.x;
    const int lane = tid & 31, wid = tid >> 5;
    const int wm = wid >> 2, wn = wid & 3;           // 2 x 4 warp grid
    const int mrow0 = blockIdx.y * 128;
    const int ncol0 = blockIdx.x * 128;
    const int nt = K / 64;

    int lrow[4], lch[4];
    uint32_t lsw[4];
    #pragma unroll
    for (int i = 0; i < 4; i++) {
        const int slot = tid + 256 * i;
        lrow[i] = slot >> 3;
        lch[i]  = slot & 7;
        lsw[i]  = swz128(lrow[i], lch[i]);
    }

    #define LOADE(s, kt) do {                                                    \
        const uint32_t st_ = sb + (uint32_t)(s) * STG_BYTES;                      \
        _Pragma("unroll")                                                         \
        for (int i_ = 0; i_ < 4; i_++) {                                          \
            const size_t go_ = (size_t)(kt) * 64 + lch[i_] * 8;                   \
            cp16(st_ + OFF_AH + lsw[i_], Ahi + (size_t)(mrow0 + lrow[i_]) * K + go_); \
            cp16(st_ + OFF_AL + lsw[i_], Alo + (size_t)(mrow0 + lrow[i_]) * K + go_); \
            cp16(st_ + OFF_BH + lsw[i_], Bhi + (size_t)(ncol0 + lrow[i_]) * K + go_); \
            cp16(st_ + OFF_BL + lsw[i_], Blo + (size_t)(ncol0 + lrow[i_]) * K + go_); \
        }                                                                         \
        CP_COMMIT();                                                              \
    } while (0)

    LOADE(0, 0);
    LOADE(1, 1);

    float acc[4][4][4];
    #pragma unroll
    for (int i = 0; i < 4; i++) {
        #pragma unroll
        for (int j = 0; j < 4; j++) {
            #pragma unroll
            for (int q = 0; q < 4; q++) { acc[i][j][q] = 0.0f; }
        }
    }

    const int arow = (lane & 7) | (((lane >> 3) & 1) << 3);
    const int ach  = lane >> 4;
    const int brow = (lane & 7) | (((lane >> 4) & 1) << 3);
    const int bch  = (lane >> 3) & 1;

    uint32_t ah[4][4], al[4][4], bh[2][4], bl[2][4];

    for (int kt = 0; kt < nt; kt++) {
        if (kt + 1 < nt) { CP_WAIT(1); } else { CP_WAIT(0); }
        __syncthreads();
        if (kt + 2 < nt) { LOADE((kt + 2) % 3, kt + 2); }

        const uint32_t st = sb + (uint32_t)(kt % 3) * STG_BYTES;
        #pragma unroll
        for (int s16 = 0; s16 < 4; s16++) {
            #pragma unroll
            for (int i = 0; i < 4; i++) {
                const uint32_t a = swz128(wm * 64 + i * 16 + arow, s16 * 2 + ach);
                ldsm4(ah[i], st + OFF_AH + a);
                ldsm4(al[i], st + OFF_AL + a);
            }
            #pragma unroll
            for (int j = 0; j < 2; j++) {
                const uint32_t b = swz128(wn * 32 + j * 16 + brow, s16 * 2 + bch);
                ldsm4(bh[j], st + OFF_BH + b);
                ldsm4(bl[j], st + OFF_BL + b);
            }
            #pragma unroll
            for (int i = 0; i < 4; i++) {
                #pragma unroll
                for (int j = 0; j < 4; j++) {
                    mma16816(acc[i][j], ah[i], &bh[j >> 1][(j & 1) * 2]);
                    mma16816(acc[i][j], ah[i], &bl[j >> 1][(j & 1) * 2]);
                    mma16816(acc[i][j], al[i], &bh[j >> 1][(j & 1) * 2]);
                }
            }
        }
    }

    // epilogue: relu + split -> Chi/Clo
    #pragma unroll
    for (int i = 0; i < 4; i++) {
        const int rb = mrow0 + wm * 64 + i * 16 + (lane >> 2);
        #pragma unroll
        for (int h = 0; h < 2; h++) {
            const int row = rb + h * 8;
            #pragma unroll
            for (int j = 0; j < 4; j++) {
                const int col = ncol0 + wn * 32 + j * 8 + (lane & 3) * 2;
                float v0 = fmaxf(acc[i][j][h * 2 + 0] + bias[col], 0.0f);
                float v1 = fmaxf(acc[i][j][h * 2 + 1] + bias[col + 1], 0.0f);
                __half h0, l0, h1, l1;
                splitf(v0, h0, l0); splitf(v1, h1, l1);
                *(__half2*)(Chi + (size_t)row * Nn + col) = __halves2half2(h0, h1);
                *(__half2*)(Clo + (size_t)row * Nn + col) = __halves2half2(l0, l1);
            }
        }
    }
    #undef LOADE
}

// ===========================================================================
// Big-tile 1-pass GEMM: CTA 256x128, BK=64, 8 warps (4x2), warp tile 64x64.
// MODE 1: (acc+bias)*rowscale -> Ch (fp16) ; MODE 2: acc+bias -> Cf (fp32)
// ===========================================================================
#define BLDFRAG(st, s16) do {                                                    \
    _Pragma("unroll")                                                             \
    for (int i_ = 0; i_ < 4; i_++) {                                              \
        ldsm4(ah[i_], (st) + BOFF_A + swz128(wm * 64 + i_ * 16 + arow, (s16) * 2 + ach)); \
    }                                                                             \
    _Pragma("unroll")                                                             \
    for (int j_ = 0; j_ < 4; j_++) {                                              \
        ldsm4(bh[j_], (st) + BOFF_B + swz128(wn * 64 + j_ * 16 + brow, (s16) * 2 + bch)); \
    }                                                                             \
} while (0)

#define BDOMMA() do {                                                             \
    _Pragma("unroll")                                                             \
    for (int i_ = 0; i_ < 4; i_++) {                                              \
        _Pragma("unroll")                                                         \
        for (int j_ = 0; j_ < 8; j_++) {                                          \
            mma16816(acc[i_][j_], ah[i_], &bh[j_ >> 1][(j_ & 1) * 2]);            \
        }                                                                         \
    }                                                                             \
} while (0)

template <int MODE>
__global__ __launch_bounds__(256, 1)
void hmma_gemm_big(const __half* __restrict__ A, const __half* __restrict__ B,
                   const float* __restrict__ bias, int K, int Nn,
                   __half* __restrict__ Ch, float* __restrict__ Cf,
                   const float* __restrict__ rowscale)
{
    extern __shared__ __align__(1024) char smem[];
    const uint32_t sb = smem_u32(smem);
    const int tid = threadIdx.x;
    const int lane = tid & 31, wid = tid >> 5;
    const int wm = wid >> 1, wn = wid & 1;           // 4 x 2 warp grid
    const int mrow0 = blockIdx.y * 256;
    const int ncol0 = blockIdx.x * 128;
    const int nt = K / 64;

    #define BLOADT(s, kt) do {                                                   \
        const uint32_t st_ = sb + (uint32_t)(s) * BSTG;                           \
        _Pragma("unroll")                                                         \
        for (int i_ = 0; i_ < 8; i_++) {                                          \
            const int slot_ = tid + 256 * i_;                                     \
            const int row_ = slot_ >> 3, ch_ = slot_ & 7;                         \
            cp16(st_ + BOFF_A + swz128(row_, ch_),                                \
                 A + (size_t)(mrow0 + row_) * K + (size_t)(kt) * 64 + ch_ * 8);   \
        }                                                                         \
        _Pragma("unroll")                                                         \
        for (int i_ = 0; i_ < 4; i_++) {                                          \
            const int slot_ = tid + 256 * i_;                                     \
            const int row_ = slot_ >> 3, ch_ = slot_ & 7;                         \
            cp16(st_ + BOFF_B + swz128(row_, ch_),                                \
                 B + (size_t)(ncol0 + row_) * K + (size_t)(kt) * 64 + ch_ * 8);   \
        }                                                                         \
        CP_COMMIT();                                                              \
    } while (0)

    BLOADT(0, 0);
    BLOADT(1, 1);

    float acc[4][8][4];
    #pragma unroll
    for (int i = 0; i < 4; i++) {
        #pragma unroll
        for (int j = 0; j < 8; j++) {
            #pragma unroll
            for (int q = 0; q < 4; q++) { acc[i][j][q] = 0.0f; }
        }
    }

    const int arow = (lane & 7) | (((lane >> 3) & 1) << 3);
    const int ach  = lane >> 4;
    const int brow = (lane & 7) | (((lane >> 4) & 1) << 3);
    const int bch  = (lane >> 3) & 1;

    uint32_t ah[4][4], bh[4][4];

    for (int kt = 0; kt < nt; kt++) {
        if (kt + 1 < nt) { CP_WAIT(1); } else { CP_WAIT(0); }
        __syncthreads();
        if (kt + 2 < nt) { BLOADT((kt + 2) % 3, kt + 2); }

        const uint32_t st = sb + (uint32_t)(kt % 3) * BSTG;
        #pragma unroll
        for (int s16 = 0; s16 < 4; s16++) {
            BLDFRAG(st, s16);
            BDOMMA();
        }
    }

    // epilogue
    #pragma unroll
    for (int i = 0; i < 4; i++) {
        const int rb = mrow0 + wm * 64 + i * 16 + (lane >> 2);
        #pragma unroll
        for (int h = 0; h < 2; h++) {
            const int row = rb + h * 8;
            const float rs = (MODE == 1) ? rowscale[row] : 0.0f;
            #pragma unroll
            for (int j = 0; j < 8; j++) {
                const int col = ncol0 + wn * 64 + j * 8 + (lane & 3) * 2;
                float v0 = acc[i][j][h * 2 + 0] + bias[col];
                float v1 = acc[i][j][h * 2 + 1] + bias[col + 1];
                if (MODE == 1) {
                    *(__half2*)(Ch + (size_t)row * Nn + col) =
                        __halves2half2(__float2half_rn(v0 * rs), __float2half_rn(v1 * rs));
                } else {
                    *(float2*)(Cf + (size_t)row * Nn + col) = make_float2(v0, v1);
                }
            }
        }
    }
    #undef BLOADT
}

// ===========================================================================
// Grouped expert GEMM (1-pass, big tile 256x128): A rows via g_perm;
// epilogue: g_uh[tok] += fp16((acc + b_e) * s0[tok])  (fp16 RMW)
// ===========================================================================
__global__ __launch_bounds__(256, 1)
void hmma_gemm_grouped_big(const float* __restrict__ bexp)
{
    extern __shared__ __align__(1024) char smem[];
    const int e = blockIdx.z;
    const int cnt = g_counts[e];
    const int rowBase = blockIdx.y * 256;
    if (rowBase >= cnt) return;

    const uint32_t sb = smem_u32(smem);
    const int tid = threadIdx.x;
    const int lane = tid & 31, wid = tid >> 5;
    const int wm = wid >> 1, wn = wid & 1;
    const int ncol0 = blockIdx.x * 128;
    const int nt = HID / 64;
    int* rmap = (int*)(smem + BSM_RMAP);

    {
        int i = rowBase + tid;
        if (i > cnt - 1) i = cnt - 1;
        rmap[tid] = g_perm[e * N_TOK + i];
    }
    __syncthreads();

    const __half* B = g_Whi + W_EXP_OFF + (size_t)e * HID * HID;

    size_t ga[8];
    #pragma unroll
    for (int i = 0; i < 8; i++) {
        ga[i] = (size_t)rmap[(tid + 256 * i) >> 3] * HID;
    }

    #define GLOADT(s, kt) do {                                                   \
        const uint32_t st_ = sb + (uint32_t)(s) * BSTG;                           \
        _Pragma("unroll")                                                         \
        for (int i_ = 0; i_ < 8; i_++) {                                          \
            const int slot_ = tid + 256 * i_;                                     \
            const int row_ = slot_ >> 3, ch_ = slot_ & 7;                         \
            cp16(st_ + BOFF_A + swz128(row_, ch_),                                \
                 g_hhi + ga[i_] + (size_t)(kt) * 64 + ch_ * 8);                   \
        }                                                                         \
        _Pragma("unroll")                                                         \
        for (int i_ = 0; i_ < 4; i_++) {                                          \
            const int slot_ = tid + 256 * i_;                                     \
            const int row_ = slot_ >> 3, ch_ = slot_ & 7;                         \
            cp16(st_ + BOFF_B + swz128(row_, ch_),                                \
                 B + (size_t)(ncol0 + row_) * HID + (size_t)(kt) * 64 + ch_ * 8); \
        }                                                                         \
        CP_COMMIT();                                                              \
    } while (0)

    GLOADT(0, 0);
    GLOADT(1, 1);

    float acc[4][8][4];
    #pragma unroll
    for (int i = 0; i < 4; i++) {
        #pragma unroll
        for (int j = 0; j < 8; j++) {
            #pragma unroll
            for (int q = 0; q < 4; q++) { acc[i][j][q] = 0.0f; }
        }
    }

    const int arow = (lane & 7) | (((lane >> 3) & 1) << 3);
    const int ach  = lane >> 4;
    const int brow = (lane & 7) | (((lane >> 4) & 1) << 3);
    const int bch  = (lane >> 3) & 1;

    uint32_t ah[4][4], bh[4][4];

    for (int kt = 0; kt < nt; kt++) {
        if (kt + 1 < nt) { CP_WAIT(1); } else { CP_WAIT(0); }
        __syncthreads();
        if (kt + 2 < nt) { GLOADT((kt + 2) % 3, kt + 2); }

        const uint32_t st = sb + (uint32_t)(kt % 3) * BSTG;
        #pragma unroll
        for (int s16 = 0; s16 < 4; s16++) {
            BLDFRAG(st, s16);
            BDOMMA();
        }
    }

    #pragma unroll
    for (int i = 0; i < 4; i++) {
        const int lb = wm * 64 + i * 16 + (lane >> 2);
        #pragma unroll
        for (int h = 0; h < 2; h++) {
            const int li = lb + h * 8;
            if (rowBase + li >= cnt) continue;
            const int tok = rmap[li];
            const float s0 = g_s0[tok];
            #pragma unroll
            for (int j = 0; j < 8; j++) {
                const int col = ncol0 + wn * 64 + j * 8 + (lane & 3) * 2;
                float2 u2 = __half22float2(*(const __half2*)(g_uh + (size_t)tok * HID + col));
                float v0 = u2.x + (acc[i][j][h * 2 + 0] + bexp[e * HID + col]) * s0;
                float v1 = u2.y + (acc[i][j][h * 2 + 1] + bexp[e * HID + col + 1]) * s0;
                *(__half2*)(g_uh + (size_t)tok * HID + col) =
                    __halves2half2(__float2half_rn(v0), __float2half_rn(v1));
            }
        }
    }
    #undef GLOADT
}

// ---------------------------------------------------------------------------
extern "C" void kernel_launch(void* const* d_in, const int* in_sizes, int n_in,
                              void* d_out, int out_size)
{
    const float* x        = (const float*)d_in[0];
    const float* enc_W    = (const float*)d_in[1];
    const float* enc_b    = (const float*)d_in[2];
    const float* gate_W   = (const float*)d_in[3];
    const float* expert_W = (const float*)d_in[4];
    const float* expert_b = (const float*)d_in[5];
    const float* res_W    = (const float*)d_in[6];
    const float* res_b    = (const float*)d_in[7];
    const float* coef_W   = (const float*)d_in[8];
    const float* coef_b   = (const float*)d_in[9];
    const float* dec_W    = (const float*)d_in[10];
    const float* dec_b    = (const float*)d_in[11];
    float* out = (float*)d_out;

    __half *xhi, *xlo, *hhi, *hlo, *uh, *whi, *wlo;
    float *s1p;
    cudaGetSymbolAddress((void**)&xhi, g_xhi);
    cudaGetSymbolAddress((void**)&xlo, g_xlo);
    cudaGetSymbolAddress((void**)&hhi, g_hhi);
    cudaGetSymbolAddress((void**)&hlo, g_hlo);
    cudaGetSymbolAddress((void**)&uh,  g_uh);
    cudaGetSymbolAddress((void**)&whi, g_Whi);
    cudaGetSymbolAddress((void**)&wlo, g_Wlo);
    cudaGetSymbolAddress((void**)&s1p, g_s1);

    cudaFuncSetAttribute((const void*)hmma_gemm_enc,         cudaFuncAttributeMaxDynamicSharedMemorySize, SMEM_TOT);
    cudaFuncSetAttribute((const void*)hmma_gemm_big<1>,      cudaFuncAttributeMaxDynamicSharedMemorySize, BSMEM_TOT);
    cudaFuncSetAttribute((const void*)hmma_gemm_big<2>,      cudaFuncAttributeMaxDynamicSharedMemorySize, BSMEM_TOT);
    cudaFuncSetAttribute((const void*)hmma_gemm_grouped_big, cudaFuncAttributeMaxDynamicSharedMemorySize, BSMEM_TOT);

    // side stream + events (lazy init; host-side only, device work identical per call)
    static cudaStream_t s2 = nullptr;
    static cudaEvent_t evF = nullptr, evJ = nullptr;
    if (!s2) {
        cudaStreamCreateWithFlags(&s2, cudaStreamNonBlocking);
        cudaEventCreateWithFlags(&evF, cudaEventDisableTiming);
        cudaEventCreateWithFlags(&evJ, cudaEventDisableTiming);
    }

    // fork: res/exp/dec weight transposes run on side stream, hidden under enc
    cudaEventRecord(evF, 0);
    cudaStreamWaitEvent(s2, evF, 0);
    transpose_conv<<<dim3(HID/32, HID/32, 1),    dim3(32, 8), 0, s2>>>(res_W,    whi + W_RES_OFF, nullptr, HID, HID);
    transpose_conv<<<dim3(HID/32, HID/32, NEXP), dim3(32, 8), 0, s2>>>(expert_W, whi + W_EXP_OFF, nullptr, HID, HID);
    transpose_conv<<<dim3(IN_DIM/32, HID/32, 1), dim3(32, 8), 0, s2>>>(dec_W,    whi + W_DEC_OFF, nullptr, HID, IN_DIM);
    cudaEventRecord(evJ, s2);

    // main stream: enc path
    conv_x_kernel<<<(N_TOK * IN_DIM) / 1024, 256>>>(x);
    transpose_conv<<<dim3(HID/32, IN_DIM/32, 1), dim3(32, 8)>>>(enc_W, whi + W_ENC_OFF, wlo, IN_DIM, HID);
    zero_counts_kernel<<<1, 32>>>();

    // h = relu(x @ enc_W + enc_b) : 3-pass 128x128 (protects argmax)
    hmma_gemm_enc<<<dim3(HID/128, N_TOK/128), 256, SMEM_TOT>>>(
        xhi, xlo, whi + W_ENC_OFF, wlo,
        enc_b, IN_DIM, HID, hhi, hlo);

    // gating
    gating_kernel<<<N_TOK, 128>>>(gate_W, coef_W, coef_b);

    // join: weight transposes must be done before post-gating GEMMs
    cudaStreamWaitEvent(0, evJ, 0);

    // u = (h @ res_W + res_b) * s1 : 1-pass 256x128 -> fp16 uh
    hmma_gemm_big<1><<<dim3(HID/128, N_TOK/256), 256, BSMEM_TOT>>>(
        hhi, whi + W_RES_OFF, res_b, HID, HID, uh, nullptr, s1p);

    // uh += (h @ W_e + b_e) * s0 : 1-pass 256x128 grouped (fp16 RMW)
    hmma_gemm_grouped_big<<<dim3(HID/128, N_TOK/256, NEXP), 256, BSMEM_TOT>>>(expert_b);

    // out = uh @ dec_W + dec_b : 1-pass 256x128 -> fp32 out
    hmma_gemm_big<2><<<dim3(IN_DIM/128, N_TOK/256), 256, BSMEM_TOT>>>(
        uh, whi + W_DEC_OFF, dec_b, HID, IN_DIM, nullptr, out, nullptr);
}

// round 12
// speedup vs baseline: 5.5236x; 1.0091x over previous
#include <cuda_runtime.h>
#include <cuda_fp16.h>
#include <cuda.h>
#include <cstdint>
#include <math.h>

#define N_TOK  16384
#define IN_DIM 1024
#define HID    2048
#define NEXP   8

// ---- device scratch (globals: allocation-free) ----
__device__ __align__(128) __half g_xhi[(size_t)N_TOK * IN_DIM];
__device__ __align__(128) __half g_xlo[(size_t)N_TOK * IN_DIM];
__device__ __align__(128) __half g_hhi[(size_t)N_TOK * HID];
__device__ __align__(128) __half g_hlo[(size_t)N_TOK * HID];
__device__ __align__(128) __half g_uh[(size_t)N_TOK * HID];

#define W_ENC_OFF 0
#define W_RES_OFF (2048*1024)
#define W_EXP_OFF (W_RES_OFF + 2048*2048)
#define W_DEC_OFF (W_EXP_OFF + 8*2048*2048)
#define W_TOTAL   (W_DEC_OFF + 1024*2048)
__device__ __align__(128) __half g_Whi[(size_t)W_TOTAL];
__device__ __align__(128) __half g_Wlo[(size_t)IN_DIM * HID];  // enc lo only

__device__ int   g_perm[NEXP * N_TOK];
__device__ int   g_counts[NEXP];
__device__ float g_s0[N_TOK];
__device__ float g_s1[N_TOK];

// ---- enc kernel SMEM: 3 stages x (Ah,Al,Bh,Bl each 16KB) = 192KB ----
#define STG_BYTES 65536
#define OFF_AH 0
#define OFF_AL 16384
#define OFF_BH 32768
#define OFF_BL 49152
#define SMEM_TOT (3 * STG_BYTES + 512)

// ---- big-tile (256x128, 1-pass) SMEM: 3 stages x (A 32KB + B 16KB) ----
#define BSTG 49152
#define BOFF_A 0
#define BOFF_B 32768
#define BSM_RMAP (3 * BSTG)
#define BSMEM_TOT (3 * BSTG + 1152)

// ---- PTX helpers ----
__device__ __forceinline__ uint32_t smem_u32(const void* p) {
    uint32_t r;
    asm("{ .reg .u64 t; cvta.to.shared.u64 t, %1; cvt.u32.u64 %0, t; }" : "=r"(r) : "l"(p));
    return r;
}
__device__ __forceinline__ void cp16(uint32_t s, const void* g) {
    asm volatile("cp.async.cg.shared.global [%0], [%1], 16;" :: "r"(s), "l"(g));
}
#define CP_COMMIT() asm volatile("cp.async.commit_group;" ::: "memory")
#define CP_WAIT(n)  asm volatile("cp.async.wait_group %0;" :: "n"(n) : "memory")

__device__ __forceinline__ void ldsm4(uint32_t* r, uint32_t a) {
    asm volatile("ldmatrix.sync.aligned.m8n8.x4.shared.b16 {%0,%1,%2,%3}, [%4];"
                 : "=r"(r[0]), "=r"(r[1]), "=r"(r[2]), "=r"(r[3]) : "r"(a));
}
__device__ __forceinline__ void mma16816(float* c, const uint32_t* a, const uint32_t* b) {
    asm volatile(
        "mma.sync.aligned.m16n8k16.row.col.f32.f16.f16.f32 "
        "{%0,%1,%2,%3}, {%4,%5,%6,%7}, {%8,%9}, {%0,%1,%2,%3};"
        : "+f"(c[0]), "+f"(c[1]), "+f"(c[2]), "+f"(c[3])
        : "r"(a[0]), "r"(a[1]), "r"(a[2]), "r"(a[3]), "r"(b[0]), "r"(b[1]));
}

// 128B-row XOR swizzle: conflict-free for ldmatrix and coalesced stores
__device__ __forceinline__ uint32_t swz128(int row, int chunk) {
    return (uint32_t)(row * 128 + ((chunk ^ (row & 7)) * 16));
}

__device__ __forceinline__ void splitf(float v, __half& h, __half& l) {
    h = __float2half_rn(v);
    l = __float2half_rn(v - __half2float(h));
}

// ---- small kernels ----
__global__ __launch_bounds__(256) void conv_x_kernel(const float* __restrict__ x) {
    if (blockIdx.x == 0 && threadIdx.x < NEXP) { g_counts[threadIdx.x] = 0; }
    size_t i = ((size_t)blockIdx.x * 256 + threadIdx.x) * 4;
    float4 v = *(const float4*)(x + i);
    __half hb[4], lb[4];
    splitf(v.x, hb[0], lb[0]); splitf(v.y, hb[1], lb[1]);
    splitf(v.z, hb[2], lb[2]); splitf(v.w, hb[3], lb[3]);
    *(uint2*)(g_xhi + i) = *(uint2*)hb;
    *(uint2*)(g_xlo + i) = *(uint2*)lb;
}

// src [K,N] fp32 (batched over z) -> dst [N,K] fp16 hi (+lo), vectorized stores
__global__ __launch_bounds__(256)
void transpose_conv(const float* __restrict__ src, __half* __restrict__ dhi,
                    __half* __restrict__ dlo, int K, int N)
{
    __shared__ float t[32][33];
    const size_t zoff = (size_t)blockIdx.z * K * N;
    const int n0 = blockIdx.x * 32, k0 = blockIdx.y * 32;
    const int tx = threadIdx.x, ty = threadIdx.y;
    #pragma unroll
    for (int i = 0; i < 4; i++) {
        t[ty + i*8][tx] = src[zoff + (size_t)(k0 + ty + i*8) * N + n0 + tx];
    }
    __syncthreads();
    const int tid = ty * 32 + tx;
    const int nl = tid >> 3;
    const int kl = (tid & 7) * 4;
    __half h4[4], l4[4];
    #pragma unroll
    for (int q = 0; q < 4; q++) {
        splitf(t[kl + q][nl], h4[q], l4[q]);
    }
    const size_t di = zoff + (size_t)(n0 + nl) * K + k0 + kl;
    *(uint2*)(dhi + di) = *(uint2*)h4;
    if (dlo) { *(uint2*)(dlo + di) = *(uint2*)l4; }
}

// ---- gating ----
__global__ __launch_bounds__(128)
void gating_kernel(const float* __restrict__ gate_W, const float* __restrict__ coef_W,
                   const float* __restrict__ coef_b)
{
    const int n = blockIdx.x;
    const int t = threadIdx.x;
    float acc[10];
    #pragma unroll
    for (int j = 0; j < 10; j++) { acc[j] = 0.0f; }

    const __half* hh = g_hhi + (size_t)n * HID;
    const __half* hl = g_hlo + (size_t)n * HID;
    for (int k = t; k < HID; k += 128) {
        const float hv = __half2float(hh[k]) + __half2float(hl[k]);
        #pragma unroll
        for (int j = 0; j < 8; j++) { acc[j] += hv * gate_W[k * 8 + j]; }
        acc[8] += hv * coef_W[k * 2 + 0];
        acc[9] += hv * coef_W[k * 2 + 1];
    }
    #pragma unroll
    for (int j = 0; j < 10; j++) {
        #pragma unroll
        for (int o = 16; o > 0; o >>= 1) {
            acc[j] += __shfl_down_sync(0xffffffffu, acc[j], o);
        }
    }

    __shared__ float red[4][10];
    const int warp = t >> 5, lane = t & 31;
    if (lane == 0) {
        #pragma unroll
        for (int j = 0; j < 10; j++) { red[warp][j] = acc[j]; }
    }
    __syncthreads();

    if (t == 0) {
        float v[10];
        #pragma unroll
        for (int j = 0; j < 10; j++) {
            v[j] = red[0][j] + red[1][j] + red[2][j] + red[3][j];
        }
        float lmax = v[0]; int idx = 0;
        #pragma unroll
        for (int j = 1; j < 8; j++) {
            if (v[j] > lmax) { lmax = v[j]; idx = j; }
        }
        float s = 0.0f;
        #pragma unroll
        for (int j = 0; j < 8; j++) { s += expf(v[j] - lmax); }
        const float gate = 1.0f / s;
        const float c0 = v[8] + coef_b[0];
        const float c1 = v[9] + coef_b[1];
        const float cm = fmaxf(c0, c1);
        const float e0 = expf(c0 - cm), e1 = expf(c1 - cm);
        const float inv = 1.0f / (e0 + e1);
        g_s0[n] = gate * e0 * inv;
        g_s1[n] = e1 * inv;
        const int pos = atomicAdd(&g_counts[idx], 1);
        g_perm[idx * N_TOK + pos] = n;
    }
}

// ===========================================================================
// ENC kernel: 128x128, 3-pass split-fp16 (protects gating argmax)
// ===========================================================================
__global__ __launch_bounds__(256, 1)
void hmma_gemm_enc(const __half* __restrict__ Ahi, const __half* __restrict__ Alo,
                   const __half* __restrict__ Bhi, const __half* __restrict__ Blo,
                   const float* __restrict__ bias, int K, int Nn,
                   __half* __restrict__ Chi, __half* __restrict__ Clo)
{
    extern __shared__ __align__(1024) char smem[];
    const uint32_t sb = smem_u32(smem);
    const int tid = threadIdx.x;
    const int lane = tid & 31, wid = tid >> 5;
    const int wm = wid >> 2, wn = wid & 3;           // 2 x 4 warp grid
    const int mrow0 = blockIdx.y * 128;
    const int ncol0 = blockIdx.x * 128;
    const int nt = K / 64;

    int lrow[4], lch[4];
    uint32_t lsw[4];
    #pragma unroll
    for (int i = 0; i < 4; i++) {
        const int slot = tid + 256 * i;
        lrow[i] = slot >> 3;
        lch[i]  = slot & 7;
        lsw[i]  = swz128(lrow[i], lch[i]);
    }

    #define LOADE(s, kt) do {                                                    \
        const uint32_t st_ = sb + (uint32_t)(s) * STG_BYTES;                      \
        _Pragma("unroll")                                                         \
        for (int i_ = 0; i_ < 4; i_++) {                                          \
            const size_t go_ = (size_t)(kt) * 64 + lch[i_] * 8;                   \
            cp16(st_ + OFF_AH + lsw[i_], Ahi + (size_t)(mrow0 + lrow[i_]) * K + go_); \
            cp16(st_ + OFF_AL + lsw[i_], Alo + (size_t)(mrow0 + lrow[i_]) * K + go_); \
            cp16(st_ + OFF_BH + lsw[i_], Bhi + (size_t)(ncol0 + lrow[i_]) * K + go_); \
            cp16(st_ + OFF_BL + lsw[i_], Blo + (size_t)(ncol0 + lrow[i_]) * K + go_); \
        }                                                                         \
        CP_COMMIT();                                                              \
    } while (0)

    LOADE(0, 0);
    LOADE(1, 1);

    float acc[4][4][4];
    #pragma unroll
    for (int i = 0; i < 4; i++) {
        #pragma unroll
        for (int j = 0; j < 4; j++) {
            #pragma unroll
            for (int q = 0; q < 4; q++) { acc[i][j][q] = 0.0f; }
        }
    }

    const int arow = (lane & 7) | (((lane >> 3) & 1) << 3);
    const int ach  = lane >> 4;
    const int brow = (lane & 7) | (((lane >> 4) & 1) << 3);
    const int bch  = (lane >> 3) & 1;

    uint32_t ah[4][4], al[4][4], bh[2][4], bl[2][4];

    for (int kt = 0; kt < nt; kt++) {
        if (kt + 1 < nt) { CP_WAIT(1); } else { CP_WAIT(0); }
        __syncthreads();
        if (kt + 2 < nt) { LOADE((kt + 2) % 3, kt + 2); }

        const uint32_t st = sb + (uint32_t)(kt % 3) * STG_BYTES;
        #pragma unroll
        for (int s16 = 0; s16 < 4; s16++) {
            #pragma unroll
            for (int i = 0; i < 4; i++) {
                const uint32_t a = swz128(wm * 64 + i * 16 + arow, s16 * 2 + ach);
                ldsm4(ah[i], st + OFF_AH + a);
                ldsm4(al[i], st + OFF_AL + a);
            }
            #pragma unroll
            for (int j = 0; j < 2; j++) {
                const uint32_t b = swz128(wn * 32 + j * 16 + brow, s16 * 2 + bch);
                ldsm4(bh[j], st + OFF_BH + b);
                ldsm4(bl[j], st + OFF_BL + b);
            }
            #pragma unroll
            for (int i = 0; i < 4; i++) {
                #pragma unroll
                for (int j = 0; j < 4; j++) {
                    mma16816(acc[i][j], ah[i], &bh[j >> 1][(j & 1) * 2]);
                    mma16816(acc[i][j], ah[i], &bl[j >> 1][(j & 1) * 2]);
                    mma16816(acc[i][j], al[i], &bh[j >> 1][(j & 1) * 2]);
                }
            }
        }
    }

    // epilogue: relu + split -> Chi/Clo
    #pragma unroll
    for (int i = 0; i < 4; i++) {
        const int rb = mrow0 + wm * 64 + i * 16 + (lane >> 2);
        #pragma unroll
        for (int h = 0; h < 2; h++) {
            const int row = rb + h * 8;
            #pragma unroll
            for (int j = 0; j < 4; j++) {
                const int col = ncol0 + wn * 32 + j * 8 + (lane & 3) * 2;
                float v0 = fmaxf(acc[i][j][h * 2 + 0] + bias[col], 0.0f);
                float v1 = fmaxf(acc[i][j][h * 2 + 1] + bias[col + 1], 0.0f);
                __half h0, l0, h1, l1;
                splitf(v0, h0, l0); splitf(v1, h1, l1);
                *(__half2*)(Chi + (size_t)row * Nn + col) = __halves2half2(h0, h1);
                *(__half2*)(Clo + (size_t)row * Nn + col) = __halves2half2(l0, l1);
            }
        }
    }
    #undef LOADE
}

// ===========================================================================
// Big-tile 1-pass GEMM: CTA 256x128, BK=64, 8 warps (4x2), warp tile 64x64.
// MODE 1: acc+bias -> Ch (fp16, unscaled) ; MODE 2: acc+bias -> Cf (fp32)
// ===========================================================================
#define BLDFRAG(st, s16) do {                                                    \
    _Pragma("unroll")                                                             \
    for (int i_ = 0; i_ < 4; i_++) {                                              \
        ldsm4(ah[i_], (st) + BOFF_A + swz128(wm * 64 + i_ * 16 + arow, (s16) * 2 + ach)); \
    }                                                                             \
    _Pragma("unroll")                                                             \
    for (int j_ = 0; j_ < 4; j_++) {                                              \
        ldsm4(bh[j_], (st) + BOFF_B + swz128(wn * 64 + j_ * 16 + brow, (s16) * 2 + bch)); \
    }                                                                             \
} while (0)

#define BDOMMA() do {                                                             \
    _Pragma("unroll")                                                             \
    for (int i_ = 0; i_ < 4; i_++) {                                              \
        _Pragma("unroll")                                                         \
        for (int j_ = 0; j_ < 8; j_++) {                                          \
            mma16816(acc[i_][j_], ah[i_], &bh[j_ >> 1][(j_ & 1) * 2]);            \
        }                                                                         \
    }                                                                             \
} while (0)

template <int MODE>
__global__ __launch_bounds__(256, 1)
void hmma_gemm_big(const __half* __restrict__ A, const __half* __restrict__ B,
                   const float* __restrict__ bias, int K, int Nn,
                   __half* __restrict__ Ch, float* __restrict__ Cf)
{
    extern __shared__ __align__(1024) char smem[];
    const uint32_t sb = smem_u32(smem);
    const int tid = threadIdx.x;
    const int lane = tid & 31, wid = tid >> 5;
    const int wm = wid >> 1, wn = wid & 1;           // 4 x 2 warp grid
    const int mrow0 = blockIdx.y * 256;
    const int ncol0 = blockIdx.x * 128;
    const int nt = K / 64;

    #define BLOADT(s, kt) do {                                                   \
        const uint32_t st_ = sb + (uint32_t)(s) * BSTG;                           \
        _Pragma("unroll")                                                         \
        for (int i_ = 0; i_ < 8; i_++) {                                          \
            const int slot_ = tid + 256 * i_;                                     \
            const int row_ = slot_ >> 3, ch_ = slot_ & 7;                         \
            cp16(st_ + BOFF_A + swz128(row_, ch_),                                \
                 A + (size_t)(mrow0 + row_) * K + (size_t)(kt) * 64 + ch_ * 8);   \
        }                                                                         \
        _Pragma("unroll")                                                         \
        for (int i_ = 0; i_ < 4; i_++) {                                          \
            const int slot_ = tid + 256 * i_;                                     \
            const int row_ = slot_ >> 3, ch_ = slot_ & 7;                         \
            cp16(st_ + BOFF_B + swz128(row_, ch_),                                \
                 B + (size_t)(ncol0 + row_) * K + (size_t)(kt) * 64 + ch_ * 8);   \
        }                                                                         \
        CP_COMMIT();                                                              \
    } while (0)

    BLOADT(0, 0);
    BLOADT(1, 1);

    float acc[4][8][4];
    #pragma unroll
    for (int i = 0; i < 4; i++) {
        #pragma unroll
        for (int j = 0; j < 8; j++) {
            #pragma unroll
            for (int q = 0; q < 4; q++) { acc[i][j][q] = 0.0f; }
        }
    }

    const int arow = (lane & 7) | (((lane >> 3) & 1) << 3);
    const int ach  = lane >> 4;
    const int brow = (lane & 7) | (((lane >> 4) & 1) << 3);
    const int bch  = (lane >> 3) & 1;

    uint32_t ah[4][4], bh[4][4];

    for (int kt = 0; kt < nt; kt++) {
        if (kt + 1 < nt) { CP_WAIT(1); } else { CP_WAIT(0); }
        __syncthreads();
        if (kt + 2 < nt) { BLOADT((kt + 2) % 3, kt + 2); }

        const uint32_t st = sb + (uint32_t)(kt % 3) * BSTG;
        #pragma unroll
        for (int s16 = 0; s16 < 4; s16++) {
            BLDFRAG(st, s16);
            BDOMMA();
        }
    }

    // epilogue
    #pragma unroll
    for (int i = 0; i < 4; i++) {
        const int rb = mrow0 + wm * 64 + i * 16 + (lane >> 2);
        #pragma unroll
        for (int h = 0; h < 2; h++) {
            const int row = rb + h * 8;
            #pragma unroll
            for (int j = 0; j < 8; j++) {
                const int col = ncol0 + wn * 64 + j * 8 + (lane & 3) * 2;
                float v0 = acc[i][j][h * 2 + 0] + bias[col];
                float v1 = acc[i][j][h * 2 + 1] + bias[col + 1];
                if (MODE == 1) {
                    *(__half2*)(Ch + (size_t)row * Nn + col) =
                        __halves2half2(__float2half_rn(v0), __float2half_rn(v1));
                } else {
                    *(float2*)(Cf + (size_t)row * Nn + col) = make_float2(v0, v1);
                }
            }
        }
    }
    #undef BLOADT
}

// ===========================================================================
// Grouped expert GEMM (1-pass, big tile 256x128): A rows via g_perm;
// epilogue: g_uh[tok] = fp16(uh_raw[tok]*s1[tok] + (acc + b_e)*s0[tok])
// ===========================================================================
__global__ __launch_bounds__(256, 1)
void hmma_gemm_grouped_big(const float* __restrict__ bexp)
{
    extern __shared__ __align__(1024) char smem[];
    const int e = blockIdx.z;
    const int cnt = g_counts[e];
    const int rowBase = blockIdx.y * 256;
    if (rowBase >= cnt) return;

    const uint32_t sb = smem_u32(smem);
    const int tid = threadIdx.x;
    const int lane = tid & 31, wid = tid >> 5;
    const int wm = wid >> 1, wn = wid & 1;
    const int ncol0 = blockIdx.x * 128;
    const int nt = HID / 64;
    int* rmap = (int*)(smem + BSM_RMAP);

    {
        int i = rowBase + tid;
        if (i > cnt - 1) i = cnt - 1;
        rmap[tid] = g_perm[e * N_TOK + i];
    }
    __syncthreads();

    const __half* B = g_Whi + W_EXP_OFF + (size_t)e * HID * HID;

    size_t ga[8];
    #pragma unroll
    for (int i = 0; i < 8; i++) {
        ga[i] = (size_t)rmap[(tid + 256 * i) >> 3] * HID;
    }

    #define GLOADT(s, kt) do {                                                   \
        const uint32_t st_ = sb + (uint32_t)(s) * BSTG;                           \
        _Pragma("unroll")                                                         \
        for (int i_ = 0; i_ < 8; i_++) {                                          \
            const int slot_ = tid + 256 * i_;                                     \
            const int row_ = slot_ >> 3, ch_ = slot_ & 7;                         \
            cp16(st_ + BOFF_A + swz128(row_, ch_),                                \
                 g_hhi + ga[i_] + (size_t)(kt) * 64 + ch_ * 8);                   \
        }                                                                         \
        _Pragma("unroll")                                                         \
        for (int i_ = 0; i_ < 4; i_++) {                                          \
            const int slot_ = tid + 256 * i_;                                     \
            const int row_ = slot_ >> 3, ch_ = slot_ & 7;                         \
            cp16(st_ + BOFF_B + swz128(row_, ch_),                                \
                 B + (size_t)(ncol0 + row_) * HID + (size_t)(kt) * 64 + ch_ * 8); \
        }                                                                         \
        CP_COMMIT();                                                              \
    } while (0)

    GLOADT(0, 0);
    GLOADT(1, 1);

    float acc[4][8][4];
    #pragma unroll
    for (int i = 0; i < 4; i++) {
        #pragma unroll
        for (int j = 0; j < 8; j++) {
            #pragma unroll
            for (int q = 0; q < 4; q++) { acc[i][j][q] = 0.0f; }
        }
    }

    const int arow = (lane & 7) | (((lane >> 3) & 1) << 3);
    const int ach  = lane >> 4;
    const int brow = (lane & 7) | (((lane >> 4) & 1) << 3);
    const int bch  = (lane >> 3) & 1;

    uint32_t ah[4][4], bh[4][4];

    for (int kt = 0; kt < nt; kt++) {
        if (kt + 1 < nt) { CP_WAIT(1); } else { CP_WAIT(0); }
        __syncthreads();
        if (kt + 2 < nt) { GLOADT((kt + 2) % 3, kt + 2); }

        const uint32_t st = sb + (uint32_t)(kt % 3) * BSTG;
        #pragma unroll
        for (int s16 = 0; s16 < 4; s16++) {
            BLDFRAG(st, s16);
            BDOMMA();
        }
    }

    #pragma unroll
    for (int i = 0; i < 4; i++) {
        const int lb = wm * 64 + i * 16 + (lane >> 2);
        #pragma unroll
        for (int h = 0; h < 2; h++) {
            const int li = lb + h * 8;
            if (rowBase + li >= cnt) continue;
            const int tok = rmap[li];
            const float s0 = g_s0[tok];
            const float s1 = g_s1[tok];
            #pragma unroll
            for (int j = 0; j < 8; j++) {
                const int col = ncol0 + wn * 64 + j * 8 + (lane & 3) * 2;
                float2 u2 = __half22float2(*(const __half2*)(g_uh + (size_t)tok * HID + col));
                float v0 = u2.x * s1 + (acc[i][j][h * 2 + 0] + bexp[e * HID + col]) * s0;
                float v1 = u2.y * s1 + (acc[i][j][h * 2 + 1] + bexp[e * HID + col + 1]) * s0;
                *(__half2*)(g_uh + (size_t)tok * HID + col) =
                    __halves2half2(__float2half_rn(v0), __float2half_rn(v1));
            }
        }
    }
    #undef GLOADT
}

// ---------------------------------------------------------------------------
extern "C" void kernel_launch(void* const* d_in, const int* in_sizes, int n_in,
                              void* d_out, int out_size)
{
    const float* x        = (const float*)d_in[0];
    const float* enc_W    = (const float*)d_in[1];
    const float* enc_b    = (const float*)d_in[2];
    const float* gate_W   = (const float*)d_in[3];
    const float* expert_W = (const float*)d_in[4];
    const float* expert_b = (const float*)d_in[5];
    const float* res_W    = (const float*)d_in[6];
    const float* res_b    = (const float*)d_in[7];
    const float* coef_W   = (const float*)d_in[8];
    const float* coef_b   = (const float*)d_in[9];
    const float* dec_W    = (const float*)d_in[10];
    const float* dec_b    = (const float*)d_in[11];
    float* out = (float*)d_out;

    __half *xhi, *xlo, *hhi, *hlo, *uh, *whi, *wlo;
    cudaGetSymbolAddress((void**)&xhi, g_xhi);
    cudaGetSymbolAddress((void**)&xlo, g_xlo);
    cudaGetSymbolAddress((void**)&hhi, g_hhi);
    cudaGetSymbolAddress((void**)&hlo, g_hlo);
    cudaGetSymbolAddress((void**)&uh,  g_uh);
    cudaGetSymbolAddress((void**)&whi, g_Whi);
    cudaGetSymbolAddress((void**)&wlo, g_Wlo);

    cudaFuncSetAttribute((const void*)hmma_gemm_enc,         cudaFuncAttributeMaxDynamicSharedMemorySize, SMEM_TOT);
    cudaFuncSetAttribute((const void*)hmma_gemm_big<1>,      cudaFuncAttributeMaxDynamicSharedMemorySize, BSMEM_TOT);
    cudaFuncSetAttribute((const void*)hmma_gemm_big<2>,      cudaFuncAttributeMaxDynamicSharedMemorySize, BSMEM_TOT);
    cudaFuncSetAttribute((const void*)hmma_gemm_grouped_big, cudaFuncAttributeMaxDynamicSharedMemorySize, BSMEM_TOT);

    // side stream + events (lazy init; host-side only, device work identical per call)
    static cudaStream_t s2 = nullptr;
    static cudaEvent_t evF = nullptr, evJ = nullptr, evE = nullptr, evG = nullptr;
    if (!s2) {
        cudaStreamCreateWithFlags(&s2, cudaStreamNonBlocking);
        cudaEventCreateWithFlags(&evF, cudaEventDisableTiming);
        cudaEventCreateWithFlags(&evJ, cudaEventDisableTiming);
        cudaEventCreateWithFlags(&evE, cudaEventDisableTiming);
        cudaEventCreateWithFlags(&evG, cudaEventDisableTiming);
    }

    // fork: res/exp/dec weight transposes on side stream (hidden under enc path)
    cudaEventRecord(evF, 0);
    cudaStreamWaitEvent(s2, evF, 0);
    transpose_conv<<<dim3(HID/32, HID/32, 1),    dim3(32, 8), 0, s2>>>(res_W,    whi + W_RES_OFF, nullptr, HID, HID);
    transpose_conv<<<dim3(HID/32, HID/32, NEXP), dim3(32, 8), 0, s2>>>(expert_W, whi + W_EXP_OFF, nullptr, HID, HID);
    transpose_conv<<<dim3(IN_DIM/32, HID/32, 1), dim3(32, 8), 0, s2>>>(dec_W,    whi + W_DEC_OFF, nullptr, HID, IN_DIM);
    cudaEventRecord(evJ, s2);

    // main stream: enc path (conv_x also zeroes g_counts)
    conv_x_kernel<<<(N_TOK * IN_DIM) / 1024, 256>>>(x);
    transpose_conv<<<dim3(HID/32, IN_DIM/32, 1), dim3(32, 8)>>>(enc_W, whi + W_ENC_OFF, wlo, IN_DIM, HID);

    // h = relu(x @ enc_W + enc_b) : 3-pass 128x128 (protects argmax)
    hmma_gemm_enc<<<dim3(HID/128, N_TOK/128), 256, SMEM_TOT>>>(
        xhi, xlo, whi + W_ENC_OFF, wlo,
        enc_b, IN_DIM, HID, hhi, hlo);
    cudaEventRecord(evE, 0);

    // gating on side stream, concurrent with res GEMM (res doesn't need s1 now)
    cudaStreamWaitEvent(s2, evE, 0);
    gating_kernel<<<N_TOK, 128, 0, s2>>>(gate_W, coef_W, coef_b);
    cudaEventRecord(evG, s2);

    // join weight transposes, then res (unscaled) on main stream
    cudaStreamWaitEvent(0, evJ, 0);

    // uh_raw = h @ res_W + res_b : 1-pass 256x128 -> fp16 (unscaled)
    hmma_gemm_big<1><<<dim3(HID/128, N_TOK/256), 256, BSMEM_TOT>>>(
        hhi, whi + W_RES_OFF, res_b, HID, HID, uh, nullptr);

    // join gating, then grouped: uh = uh_raw*s1 + (h @ W_e + b_e)*s0
    cudaStreamWaitEvent(0, evG, 0);
    hmma_gemm_grouped_big<<<dim3(HID/128, N_TOK/256, NEXP), 256, BSMEM_TOT>>>(expert_b);

    // out = uh @ dec_W + dec_b : 1-pass 256x128 -> fp32 out
    hmma_gemm_big<2><<<dim3(IN_DIM/128, N_TOK/256), 256, BSMEM_TOT>>>(
        uh, whi + W_DEC_OFF, dec_b, HID, IN_DIM, nullptr, out);
}

// round 13
// speedup vs baseline: 5.5418x; 1.0033x over previous
#include <cuda_runtime.h>
#include <cuda_fp16.h>
#include <cuda.h>
#include <cstdint>
#include <math.h>

#define N_TOK  16384
#define IN_DIM 1024
#define HID    2048
#define NEXP   8

// ---- device scratch (globals: allocation-free) ----
__device__ __align__(128) __half g_xhi[(size_t)N_TOK * IN_DIM];
__device__ __align__(128) __half g_xlo[(size_t)N_TOK * IN_DIM];
__device__ __align__(128) __half g_hhi[(size_t)N_TOK * HID];
__device__ __align__(128) __half g_hlo[(size_t)N_TOK * HID];
__device__ __align__(128) __half g_uh[(size_t)N_TOK * HID];

#define W_ENC_OFF 0
#define W_RES_OFF (2048*1024)
#define W_EXP_OFF (W_RES_OFF + 2048*2048)
#define W_DEC_OFF (W_EXP_OFF + 8*2048*2048)
#define W_TOTAL   (W_DEC_OFF + 1024*2048)
__device__ __align__(128) __half g_Whi[(size_t)W_TOTAL];
__device__ __align__(128) __half g_Wlo[(size_t)IN_DIM * HID];  // enc lo only

__device__ int   g_perm[NEXP * N_TOK];
__device__ int   g_counts[NEXP];
__device__ float g_s0[N_TOK];
__device__ float g_s1[N_TOK];

// ---- enc kernel SMEM: 3 stages x (Ah,Al,Bh,Bl each 16KB) = 192KB ----
#define STG_BYTES 65536
#define OFF_AH 0
#define OFF_AL 16384
#define OFF_BH 32768
#define OFF_BL 49152
#define SMEM_TOT (3 * STG_BYTES + 512)

// ---- big-tile (256x128, 1-pass) SMEM: 3 stages x (A 32KB + B 16KB) ----
#define BSTG 49152
#define BOFF_A 0
#define BOFF_B 32768
#define BSM_RMAP (3 * BSTG)
#define BSMEM_TOT (3 * BSTG + 1152)

// ---- PTX helpers ----
__device__ __forceinline__ uint32_t smem_u32(const void* p) {
    uint32_t r;
    asm("{ .reg .u64 t; cvta.to.shared.u64 t, %1; cvt.u32.u64 %0, t; }" : "=r"(r) : "l"(p));
    return r;
}
__device__ __forceinline__ void cp16(uint32_t s, const void* g) {
    asm volatile("cp.async.cg.shared.global [%0], [%1], 16;" :: "r"(s), "l"(g));
}
#define CP_COMMIT() asm volatile("cp.async.commit_group;" ::: "memory")
#define CP_WAIT(n)  asm volatile("cp.async.wait_group %0;" :: "n"(n) : "memory")

__device__ __forceinline__ void ldsm4(uint32_t* r, uint32_t a) {
    asm volatile("ldmatrix.sync.aligned.m8n8.x4.shared.b16 {%0,%1,%2,%3}, [%4];"
                 : "=r"(r[0]), "=r"(r[1]), "=r"(r[2]), "=r"(r[3]) : "r"(a));
}
__device__ __forceinline__ void mma16816(float* c, const uint32_t* a, const uint32_t* b) {
    asm volatile(
        "mma.sync.aligned.m16n8k16.row.col.f32.f16.f16.f32 "
        "{%0,%1,%2,%3}, {%4,%5,%6,%7}, {%8,%9}, {%0,%1,%2,%3};"
        : "+f"(c[0]), "+f"(c[1]), "+f"(c[2]), "+f"(c[3])
        : "r"(a[0]), "r"(a[1]), "r"(a[2]), "r"(a[3]), "r"(b[0]), "r"(b[1]));
}

// 128B-row XOR swizzle: conflict-free for ldmatrix and coalesced stores
__device__ __forceinline__ uint32_t swz128(int row, int chunk) {
    return (uint32_t)(row * 128 + ((chunk ^ (row & 7)) * 16));
}

__device__ __forceinline__ void splitf(float v, __half& h, __half& l) {
    h = __float2half_rn(v);
    l = __float2half_rn(v - __half2float(h));
}

// ---- small kernels ----
__global__ __launch_bounds__(256) void conv_x_kernel(const float* __restrict__ x) {
    if (blockIdx.x == 0 && threadIdx.x < NEXP) { g_counts[threadIdx.x] = 0; }
    size_t i = ((size_t)blockIdx.x * 256 + threadIdx.x) * 4;
    float4 v = *(const float4*)(x + i);
    __half hb[4], lb[4];
    splitf(v.x, hb[0], lb[0]); splitf(v.y, hb[1], lb[1]);
    splitf(v.z, hb[2], lb[2]); splitf(v.w, hb[3], lb[3]);
    *(uint2*)(g_xhi + i) = *(uint2*)hb;
    *(uint2*)(g_xlo + i) = *(uint2*)lb;
}

// src [K,N] fp32 (batched over z) -> dst [N,K] fp16 hi (+lo), vectorized stores
__global__ __launch_bounds__(256)
void transpose_conv(const float* __restrict__ src, __half* __restrict__ dhi,
                    __half* __restrict__ dlo, int K, int N)
{
    __shared__ float t[32][33];
    const size_t zoff = (size_t)blockIdx.z * K * N;
    const int n0 = blockIdx.x * 32, k0 = blockIdx.y * 32;
    const int tx = threadIdx.x, ty = threadIdx.y;
    #pragma unroll
    for (int i = 0; i < 4; i++) {
        t[ty + i*8][tx] = src[zoff + (size_t)(k0 + ty + i*8) * N + n0 + tx];
    }
    __syncthreads();
    const int tid = ty * 32 + tx;
    const int nl = tid >> 3;
    const int kl = (tid & 7) * 4;
    __half h4[4], l4[4];
    #pragma unroll
    for (int q = 0; q < 4; q++) {
        splitf(t[kl + q][nl], h4[q], l4[q]);
    }
    const size_t di = zoff + (size_t)(n0 + nl) * K + k0 + kl;
    *(uint2*)(dhi + di) = *(uint2*)h4;
    if (dlo) { *(uint2*)(dlo + di) = *(uint2*)l4; }
}

// ---- gating ----
__global__ __launch_bounds__(128)
void gating_kernel(const float* __restrict__ gate_W, const float* __restrict__ coef_W,
                   const float* __restrict__ coef_b)
{
    const int n = blockIdx.x;
    const int t = threadIdx.x;
    float acc[10];
    #pragma unroll
    for (int j = 0; j < 10; j++) { acc[j] = 0.0f; }

    const __half* hh = g_hhi + (size_t)n * HID;
    const __half* hl = g_hlo + (size_t)n * HID;
    for (int k = t; k < HID; k += 128) {
        const float hv = __half2float(hh[k]) + __half2float(hl[k]);
        #pragma unroll
        for (int j = 0; j < 8; j++) { acc[j] += hv * gate_W[k * 8 + j]; }
        acc[8] += hv * coef_W[k * 2 + 0];
        acc[9] += hv * coef_W[k * 2 + 1];
    }
    #pragma unroll
    for (int j = 0; j < 10; j++) {
        #pragma unroll
        for (int o = 16; o > 0; o >>= 1) {
            acc[j] += __shfl_down_sync(0xffffffffu, acc[j], o);
        }
    }

    __shared__ float red[4][10];
    const int warp = t >> 5, lane = t & 31;
    if (lane == 0) {
        #pragma unroll
        for (int j = 0; j < 10; j++) { red[warp][j] = acc[j]; }
    }
    __syncthreads();

    if (t == 0) {
        float v[10];
        #pragma unroll
        for (int j = 0; j < 10; j++) {
            v[j] = red[0][j] + red[1][j] + red[2][j] + red[3][j];
        }
        float lmax = v[0]; int idx = 0;
        #pragma unroll
        for (int j = 1; j < 8; j++) {
            if (v[j] > lmax) { lmax = v[j]; idx = j; }
        }
        float s = 0.0f;
        #pragma unroll
        for (int j = 0; j < 8; j++) { s += expf(v[j] - lmax); }
        const float gate = 1.0f / s;
        const float c0 = v[8] + coef_b[0];
        const float c1 = v[9] + coef_b[1];
        const float cm = fmaxf(c0, c1);
        const float e0 = expf(c0 - cm), e1 = expf(c1 - cm);
        const float inv = 1.0f / (e0 + e1);
        g_s0[n] = gate * e0 * inv;
        g_s1[n] = e1 * inv;
        const int pos = atomicAdd(&g_counts[idx], 1);
        g_perm[idx * N_TOK + pos] = n;
    }
}

// ===========================================================================
// ENC kernel: 128x128, 3-pass split-fp16 (protects gating argmax)
// ===========================================================================
__global__ __launch_bounds__(256, 1)
void hmma_gemm_enc(const __half* __restrict__ Ahi, const __half* __restrict__ Alo,
                   const __half* __restrict__ Bhi, const __half* __restrict__ Blo,
                   const float* __restrict__ bias, int K, int Nn,
                   __half* __restrict__ Chi, __half* __restrict__ Clo)
{
    extern __shared__ __align__(1024) char smem[];
    const uint32_t sb = smem_u32(smem);
    const int tid = threadIdx.x;
    const int lane = tid & 31, wid = tid >> 5;
    const int wm = wid >> 2, wn = wid & 3;           // 2 x 4 warp grid
    const int mrow0 = blockIdx.y * 128;
    const int ncol0 = blockIdx.x * 128;
    const int nt = K / 64;

    int lrow[4], lch[4];
    uint32_t lsw[4];
    #pragma unroll
    for (int i = 0; i < 4; i++) {
        const int slot = tid + 256 * i;
        lrow[i] = slot >> 3;
        lch[i]  = slot & 7;
        lsw[i]  = swz128(lrow[i], lch[i]);
    }

    #define LOADE(s, kt) do {                                                    \
        const uint32_t st_ = sb + (uint32_t)(s) * STG_BYTES;                      \
        _Pragma("unroll")                                                         \
        for (int i_ = 0; i_ < 4; i_++) {                                          \
            const size_t go_ = (size_t)(kt) * 64 + lch[i_] * 8;                   \
            cp16(st_ + OFF_AH + lsw[i_], Ahi + (size_t)(mrow0 + lrow[i_]) * K + go_); \
            cp16(st_ + OFF_AL + lsw[i_], Alo + (size_t)(mrow0 + lrow[i_]) * K + go_); \
            cp16(st_ + OFF_BH + lsw[i_], Bhi + (size_t)(ncol0 + lrow[i_]) * K + go_); \
            cp16(st_ + OFF_BL + lsw[i_], Blo + (size_t)(ncol0 + lrow[i_]) * K + go_); \
        }                                                                         \
        CP_COMMIT();                                                              \
    } while (0)

    LOADE(0, 0);
    LOADE(1, 1);

    float acc[4][4][4];
    #pragma unroll
    for (int i = 0; i < 4; i++) {
        #pragma unroll
        for (int j = 0; j < 4; j++) {
            #pragma unroll
            for (int q = 0; q < 4; q++) { acc[i][j][q] = 0.0f; }
        }
    }

    const int arow = (lane & 7) | (((lane >> 3) & 1) << 3);
    const int ach  = lane >> 4;
    const int brow = (lane & 7) | (((lane >> 4) & 1) << 3);
    const int bch  = (lane >> 3) & 1;

    uint32_t ah[4][4], al[4][4], bh[2][4], bl[2][4];

    for (int kt = 0; kt < nt; kt++) {
        if (kt + 1 < nt) { CP_WAIT(1); } else { CP_WAIT(0); }
        __syncthreads();
        if (kt + 2 < nt) { LOADE((kt + 2) % 3, kt + 2); }

        const uint32_t st = sb + (uint32_t)(kt % 3) * STG_BYTES;
        #pragma unroll
        for (int s16 = 0; s16 < 4; s16++) {
            #pragma unroll
            for (int i = 0; i < 4; i++) {
                const uint32_t a = swz128(wm * 64 + i * 16 + arow, s16 * 2 + ach);
                ldsm4(ah[i], st + OFF_AH + a);
                ldsm4(al[i], st + OFF_AL + a);
            }
            #pragma unroll
            for (int j = 0; j < 2; j++) {
                const uint32_t b = swz128(wn * 32 + j * 16 + brow, s16 * 2 + bch);
                ldsm4(bh[j], st + OFF_BH + b);
                ldsm4(bl[j], st + OFF_BL + b);
            }
            #pragma unroll
            for (int i = 0; i < 4; i++) {
                #pragma unroll
                for (int j = 0; j < 4; j++) {
                    mma16816(acc[i][j], ah[i], &bh[j >> 1][(j & 1) * 2]);
                    mma16816(acc[i][j], ah[i], &bl[j >> 1][(j & 1) * 2]);
                    mma16816(acc[i][j], al[i], &bh[j >> 1][(j & 1) * 2]);
                }
            }
        }
    }

    // epilogue: relu + split -> Chi/Clo
    #pragma unroll
    for (int i = 0; i < 4; i++) {
        const int rb = mrow0 + wm * 64 + i * 16 + (lane >> 2);
        #pragma unroll
        for (int h = 0; h < 2; h++) {
            const int row = rb + h * 8;
            #pragma unroll
            for (int j = 0; j < 4; j++) {
                const int col = ncol0 + wn * 32 + j * 8 + (lane & 3) * 2;
                const float2 b2 = *(const float2*)(bias + col);
                float v0 = fmaxf(acc[i][j][h * 2 + 0] + b2.x, 0.0f);
                float v1 = fmaxf(acc[i][j][h * 2 + 1] + b2.y, 0.0f);
                __half h0, l0, h1, l1;
                splitf(v0, h0, l0); splitf(v1, h1, l1);
                *(__half2*)(Chi + (size_t)row * Nn + col) = __halves2half2(h0, h1);
                *(__half2*)(Clo + (size_t)row * Nn + col) = __halves2half2(l0, l1);
            }
        }
    }
    #undef LOADE
}

// ===========================================================================
// Big-tile 1-pass GEMM: CTA 256x128, BK=64, 8 warps (4x2), warp tile 64x64.
// MODE 1: acc+bias -> Ch (fp16, unscaled) ; MODE 2: acc+bias -> Cf (fp32)
// ===========================================================================
#define BLDFRAG(st, s16) do {                                                    \
    _Pragma("unroll")                                                             \
    for (int i_ = 0; i_ < 4; i_++) {                                              \
        ldsm4(ah[i_], (st) + BOFF_A + swz128(wm * 64 + i_ * 16 + arow, (s16) * 2 + ach)); \
    }                                                                             \
    _Pragma("unroll")                                                             \
    for (int j_ = 0; j_ < 4; j_++) {                                              \
        ldsm4(bh[j_], (st) + BOFF_B + swz128(wn * 64 + j_ * 16 + brow, (s16) * 2 + bch)); \
    }                                                                             \
} while (0)

#define BDOMMA() do {                                                             \
    _Pragma("unroll")                                                             \
    for (int i_ = 0; i_ < 4; i_++) {                                              \
        _Pragma("unroll")                                                         \
        for (int j_ = 0; j_ < 8; j_++) {                                          \
            mma16816(acc[i_][j_], ah[i_], &bh[j_ >> 1][(j_ & 1) * 2]);            \
        }                                                                         \
    }                                                                             \
} while (0)

template <int MODE>
__global__ __launch_bounds__(256, 1)
void hmma_gemm_big(const __half* __restrict__ A, const __half* __restrict__ B,
                   const float* __restrict__ bias, int K, int Nn,
                   __half* __restrict__ Ch, float* __restrict__ Cf)
{
    extern __shared__ __align__(1024) char smem[];
    const uint32_t sb = smem_u32(smem);
    const int tid = threadIdx.x;
    const int lane = tid & 31, wid = tid >> 5;
    const int wm = wid >> 1, wn = wid & 1;           // 4 x 2 warp grid
    const int mrow0 = blockIdx.y * 256;
    const int ncol0 = blockIdx.x * 128;
    const int nt = K / 64;

    #define BLOADT(s, kt) do {                                                   \
        const uint32_t st_ = sb + (uint32_t)(s) * BSTG;                           \
        _Pragma("unroll")                                                         \
        for (int i_ = 0; i_ < 8; i_++) {                                          \
            const int slot_ = tid + 256 * i_;                                     \
            const int row_ = slot_ >> 3, ch_ = slot_ & 7;                         \
            cp16(st_ + BOFF_A + swz128(row_, ch_),                                \
                 A + (size_t)(mrow0 + row_) * K + (size_t)(kt) * 64 + ch_ * 8);   \
        }                                                                         \
        _Pragma("unroll")                                                         \
        for (int i_ = 0; i_ < 4; i_++) {                                          \
            const int slot_ = tid + 256 * i_;                                     \
            const int row_ = slot_ >> 3, ch_ = slot_ & 7;                         \
            cp16(st_ + BOFF_B + swz128(row_, ch_),                                \
                 B + (size_t)(ncol0 + row_) * K + (size_t)(kt) * 64 + ch_ * 8);   \
        }                                                                         \
        CP_COMMIT();                                                              \
    } while (0)

    BLOADT(0, 0);
    BLOADT(1, 1);

    float acc[4][8][4];
    #pragma unroll
    for (int i = 0; i < 4; i++) {
        #pragma unroll
        for (int j = 0; j < 8; j++) {
            #pragma unroll
            for (int q = 0; q < 4; q++) { acc[i][j][q] = 0.0f; }
        }
    }

    const int arow = (lane & 7) | (((lane >> 3) & 1) << 3);
    const int ach  = lane >> 4;
    const int brow = (lane & 7) | (((lane >> 4) & 1) << 3);
    const int bch  = (lane >> 3) & 1;

    uint32_t ah[4][4], bh[4][4];

    for (int kt = 0; kt < nt; kt++) {
        if (kt + 1 < nt) { CP_WAIT(1); } else { CP_WAIT(0); }
        __syncthreads();
        if (kt + 2 < nt) { BLOADT((kt + 2) % 3, kt + 2); }

        const uint32_t st = sb + (uint32_t)(kt % 3) * BSTG;
        #pragma unroll
        for (int s16 = 0; s16 < 4; s16++) {
            BLDFRAG(st, s16);
            BDOMMA();
        }
    }

    // epilogue
    #pragma unroll
    for (int i = 0; i < 4; i++) {
        const int rb = mrow0 + wm * 64 + i * 16 + (lane >> 2);
        #pragma unroll
        for (int h = 0; h < 2; h++) {
            const int row = rb + h * 8;
            #pragma unroll
            for (int j = 0; j < 8; j++) {
                const int col = ncol0 + wn * 64 + j * 8 + (lane & 3) * 2;
                const float2 b2 = *(const float2*)(bias + col);
                float v0 = acc[i][j][h * 2 + 0] + b2.x;
                float v1 = acc[i][j][h * 2 + 1] + b2.y;
                if (MODE == 1) {
                    *(__half2*)(Ch + (size_t)row * Nn + col) =
                        __halves2half2(__float2half_rn(v0), __float2half_rn(v1));
                } else {
                    *(float2*)(Cf + (size_t)row * Nn + col) = make_float2(v0, v1);
                }
            }
        }
    }
    #undef BLOADT
}

// ===========================================================================
// Grouped expert GEMM (1-pass, big tile 256x128): A rows via g_perm;
// epilogue: g_uh[tok] = fp16(uh_raw[tok]*s1[tok] + (acc + b_e)*s0[tok])
// ===========================================================================
__global__ __launch_bounds__(256, 1)
void hmma_gemm_grouped_big(const float* __restrict__ bexp)
{
    extern __shared__ __align__(1024) char smem[];
    const int e = blockIdx.z;
    const int cnt = g_counts[e];
    const int rowBase = blockIdx.y * 256;
    if (rowBase >= cnt) return;

    const uint32_t sb = smem_u32(smem);
    const int tid = threadIdx.x;
    const int lane = tid & 31, wid = tid >> 5;
    const int wm = wid >> 1, wn = wid & 1;
    const int ncol0 = blockIdx.x * 128;
    const int nt = HID / 64;
    int* rmap = (int*)(smem + BSM_RMAP);

    {
        int i = rowBase + tid;
        if (i > cnt - 1) i = cnt - 1;
        rmap[tid] = g_perm[e * N_TOK + i];
    }
    __syncthreads();

    const __half* B = g_Whi + W_EXP_OFF + (size_t)e * HID * HID;

    size_t ga[8];
    #pragma unroll
    for (int i = 0; i < 8; i++) {
        ga[i] = (size_t)rmap[(tid + 256 * i) >> 3] * HID;
    }

    #define GLOADT(s, kt) do {                                                   \
        const uint32_t st_ = sb + (uint32_t)(s) * BSTG;                           \
        _Pragma("unroll")                                                         \
        for (int i_ = 0; i_ < 8; i_++) {                                          \
            const int slot_ = tid + 256 * i_;                                     \
            const int row_ = slot_ >> 3, ch_ = slot_ & 7;                         \
            cp16(st_ + BOFF_A + swz128(row_, ch_),                                \
                 g_hhi + ga[i_] + (size_t)(kt) * 64 + ch_ * 8);                   \
        }                                                                         \
        _Pragma("unroll")                                                         \
        for (int i_ = 0; i_ < 4; i_++) {                                          \
            const int slot_ = tid + 256 * i_;                                     \
            const int row_ = slot_ >> 3, ch_ = slot_ & 7;                         \
            cp16(st_ + BOFF_B + swz128(row_, ch_),                                \
                 B + (size_t)(ncol0 + row_) * HID + (size_t)(kt) * 64 + ch_ * 8); \
        }                                                                         \
        CP_COMMIT();                                                              \
    } while (0)

    GLOADT(0, 0);
    GLOADT(1, 1);

    float acc[4][8][4];
    #pragma unroll
    for (int i = 0; i < 4; i++) {
        #pragma unroll
        for (int j = 0; j < 8; j++) {
            #pragma unroll
            for (int q = 0; q < 4; q++) { acc[i][j][q] = 0.0f; }
        }
    }

    const int arow = (lane & 7) | (((lane >> 3) & 1) << 3);
    const int ach  = lane >> 4;
    const int brow = (lane & 7) | (((lane >> 4) & 1) << 3);
    const int bch  = (lane >> 3) & 1;

    uint32_t ah[4][4], bh[4][4];

    for (int kt = 0; kt < nt; kt++) {
        if (kt + 1 < nt) { CP_WAIT(1); } else { CP_WAIT(0); }
        __syncthreads();
        if (kt + 2 < nt) { GLOADT((kt + 2) % 3, kt + 2); }

        const uint32_t st = sb + (uint32_t)(kt % 3) * BSTG;
        #pragma unroll
        for (int s16 = 0; s16 < 4; s16++) {
            BLDFRAG(st, s16);
            BDOMMA();
        }
    }

    #pragma unroll
    for (int i = 0; i < 4; i++) {
        const int lb = wm * 64 + i * 16 + (lane >> 2);
        #pragma unroll
        for (int h = 0; h < 2; h++) {
            const int li = lb + h * 8;
            if (rowBase + li >= cnt) continue;
            const int tok = rmap[li];
            const float s0 = g_s0[tok];
            const float s1 = g_s1[tok];
            #pragma unroll
            for (int j = 0; j < 8; j++) {
                const int col = ncol0 + wn * 64 + j * 8 + (lane & 3) * 2;
                const float2 b2 = *(const float2*)(bexp + e * HID + col);
                float2 u2 = __half22float2(*(const __half2*)(g_uh + (size_t)tok * HID + col));
                float v0 = u2.x * s1 + (acc[i][j][h * 2 + 0] + b2.x) * s0;
                float v1 = u2.y * s1 + (acc[i][j][h * 2 + 1] + b2.y) * s0;
                *(__half2*)(g_uh + (size_t)tok * HID + col) =
                    __halves2half2(__float2half_rn(v0), __float2half_rn(v1));
            }
        }
    }
    #undef GLOADT
}

// ---------------------------------------------------------------------------
extern "C" void kernel_launch(void* const* d_in, const int* in_sizes, int n_in,
                              void* d_out, int out_size)
{
    const float* x        = (const float*)d_in[0];
    const float* enc_W    = (const float*)d_in[1];
    const float* enc_b    = (const float*)d_in[2];
    const float* gate_W   = (const float*)d_in[3];
    const float* expert_W = (const float*)d_in[4];
    const float* expert_b = (const float*)d_in[5];
    const float* res_W    = (const float*)d_in[6];
    const float* res_b    = (const float*)d_in[7];
    const float* coef_W   = (const float*)d_in[8];
    const float* coef_b   = (const float*)d_in[9];
    const float* dec_W    = (const float*)d_in[10];
    const float* dec_b    = (const float*)d_in[11];
    float* out = (float*)d_out;

    __half *xhi, *xlo, *hhi, *hlo, *uh, *whi, *wlo;
    cudaGetSymbolAddress((void**)&xhi, g_xhi);
    cudaGetSymbolAddress((void**)&xlo, g_xlo);
    cudaGetSymbolAddress((void**)&hhi, g_hhi);
    cudaGetSymbolAddress((void**)&hlo, g_hlo);
    cudaGetSymbolAddress((void**)&uh,  g_uh);
    cudaGetSymbolAddress((void**)&whi, g_Whi);
    cudaGetSymbolAddress((void**)&wlo, g_Wlo);

    cudaFuncSetAttribute((const void*)hmma_gemm_enc,         cudaFuncAttributeMaxDynamicSharedMemorySize, SMEM_TOT);
    cudaFuncSetAttribute((const void*)hmma_gemm_big<1>,      cudaFuncAttributeMaxDynamicSharedMemorySize, BSMEM_TOT);
    cudaFuncSetAttribute((const void*)hmma_gemm_big<2>,      cudaFuncAttributeMaxDynamicSharedMemorySize, BSMEM_TOT);
    cudaFuncSetAttribute((const void*)hmma_gemm_grouped_big, cudaFuncAttributeMaxDynamicSharedMemorySize, BSMEM_TOT);

    // side stream + events (lazy init; host-side only, device work identical per call)
    static cudaStream_t s2 = nullptr;
    static cudaEvent_t evF = nullptr, evJ = nullptr, evE = nullptr, evG = nullptr;
    if (!s2) {
        cudaStreamCreateWithFlags(&s2, cudaStreamNonBlocking);
        cudaEventCreateWithFlags(&evF, cudaEventDisableTiming);
        cudaEventCreateWithFlags(&evJ, cudaEventDisableTiming);
        cudaEventCreateWithFlags(&evE, cudaEventDisableTiming);
        cudaEventCreateWithFlags(&evG, cudaEventDisableTiming);
    }

    // main stream: enc path (submitted first so enc is the 4th launch -> ncu window)
    conv_x_kernel<<<(N_TOK * IN_DIM) / 1024, 256>>>(x);                              // launch 1
    transpose_conv<<<dim3(HID/32, IN_DIM/32, 1), dim3(32, 8)>>>(enc_W, whi + W_ENC_OFF, wlo, IN_DIM, HID);  // launch 2

    // fork side stream for res transpose before enc (launch 3)
    cudaEventRecord(evF, 0);
    cudaStreamWaitEvent(s2, evF, 0);
    transpose_conv<<<dim3(HID/32, HID/32, 1), dim3(32, 8), 0, s2>>>(res_W, whi + W_RES_OFF, nullptr, HID, HID);  // launch 3

    // h = relu(x @ enc_W + enc_b) : 3-pass 128x128 (protects argmax) -- launch 4 (profiled)
    hmma_gemm_enc<<<dim3(HID/128, N_TOK/128), 256, SMEM_TOT>>>(
        xhi, xlo, whi + W_ENC_OFF, wlo,
        enc_b, IN_DIM, HID, hhi, hlo);
    cudaEventRecord(evE, 0);

    // remaining weight transposes on side stream (overlap enc execution)
    transpose_conv<<<dim3(HID/32, HID/32, NEXP), dim3(32, 8), 0, s2>>>(expert_W, whi + W_EXP_OFF, nullptr, HID, HID);
    transpose_conv<<<dim3(IN_DIM/32, HID/32, 1), dim3(32, 8), 0, s2>>>(dec_W,    whi + W_DEC_OFF, nullptr, HID, IN_DIM);
    cudaEventRecord(evJ, s2);

    // gating on side stream, concurrent with res GEMM (res doesn't need s1)
    cudaStreamWaitEvent(s2, evE, 0);
    gating_kernel<<<N_TOK, 128, 0, s2>>>(gate_W, coef_W, coef_b);
    cudaEventRecord(evG, s2);

    // join weight transposes, then res (unscaled) on main stream
    cudaStreamWaitEvent(0, evJ, 0);

    // uh_raw = h @ res_W + res_b : 1-pass 256x128 -> fp16 (unscaled)
    hmma_gemm_big<1><<<dim3(HID/128, N_TOK/256), 256, BSMEM_TOT>>>(
        hhi, whi + W_RES_OFF, res_b, HID, HID, uh, nullptr);

    // join gating, then grouped: uh = uh_raw*s1 + (h @ W_e + b_e)*s0
    cudaStreamWaitEvent(0, evG, 0);
    hmma_gemm_grouped_big<<<dim3(HID/128, N_TOK/256, NEXP), 256, BSMEM_TOT>>>(expert_b);

    // out = uh @ dec_W + dec_b : 1-pass 256x128 -> fp32 out
    hmma_gemm_big<2><<<dim3(IN_DIM/128, N_TOK/256), 256, BSMEM_TOT>>>(
        uh, whi + W_DEC_OFF, dec_b, HID, IN_DIM, nullptr, out);
}

// round 14
// speedup vs baseline: 5.9393x; 1.0717x over previous
#include <cuda_runtime.h>
#include <cuda_fp16.h>
#include <cuda.h>
#include <cstdint>
#include <math.h>

#define N_TOK  16384
#define IN_DIM 1024
#define HID    2048
#define NEXP   8

// ---- device scratch (globals: allocation-free) ----
__device__ __align__(128) __half g_xhi[(size_t)N_TOK * IN_DIM];
__device__ __align__(128) __half g_xlo[(size_t)N_TOK * IN_DIM];
__device__ __align__(128) __half g_hhi[(size_t)N_TOK * HID];
__device__ __align__(128) __half g_hlo[(size_t)N_TOK * HID];
__device__ __align__(128) __half g_uh[(size_t)N_TOK * HID];

#define W_ENC_OFF 0
#define W_RES_OFF (2048*1024)
#define W_EXP_OFF (W_RES_OFF + 2048*2048)
#define W_DEC_OFF (W_EXP_OFF + 8*2048*2048)
#define W_TOTAL   (W_DEC_OFF + 1024*2048)
__device__ __align__(128) __half g_Whi[(size_t)W_TOTAL];
__device__ __align__(128) __half g_Wlo[(size_t)IN_DIM * HID];  // enc lo only

__device__ int   g_perm[NEXP * N_TOK];
__device__ int   g_counts[NEXP];
__device__ float g_s0[N_TOK];
__device__ float g_s1[N_TOK];

// ---- enc kernel SMEM: 3 stages x (Ah,Al,Bh,Bl each 16KB) = 192KB ----
#define STG_BYTES 65536
#define OFF_AH 0
#define OFF_AL 16384
#define OFF_BH 32768
#define OFF_BL 49152
#define SMEM_TOT (3 * STG_BYTES + 512)

// ---- small-CTA 1-pass tile (128x128, 128 thr, 2 CTA/SM): 3 x 32KB ----
#define B2STG 32768
#define B2OFF_A 0
#define B2OFF_B 16384
#define B2_RMAP (3 * B2STG)
#define B2SMEM_TOT (3 * B2STG + 640)

// ---- PTX helpers ----
__device__ __forceinline__ uint32_t smem_u32(const void* p) {
    uint32_t r;
    asm("{ .reg .u64 t; cvta.to.shared.u64 t, %1; cvt.u32.u64 %0, t; }" : "=r"(r) : "l"(p));
    return r;
}
__device__ __forceinline__ void cp16(uint32_t s, const void* g) {
    asm volatile("cp.async.cg.shared.global [%0], [%1], 16;" :: "r"(s), "l"(g));
}
#define CP_COMMIT() asm volatile("cp.async.commit_group;" ::: "memory")
#define CP_WAIT(n)  asm volatile("cp.async.wait_group %0;" :: "n"(n) : "memory")

__device__ __forceinline__ void ldsm4(uint32_t* r, uint32_t a) {
    asm volatile("ldmatrix.sync.aligned.m8n8.x4.shared.b16 {%0,%1,%2,%3}, [%4];"
                 : "=r"(r[0]), "=r"(r[1]), "=r"(r[2]), "=r"(r[3]) : "r"(a));
}
__device__ __forceinline__ void mma16816(float* c, const uint32_t* a, const uint32_t* b) {
    asm volatile(
        "mma.sync.aligned.m16n8k16.row.col.f32.f16.f16.f32 "
        "{%0,%1,%2,%3}, {%4,%5,%6,%7}, {%8,%9}, {%0,%1,%2,%3};"
        : "+f"(c[0]), "+f"(c[1]), "+f"(c[2]), "+f"(c[3])
        : "r"(a[0]), "r"(a[1]), "r"(a[2]), "r"(a[3]), "r"(b[0]), "r"(b[1]));
}

// 128B-row XOR swizzle: conflict-free for ldmatrix and coalesced stores
__device__ __forceinline__ uint32_t swz128(int row, int chunk) {
    return (uint32_t)(row * 128 + ((chunk ^ (row & 7)) * 16));
}

__device__ __forceinline__ void splitf(float v, __half& h, __half& l) {
    h = __float2half_rn(v);
    l = __float2half_rn(v - __half2float(h));
}

// ---- small kernels ----
__global__ __launch_bounds__(256) void conv_x_kernel(const float* __restrict__ x) {
    if (blockIdx.x == 0 && threadIdx.x < NEXP) { g_counts[threadIdx.x] = 0; }
    size_t i = ((size_t)blockIdx.x * 256 + threadIdx.x) * 4;
    float4 v = *(const float4*)(x + i);
    __half hb[4], lb[4];
    splitf(v.x, hb[0], lb[0]); splitf(v.y, hb[1], lb[1]);
    splitf(v.z, hb[2], lb[2]); splitf(v.w, hb[3], lb[3]);
    *(uint2*)(g_xhi + i) = *(uint2*)hb;
    *(uint2*)(g_xlo + i) = *(uint2*)lb;
}

// src [K,N] fp32 (batched over z) -> dst [N,K] fp16 hi (+lo), vectorized stores
__global__ __launch_bounds__(256)
void transpose_conv(const float* __restrict__ src, __half* __restrict__ dhi,
                    __half* __restrict__ dlo, int K, int N)
{
    __shared__ float t[32][33];
    const size_t zoff = (size_t)blockIdx.z * K * N;
    const int n0 = blockIdx.x * 32, k0 = blockIdx.y * 32;
    const int tx = threadIdx.x, ty = threadIdx.y;
    #pragma unroll
    for (int i = 0; i < 4; i++) {
        t[ty + i*8][tx] = src[zoff + (size_t)(k0 + ty + i*8) * N + n0 + tx];
    }
    __syncthreads();
    const int tid = ty * 32 + tx;
    const int nl = tid >> 3;
    const int kl = (tid & 7) * 4;
    __half h4[4], l4[4];
    #pragma unroll
    for (int q = 0; q < 4; q++) {
        splitf(t[kl + q][nl], h4[q], l4[q]);
    }
    const size_t di = zoff + (size_t)(n0 + nl) * K + k0 + kl;
    *(uint2*)(dhi + di) = *(uint2*)h4;
    if (dlo) { *(uint2*)(dlo + di) = *(uint2*)l4; }
}

// ---- gating ----
__global__ __launch_bounds__(128)
void gating_kernel(const float* __restrict__ gate_W, const float* __restrict__ coef_W,
                   const float* __restrict__ coef_b)
{
    const int n = blockIdx.x;
    const int t = threadIdx.x;
    float acc[10];
    #pragma unroll
    for (int j = 0; j < 10; j++) { acc[j] = 0.0f; }

    const __half* hh = g_hhi + (size_t)n * HID;
    const __half* hl = g_hlo + (size_t)n * HID;
    for (int k = t; k < HID; k += 128) {
        const float hv = __half2float(hh[k]) + __half2float(hl[k]);
        #pragma unroll
        for (int j = 0; j < 8; j++) { acc[j] += hv * gate_W[k * 8 + j]; }
        acc[8] += hv * coef_W[k * 2 + 0];
        acc[9] += hv * coef_W[k * 2 + 1];
    }
    #pragma unroll
    for (int j = 0; j < 10; j++) {
        #pragma unroll
        for (int o = 16; o > 0; o >>= 1) {
            acc[j] += __shfl_down_sync(0xffffffffu, acc[j], o);
        }
    }

    __shared__ float red[4][10];
    const int warp = t >> 5, lane = t & 31;
    if (lane == 0) {
        #pragma unroll
        for (int j = 0; j < 10; j++) { red[warp][j] = acc[j]; }
    }
    __syncthreads();

    if (t == 0) {
        float v[10];
        #pragma unroll
        for (int j = 0; j < 10; j++) {
            v[j] = red[0][j] + red[1][j] + red[2][j] + red[3][j];
        }
        float lmax = v[0]; int idx = 0;
        #pragma unroll
        for (int j = 1; j < 8; j++) {
            if (v[j] > lmax) { lmax = v[j]; idx = j; }
        }
        float s = 0.0f;
        #pragma unroll
        for (int j = 0; j < 8; j++) { s += expf(v[j] - lmax); }
        const float gate = 1.0f / s;
        const float c0 = v[8] + coef_b[0];
        const float c1 = v[9] + coef_b[1];
        const float cm = fmaxf(c0, c1);
        const float e0 = expf(c0 - cm), e1 = expf(c1 - cm);
        const float inv = 1.0f / (e0 + e1);
        g_s0[n] = gate * e0 * inv;
        g_s1[n] = e1 * inv;
        const int pos = atomicAdd(&g_counts[idx], 1);
        g_perm[idx * N_TOK + pos] = n;
    }
}

// ===========================================================================
// ENC kernel: 128x128, 3-pass split-fp16 (protects gating argmax)
// ===========================================================================
__global__ __launch_bounds__(256, 1)
void hmma_gemm_enc(const __half* __restrict__ Ahi, const __half* __restrict__ Alo,
                   const __half* __restrict__ Bhi, const __half* __restrict__ Blo,
                   const float* __restrict__ bias, int K, int Nn,
                   __half* __restrict__ Chi, __half* __restrict__ Clo)
{
    extern __shared__ __align__(1024) char smem[];
    const uint32_t sb = smem_u32(smem);
    const int tid = threadIdx.x;
    const int lane = tid & 31, wid = tid >> 5;
    const int wm = wid >> 2, wn = wid & 3;           // 2 x 4 warp grid
    const int mrow0 = blockIdx.y * 128;
    const int ncol0 = blockIdx.x * 128;
    const int nt = K / 64;

    int lrow[4], lch[4];
    uint32_t lsw[4];
    #pragma unroll
    for (int i = 0; i < 4; i++) {
        const int slot = tid + 256 * i;
        lrow[i] = slot >> 3;
        lch[i]  = slot & 7;
        lsw[i]  = swz128(lrow[i], lch[i]);
    }

    #define LOADE(s, kt) do {                                                    \
        const uint32_t st_ = sb + (uint32_t)(s) * STG_BYTES;                      \
        _Pragma("unroll")                                                         \
        for (int i_ = 0; i_ < 4; i_++) {                                          \
            const size_t go_ = (size_t)(kt) * 64 + lch[i_] * 8;                   \
            cp16(st_ + OFF_AH + lsw[i_], Ahi + (size_t)(mrow0 + lrow[i_]) * K + go_); \
            cp16(st_ + OFF_AL + lsw[i_], Alo + (size_t)(mrow0 + lrow[i_]) * K + go_); \
            cp16(st_ + OFF_BH + lsw[i_], Bhi + (size_t)(ncol0 + lrow[i_]) * K + go_); \
            cp16(st_ + OFF_BL + lsw[i_], Blo + (size_t)(ncol0 + lrow[i_]) * K + go_); \
        }                                                                         \
        CP_COMMIT();                                                              \
    } while (0)

    LOADE(0, 0);
    LOADE(1, 1);

    float acc[4][4][4];
    #pragma unroll
    for (int i = 0; i < 4; i++) {
        #pragma unroll
        for (int j = 0; j < 4; j++) {
            #pragma unroll
            for (int q = 0; q < 4; q++) { acc[i][j][q] = 0.0f; }
        }
    }

    const int arow = (lane & 7) | (((lane >> 3) & 1) << 3);
    const int ach  = lane >> 4;
    const int brow = (lane & 7) | (((lane >> 4) & 1) << 3);
    const int bch  = (lane >> 3) & 1;

    uint32_t ah[4][4], al[4][4], bh[2][4], bl[2][4];

    for (int kt = 0; kt < nt; kt++) {
        if (kt + 1 < nt) { CP_WAIT(1); } else { CP_WAIT(0); }
        __syncthreads();
        if (kt + 2 < nt) { LOADE((kt + 2) % 3, kt + 2); }

        const uint32_t st = sb + (uint32_t)(kt % 3) * STG_BYTES;
        #pragma unroll
        for (int s16 = 0; s16 < 4; s16++) {
            #pragma unroll
            for (int i = 0; i < 4; i++) {
                const uint32_t a = swz128(wm * 64 + i * 16 + arow, s16 * 2 + ach);
                ldsm4(ah[i], st + OFF_AH + a);
                ldsm4(al[i], st + OFF_AL + a);
            }
            #pragma unroll
            for (int j = 0; j < 2; j++) {
                const uint32_t b = swz128(wn * 32 + j * 16 + brow, s16 * 2 + bch);
                ldsm4(bh[j], st + OFF_BH + b);
                ldsm4(bl[j], st + OFF_BL + b);
            }
            #pragma unroll
            for (int i = 0; i < 4; i++) {
                #pragma unroll
                for (int j = 0; j < 4; j++) {
                    mma16816(acc[i][j], ah[i], &bh[j >> 1][(j & 1) * 2]);
                    mma16816(acc[i][j], ah[i], &bl[j >> 1][(j & 1) * 2]);
                    mma16816(acc[i][j], al[i], &bh[j >> 1][(j & 1) * 2]);
                }
            }
        }
    }

    // epilogue: relu + split -> Chi/Clo
    #pragma unroll
    for (int i = 0; i < 4; i++) {
        const int rb = mrow0 + wm * 64 + i * 16 + (lane >> 2);
        #pragma unroll
        for (int h = 0; h < 2; h++) {
            const int row = rb + h * 8;
            #pragma unroll
            for (int j = 0; j < 4; j++) {
                const int col = ncol0 + wn * 32 + j * 8 + (lane & 3) * 2;
                const float2 b2 = *(const float2*)(bias + col);
                float v0 = fmaxf(acc[i][j][h * 2 + 0] + b2.x, 0.0f);
                float v1 = fmaxf(acc[i][j][h * 2 + 1] + b2.y, 0.0f);
                __half h0, l0, h1, l1;
                splitf(v0, h0, l0); splitf(v1, h1, l1);
                *(__half2*)(Chi + (size_t)row * Nn + col) = __halves2half2(h0, h1);
                *(__half2*)(Clo + (size_t)row * Nn + col) = __halves2half2(l0, l1);
            }
        }
    }
    #undef LOADE
}

// ===========================================================================
// Small-CTA 1-pass GEMM: 128 threads (2x2 warps, 64x64 warp tile),
// tile 128x128, BK=64, 3 stages (96KB) -> 2 CTAs/SM.
// MODE 1: acc+bias -> Ch (fp16, unscaled) ; MODE 2: acc+bias -> Cf (fp32)
// ===========================================================================
#define B2LDFRAG(st, s16) do {                                                    \
    _Pragma("unroll")                                                             \
    for (int i_ = 0; i_ < 4; i_++) {                                               \
        ldsm4(ah[i_], (st) + B2OFF_A + swz128(wm * 64 + i_ * 16 + arow, (s16) * 2 + ach)); \
    }                                                                             \
    _Pragma("unroll")                                                             \
    for (int j_ = 0; j_ < 4; j_++) {                                               \
        ldsm4(bh[j_], (st) + B2OFF_B + swz128(wn * 64 + j_ * 16 + brow, (s16) * 2 + bch)); \
    }                                                                             \
} while (0)

#define B2DOMMA() do {                                                            \
    _Pragma("unroll")                                                             \
    for (int i_ = 0; i_ < 4; i_++) {                                               \
        _Pragma("unroll")                                                         \
        for (int j_ = 0; j_ < 8; j_++) {                                           \
            mma16816(acc[i_][j_], ah[i_], &bh[j_ >> 1][(j_ & 1) * 2]);             \
        }                                                                         \
    }                                                                             \
} while (0)

template <int MODE>
__global__ __launch_bounds__(128, 2)
void hmma_gemm_b2(const __half* __restrict__ A, const __half* __restrict__ B,
                  const float* __restrict__ bias, int K, int Nn,
                  __half* __restrict__ Ch, float* __restrict__ Cf)
{
    extern __shared__ __align__(1024) char smem[];
    const uint32_t sb = smem_u32(smem);
    const int tid = threadIdx.x;
    const int lane = tid & 31, wid = tid >> 5;
    const int wm = wid >> 1, wn = wid & 1;           // 2 x 2 warp grid
    const int mrow0 = blockIdx.y * 128;
    const int ncol0 = blockIdx.x * 128;
    const int nt = K / 64;

    #define B2LOADT(s, kt) do {                                                  \
        const uint32_t st_ = sb + (uint32_t)(s) * B2STG;                          \
        _Pragma("unroll")                                                         \
        for (int i_ = 0; i_ < 8; i_++) {                                          \
            const int slot_ = tid + 128 * i_;                                     \
            const int row_ = slot_ >> 3, ch_ = slot_ & 7;                         \
            const size_t go_ = (size_t)(kt) * 64 + ch_ * 8;                       \
            cp16(st_ + B2OFF_A + swz128(row_, ch_),                               \
                 A + (size_t)(mrow0 + row_) * K + go_);                           \
            cp16(st_ + B2OFF_B + swz128(row_, ch_),                               \
                 B + (size_t)(ncol0 + row_) * K + go_);                           \
        }                                                                         \
        CP_COMMIT();                                                              \
    } while (0)

    B2LOADT(0, 0);
    B2LOADT(1, 1);

    float acc[4][8][4];
    #pragma unroll
    for (int i = 0; i < 4; i++) {
        #pragma unroll
        for (int j = 0; j < 8; j++) {
            #pragma unroll
            for (int q = 0; q < 4; q++) { acc[i][j][q] = 0.0f; }
        }
    }

    const int arow = (lane & 7) | (((lane >> 3) & 1) << 3);
    const int ach  = lane >> 4;
    const int brow = (lane & 7) | (((lane >> 4) & 1) << 3);
    const int bch  = (lane >> 3) & 1;

    uint32_t ah[4][4], bh[4][4];

    for (int kt = 0; kt < nt; kt++) {
        if (kt + 1 < nt) { CP_WAIT(1); } else { CP_WAIT(0); }
        __syncthreads();
        if (kt + 2 < nt) { B2LOADT((kt + 2) % 3, kt + 2); }

        const uint32_t st = sb + (uint32_t)(kt % 3) * B2STG;
        #pragma unroll
        for (int s16 = 0; s16 < 4; s16++) {
            B2LDFRAG(st, s16);
            B2DOMMA();
        }
    }

    // epilogue
    #pragma unroll
    for (int i = 0; i < 4; i++) {
        const int rb = mrow0 + wm * 64 + i * 16 + (lane >> 2);
        #pragma unroll
        for (int h = 0; h < 2; h++) {
            const int row = rb + h * 8;
            #pragma unroll
            for (int j = 0; j < 8; j++) {
                const int col = ncol0 + wn * 64 + j * 8 + (lane & 3) * 2;
                const float2 b2 = *(const float2*)(bias + col);
                float v0 = acc[i][j][h * 2 + 0] + b2.x;
                float v1 = acc[i][j][h * 2 + 1] + b2.y;
                if (MODE == 1) {
                    *(__half2*)(Ch + (size_t)row * Nn + col) =
                        __halves2half2(__float2half_rn(v0), __float2half_rn(v1));
                } else {
                    *(float2*)(Cf + (size_t)row * Nn + col) = make_float2(v0, v1);
                }
            }
        }
    }
    #undef B2LOADT
}

// ===========================================================================
// Grouped expert GEMM (1-pass small-CTA): A rows via g_perm;
// epilogue: g_uh[tok] = fp16(uh_raw[tok]*s1[tok] + (acc + b_e)*s0[tok])
// ===========================================================================
__global__ __launch_bounds__(128, 2)
void hmma_gemm_grouped_b2(const float* __restrict__ bexp)
{
    extern __shared__ __align__(1024) char smem[];
    const int e = blockIdx.z;
    const int cnt = g_counts[e];
    const int rowBase = blockIdx.y * 128;
    if (rowBase >= cnt) return;

    const uint32_t sb = smem_u32(smem);
    const int tid = threadIdx.x;
    const int lane = tid & 31, wid = tid >> 5;
    const int wm = wid >> 1, wn = wid & 1;
    const int ncol0 = blockIdx.x * 128;
    const int nt = HID / 64;
    int* rmap = (int*)(smem + B2_RMAP);

    {
        int i = rowBase + tid;
        if (i > cnt - 1) i = cnt - 1;
        rmap[tid] = g_perm[e * N_TOK + i];
    }
    __syncthreads();

    const __half* B = g_Whi + W_EXP_OFF + (size_t)e * HID * HID;

    size_t ga[8];
    #pragma unroll
    for (int i = 0; i < 8; i++) {
        ga[i] = (size_t)rmap[(tid + 128 * i) >> 3] * HID;
    }

    #define G2LOADT(s, kt) do {                                                  \
        const uint32_t st_ = sb + (uint32_t)(s) * B2STG;                          \
        _Pragma("unroll")                                                         \
        for (int i_ = 0; i_ < 8; i_++) {                                          \
            const int slot_ = tid + 128 * i_;                                     \
            const int row_ = slot_ >> 3, ch_ = slot_ & 7;                         \
            const size_t go_ = (size_t)(kt) * 64 + ch_ * 8;                       \
            cp16(st_ + B2OFF_A + swz128(row_, ch_), g_hhi + ga[i_] + go_);        \
            cp16(st_ + B2OFF_B + swz128(row_, ch_),                               \
                 B + (size_t)(ncol0 + row_) * HID + go_);                         \
        }                                                                         \
        CP_COMMIT();                                                              \
    } while (0)

    G2LOADT(0, 0);
    G2LOADT(1, 1);

    float acc[4][8][4];
    #pragma unroll
    for (int i = 0; i < 4; i++) {
        #pragma unroll
        for (int j = 0; j < 8; j++) {
            #pragma unroll
            for (int q = 0; q < 4; q++) { acc[i][j][q] = 0.0f; }
        }
    }

    const int arow = (lane & 7) | (((lane >> 3) & 1) << 3);
    const int ach  = lane >> 4;
    const int brow = (lane & 7) | (((lane >> 4) & 1) << 3);
    const int bch  = (lane >> 3) & 1;

    uint32_t ah[4][4], bh[4][4];

    for (int kt = 0; kt < nt; kt++) {
        if (kt + 1 < nt) { CP_WAIT(1); } else { CP_WAIT(0); }
        __syncthreads();
        if (kt + 2 < nt) { G2LOADT((kt + 2) % 3, kt + 2); }

        const uint32_t st = sb + (uint32_t)(kt % 3) * B2STG;
        #pragma unroll
        for (int s16 = 0; s16 < 4; s16++) {
            B2LDFRAG(st, s16);
            B2DOMMA();
        }
    }

    #pragma unroll
    for (int i = 0; i < 4; i++) {
        const int lb = wm * 64 + i * 16 + (lane >> 2);
        #pragma unroll
        for (int h = 0; h < 2; h++) {
            const int li = lb + h * 8;
            if (rowBase + li >= cnt) continue;
            const int tok = rmap[li];
            const float s0 = g_s0[tok];
            const float s1 = g_s1[tok];
            #pragma unroll
            for (int j = 0; j < 8; j++) {
                const int col = ncol0 + wn * 64 + j * 8 + (lane & 3) * 2;
                const float2 b2 = *(const float2*)(bexp + e * HID + col);
                float2 u2 = __half22float2(*(const __half2*)(g_uh + (size_t)tok * HID + col));
                float v0 = u2.x * s1 + (acc[i][j][h * 2 + 0] + b2.x) * s0;
                float v1 = u2.y * s1 + (acc[i][j][h * 2 + 1] + b2.y) * s0;
                *(__half2*)(g_uh + (size_t)tok * HID + col) =
                    __halves2half2(__float2half_rn(v0), __float2half_rn(v1));
            }
        }
    }
    #undef G2LOADT
}

// ---------------------------------------------------------------------------
extern "C" void kernel_launch(void* const* d_in, const int* in_sizes, int n_in,
                              void* d_out, int out_size)
{
    const float* x        = (const float*)d_in[0];
    const float* enc_W    = (const float*)d_in[1];
    const float* enc_b    = (const float*)d_in[2];
    const float* gate_W   = (const float*)d_in[3];
    const float* expert_W = (const float*)d_in[4];
    const float* expert_b = (const float*)d_in[5];
    const float* res_W    = (const float*)d_in[6];
    const float* res_b    = (const float*)d_in[7];
    const float* coef_W   = (const float*)d_in[8];
    const float* coef_b   = (const float*)d_in[9];
    const float* dec_W    = (const float*)d_in[10];
    const float* dec_b    = (const float*)d_in[11];
    float* out = (float*)d_out;

    __half *xhi, *xlo, *hhi, *hlo, *uh, *whi, *wlo;
    cudaGetSymbolAddress((void**)&xhi, g_xhi);
    cudaGetSymbolAddress((void**)&xlo, g_xlo);
    cudaGetSymbolAddress((void**)&hhi, g_hhi);
    cudaGetSymbolAddress((void**)&hlo, g_hlo);
    cudaGetSymbolAddress((void**)&uh,  g_uh);
    cudaGetSymbolAddress((void**)&whi, g_Whi);
    cudaGetSymbolAddress((void**)&wlo, g_Wlo);

    cudaFuncSetAttribute((const void*)hmma_gemm_enc,        cudaFuncAttributeMaxDynamicSharedMemorySize, SMEM_TOT);
    cudaFuncSetAttribute((const void*)hmma_gemm_b2<1>,      cudaFuncAttributeMaxDynamicSharedMemorySize, B2SMEM_TOT);
    cudaFuncSetAttribute((const void*)hmma_gemm_b2<2>,      cudaFuncAttributeMaxDynamicSharedMemorySize, B2SMEM_TOT);
    cudaFuncSetAttribute((const void*)hmma_gemm_grouped_b2, cudaFuncAttributeMaxDynamicSharedMemorySize, B2SMEM_TOT);

    // side stream + events (lazy init; host-side only)
    static cudaStream_t s2 = nullptr;
    static cudaEvent_t evF = nullptr, evJ = nullptr, evE = nullptr, evG = nullptr, evT = nullptr;
    if (!s2) {
        cudaStreamCreateWithFlags(&s2, cudaStreamNonBlocking);
        cudaEventCreateWithFlags(&evF, cudaEventDisableTiming);
        cudaEventCreateWithFlags(&evJ, cudaEventDisableTiming);
        cudaEventCreateWithFlags(&evE, cudaEventDisableTiming);
        cudaEventCreateWithFlags(&evG, cudaEventDisableTiming);
        cudaEventCreateWithFlags(&evT, cudaEventDisableTiming);
    }

    // launch 1: conv_x (main) — also zeroes g_counts
    conv_x_kernel<<<(N_TOK * IN_DIM) / 1024, 256>>>(x);

    // fork side stream: enc transpose (launch 2) + res transpose (launch 3)
    cudaEventRecord(evF, 0);
    cudaStreamWaitEvent(s2, evF, 0);
    transpose_conv<<<dim3(HID/32, IN_DIM/32, 1), dim3(32, 8), 0, s2>>>(enc_W, whi + W_ENC_OFF, wlo, IN_DIM, HID);
    cudaEventRecord(evT, s2);
    transpose_conv<<<dim3(HID/32, HID/32, 1),    dim3(32, 8), 0, s2>>>(res_W, whi + W_RES_OFF, nullptr, HID, HID);

    // launch 4 (profiled): enc GEMM — waits for enc transpose
    cudaStreamWaitEvent(0, evT, 0);
    hmma_gemm_enc<<<dim3(HID/128, N_TOK/128), 256, SMEM_TOT>>>(
        xhi, xlo, whi + W_ENC_OFF, wlo,
        enc_b, IN_DIM, HID, hhi, hlo);
    cudaEventRecord(evE, 0);

    // remaining weight transposes on side stream (overlap enc execution)
    transpose_conv<<<dim3(HID/32, HID/32, NEXP), dim3(32, 8), 0, s2>>>(expert_W, whi + W_EXP_OFF, nullptr, HID, HID);
    transpose_conv<<<dim3(IN_DIM/32, HID/32, 1), dim3(32, 8), 0, s2>>>(dec_W,    whi + W_DEC_OFF, nullptr, HID, IN_DIM);
    cudaEventRecord(evJ, s2);

    // gating on side stream, concurrent with res GEMM
    cudaStreamWaitEvent(s2, evE, 0);
    gating_kernel<<<N_TOK, 128, 0, s2>>>(gate_W, coef_W, coef_b);
    cudaEventRecord(evG, s2);

    // join weight transposes, then res (unscaled) on main stream
    cudaStreamWaitEvent(0, evJ, 0);

    // uh_raw = h @ res_W + res_b : 1-pass 128x128 (2 CTA/SM) -> fp16
    hmma_gemm_b2<1><<<dim3(HID/128, N_TOK/128), 128, B2SMEM_TOT>>>(
        hhi, whi + W_RES_OFF, res_b, HID, HID, uh, nullptr);

    // join gating, then grouped: uh = uh_raw*s1 + (h @ W_e + b_e)*s0
    cudaStreamWaitEvent(0, evG, 0);
    hmma_gemm_grouped_b2<<<dim3(HID/128, N_TOK/128, NEXP), 128, B2SMEM_TOT>>>(expert_b);

    // out = uh @ dec_W + dec_b : 1-pass 128x128 (2 CTA/SM) -> fp32
    hmma_gemm_b2<2><<<dim3(IN_DIM/128, N_TOK/128), 128, B2SMEM_TOT>>>(
        uh, whi + W_DEC_OFF, dec_b, HID, IN_DIM, nullptr, out);
}

// round 15
// speedup vs baseline: 6.1672x; 1.0384x over previous
#include <cuda_runtime.h>
#include <cuda_fp16.h>
#include <cuda.h>
#include <cstdint>
#include <math.h>

#define N_TOK  16384
#define IN_DIM 1024
#define HID    2048
#define NEXP   8

// ---- device scratch (globals: allocation-free) ----
__device__ __align__(128) __half g_xhi[(size_t)N_TOK * IN_DIM];
__device__ __align__(128) __half g_xlo[(size_t)N_TOK * IN_DIM];
__device__ __align__(128) __half g_hhi[(size_t)N_TOK * HID];
__device__ __align__(128) __half g_hlo[(size_t)N_TOK * HID];
__device__ __align__(128) __half g_uh[(size_t)N_TOK * HID];

#define W_ENC_OFF 0
#define W_RES_OFF (2048*1024)
#define W_EXP_OFF (W_RES_OFF + 2048*2048)
#define W_DEC_OFF (W_EXP_OFF + 8*2048*2048)
#define W_TOTAL   (W_DEC_OFF + 1024*2048)
__device__ __align__(128) __half g_Whi[(size_t)W_TOTAL];
__device__ __align__(128) __half g_Wlo[(size_t)IN_DIM * HID];  // enc lo only

__device__ int   g_perm[NEXP * N_TOK];
__device__ int   g_counts[NEXP];
__device__ float g_s0[N_TOK];
__device__ float g_s1[N_TOK];

// ---- enc small-CTA SMEM: 3 stages x (Ah,Al,Bh,Bl each 8KB: 128r x 64B) = 96KB
#define ESTG 32768
#define EOFF_AH 0
#define EOFF_AL 8192
#define EOFF_BH 16384
#define EOFF_BL 24576
#define ESMEM_TOT (3 * ESTG + 128)

// ---- small-CTA 1-pass tile (128x128, 128 thr, 2 CTA/SM): 3 x 32KB ----
#define B2STG 32768
#define B2OFF_A 0
#define B2OFF_B 16384
#define B2_RMAP (3 * B2STG)
#define B2SMEM_TOT (3 * B2STG + 640)

// ---- PTX helpers ----
__device__ __forceinline__ uint32_t smem_u32(const void* p) {
    uint32_t r;
    asm("{ .reg .u64 t; cvta.to.shared.u64 t, %1; cvt.u32.u64 %0, t; }" : "=r"(r) : "l"(p));
    return r;
}
__device__ __forceinline__ void cp16(uint32_t s, const void* g) {
    asm volatile("cp.async.cg.shared.global [%0], [%1], 16;" :: "r"(s), "l"(g));
}
#define CP_COMMIT() asm volatile("cp.async.commit_group;" ::: "memory")
#define CP_WAIT(n)  asm volatile("cp.async.wait_group %0;" :: "n"(n) : "memory")

__device__ __forceinline__ void ldsm4(uint32_t* r, uint32_t a) {
    asm volatile("ldmatrix.sync.aligned.m8n8.x4.shared.b16 {%0,%1,%2,%3}, [%4];"
                 : "=r"(r[0]), "=r"(r[1]), "=r"(r[2]), "=r"(r[3]) : "r"(a));
}
__device__ __forceinline__ void mma16816(float* c, const uint32_t* a, const uint32_t* b) {
    asm volatile(
        "mma.sync.aligned.m16n8k16.row.col.f32.f16.f16.f32 "
        "{%0,%1,%2,%3}, {%4,%5,%6,%7}, {%8,%9}, {%0,%1,%2,%3};"
        : "+f"(c[0]), "+f"(c[1]), "+f"(c[2]), "+f"(c[3])
        : "r"(a[0]), "r"(a[1]), "r"(a[2]), "r"(a[3]), "r"(b[0]), "r"(b[1]));
}

// 128B-row XOR swizzle (BK=64 paths)
__device__ __forceinline__ uint32_t swz128(int row, int chunk) {
    return (uint32_t)(row * 128 + ((chunk ^ (row & 7)) * 16));
}
// 64B-row XOR swizzle (BK=32 enc path; proven in rounds 5-8)
__device__ __forceinline__ uint32_t swz64(int row, int chunk) {
    return (uint32_t)(row * 64 + ((chunk ^ ((row >> 1) & 3)) * 16));
}

__device__ __forceinline__ void splitf(float v, __half& h, __half& l) {
    h = __float2half_rn(v);
    l = __float2half_rn(v - __half2float(h));
}

// ---- small kernels ----
__global__ __launch_bounds__(256) void conv_x_kernel(const float* __restrict__ x) {
    if (blockIdx.x == 0 && threadIdx.x < NEXP) { g_counts[threadIdx.x] = 0; }
    size_t i = ((size_t)blockIdx.x * 256 + threadIdx.x) * 4;
    float4 v = *(const float4*)(x + i);
    __half hb[4], lb[4];
    splitf(v.x, hb[0], lb[0]); splitf(v.y, hb[1], lb[1]);
    splitf(v.z, hb[2], lb[2]); splitf(v.w, hb[3], lb[3]);
    *(uint2*)(g_xhi + i) = *(uint2*)hb;
    *(uint2*)(g_xlo + i) = *(uint2*)lb;
}

// src [K,N] fp32 (batched over z) -> dst [N,K] fp16 hi (+lo), vectorized stores
__global__ __launch_bounds__(256)
void transpose_conv(const float* __restrict__ src, __half* __restrict__ dhi,
                    __half* __restrict__ dlo, int K, int N)
{
    __shared__ float t[32][33];
    const size_t zoff = (size_t)blockIdx.z * K * N;
    const int n0 = blockIdx.x * 32, k0 = blockIdx.y * 32;
    const int tx = threadIdx.x, ty = threadIdx.y;
    #pragma unroll
    for (int i = 0; i < 4; i++) {
        t[ty + i*8][tx] = src[zoff + (size_t)(k0 + ty + i*8) * N + n0 + tx];
    }
    __syncthreads();
    const int tid = ty * 32 + tx;
    const int nl = tid >> 3;
    const int kl = (tid & 7) * 4;
    __half h4[4], l4[4];
    #pragma unroll
    for (int q = 0; q < 4; q++) {
        splitf(t[kl + q][nl], h4[q], l4[q]);
    }
    const size_t di = zoff + (size_t)(n0 + nl) * K + k0 + kl;
    *(uint2*)(dhi + di) = *(uint2*)h4;
    if (dlo) { *(uint2*)(dlo + di) = *(uint2*)l4; }
}

// ---- gating ----
__global__ __launch_bounds__(128)
void gating_kernel(const float* __restrict__ gate_W, const float* __restrict__ coef_W,
                   const float* __restrict__ coef_b)
{
    const int n = blockIdx.x;
    const int t = threadIdx.x;
    float acc[10];
    #pragma unroll
    for (int j = 0; j < 10; j++) { acc[j] = 0.0f; }

    const __half* hh = g_hhi + (size_t)n * HID;
    const __half* hl = g_hlo + (size_t)n * HID;
    for (int k = t; k < HID; k += 128) {
        const float hv = __half2float(hh[k]) + __half2float(hl[k]);
        #pragma unroll
        for (int j = 0; j < 8; j++) { acc[j] += hv * gate_W[k * 8 + j]; }
        acc[8] += hv * coef_W[k * 2 + 0];
        acc[9] += hv * coef_W[k * 2 + 1];
    }
    #pragma unroll
    for (int j = 0; j < 10; j++) {
        #pragma unroll
        for (int o = 16; o > 0; o >>= 1) {
            acc[j] += __shfl_down_sync(0xffffffffu, acc[j], o);
        }
    }

    __shared__ float red[4][10];
    const int warp = t >> 5, lane = t & 31;
    if (lane == 0) {
        #pragma unroll
        for (int j = 0; j < 10; j++) { red[warp][j] = acc[j]; }
    }
    __syncthreads();

    if (t == 0) {
        float v[10];
        #pragma unroll
        for (int j = 0; j < 10; j++) {
            v[j] = red[0][j] + red[1][j] + red[2][j] + red[3][j];
        }
        float lmax = v[0]; int idx = 0;
        #pragma unroll
        for (int j = 1; j < 8; j++) {
            if (v[j] > lmax) { lmax = v[j]; idx = j; }
        }
        float s = 0.0f;
        #pragma unroll
        for (int j = 0; j < 8; j++) { s += expf(v[j] - lmax); }
        const float gate = 1.0f / s;
        const float c0 = v[8] + coef_b[0];
        const float c1 = v[9] + coef_b[1];
        const float cm = fmaxf(c0, c1);
        const float e0 = expf(c0 - cm), e1 = expf(c1 - cm);
        const float inv = 1.0f / (e0 + e1);
        g_s0[n] = gate * e0 * inv;
        g_s1[n] = e1 * inv;
        const int pos = atomicAdd(&g_counts[idx], 1);
        g_perm[idx * N_TOK + pos] = n;
    }
}

// ===========================================================================
// ENC kernel (small-CTA): 128 threads (2x2 warps, 64x64 warp tile),
// tile 128x128, BK=32 (64B-row swizzle), 3 stages (96KB) -> 2 CTAs/SM.
// 3-pass split-fp16: Ah*Bh + Ah*Bl + Al*Bh (protects gating argmax).
// ===========================================================================
__global__ __launch_bounds__(128, 2)
void hmma_gemm_enc2(const __half* __restrict__ Ahi, const __half* __restrict__ Alo,
                    const __half* __restrict__ Bhi, const __half* __restrict__ Blo,
                    const float* __restrict__ bias, int K, int Nn,
                    __half* __restrict__ Chi, __half* __restrict__ Clo)
{
    extern __shared__ __align__(1024) char smem[];
    const uint32_t sb = smem_u32(smem);
    const int tid = threadIdx.x;
    const int lane = tid & 31, wid = tid >> 5;
    const int wm = wid >> 1, wn = wid & 1;           // 2 x 2 warp grid
    const int mrow0 = blockIdx.y * 128;
    const int ncol0 = blockIdx.x * 128;
    const int nt = K / 32;

    // 4 load slots per array per thread: slot = tid + 128*i, row = slot>>2, ch = slot&3
    #define ELOADT(s, kt) do {                                                   \
        const uint32_t st_ = sb + (uint32_t)(s) * ESTG;                           \
        _Pragma("unroll")                                                         \
        for (int i_ = 0; i_ < 4; i_++) {                                          \
            const int slot_ = tid + 128 * i_;                                     \
            const int row_ = slot_ >> 2, ch_ = slot_ & 3;                         \
            const uint32_t sw_ = swz64(row_, ch_);                                \
            const size_t go_ = (size_t)(kt) * 32 + ch_ * 8;                       \
            cp16(st_ + EOFF_AH + sw_, Ahi + (size_t)(mrow0 + row_) * K + go_);    \
            cp16(st_ + EOFF_AL + sw_, Alo + (size_t)(mrow0 + row_) * K + go_);    \
            cp16(st_ + EOFF_BH + sw_, Bhi + (size_t)(ncol0 + row_) * K + go_);    \
            cp16(st_ + EOFF_BL + sw_, Blo + (size_t)(ncol0 + row_) * K + go_);    \
        }                                                                         \
        CP_COMMIT();                                                              \
    } while (0)

    ELOADT(0, 0);
    ELOADT(1, 1);

    float acc[4][8][4];
    #pragma unroll
    for (int i = 0; i < 4; i++) {
        #pragma unroll
        for (int j = 0; j < 8; j++) {
            #pragma unroll
            for (int q = 0; q < 4; q++) { acc[i][j][q] = 0.0f; }
        }
    }

    const int arow = (lane & 7) | (((lane >> 3) & 1) << 3);
    const int ach  = lane >> 4;
    const int brow = (lane & 7) | (((lane >> 4) & 1) << 3);
    const int bch  = (lane >> 3) & 1;

    uint32_t ah[4][4], al[4][4], bh[4][4], bl[4][4];

    for (int kt = 0; kt < nt; kt++) {
        if (kt + 1 < nt) { CP_WAIT(1); } else { CP_WAIT(0); }
        __syncthreads();
        if (kt + 2 < nt) { ELOADT((kt + 2) % 3, kt + 2); }

        const uint32_t st = sb + (uint32_t)(kt % 3) * ESTG;
        #pragma unroll
        for (int s16 = 0; s16 < 2; s16++) {
            #pragma unroll
            for (int i = 0; i < 4; i++) {
                const uint32_t a = swz64(wm * 64 + i * 16 + arow, s16 * 2 + ach);
                ldsm4(ah[i], st + EOFF_AH + a);
                ldsm4(al[i], st + EOFF_AL + a);
            }
            #pragma unroll
            for (int j = 0; j < 4; j++) {
                const uint32_t b = swz64(wn * 64 + j * 16 + brow, s16 * 2 + bch);
                ldsm4(bh[j], st + EOFF_BH + b);
                ldsm4(bl[j], st + EOFF_BL + b);
            }
            #pragma unroll
            for (int i = 0; i < 4; i++) {
                #pragma unroll
                for (int j = 0; j < 8; j++) {
                    mma16816(acc[i][j], ah[i], &bh[j >> 1][(j & 1) * 2]);
                    mma16816(acc[i][j], ah[i], &bl[j >> 1][(j & 1) * 2]);
                    mma16816(acc[i][j], al[i], &bh[j >> 1][(j & 1) * 2]);
                }
            }
        }
    }

    // epilogue: relu + split -> Chi/Clo
    #pragma unroll
    for (int i = 0; i < 4; i++) {
        const int rb = mrow0 + wm * 64 + i * 16 + (lane >> 2);
        #pragma unroll
        for (int h = 0; h < 2; h++) {
            const int row = rb + h * 8;
            #pragma unroll
            for (int j = 0; j < 8; j++) {
                const int col = ncol0 + wn * 64 + j * 8 + (lane & 3) * 2;
                const float2 b2 = *(const float2*)(bias + col);
                float v0 = fmaxf(acc[i][j][h * 2 + 0] + b2.x, 0.0f);
                float v1 = fmaxf(acc[i][j][h * 2 + 1] + b2.y, 0.0f);
                __half h0, l0, h1, l1;
                splitf(v0, h0, l0); splitf(v1, h1, l1);
                *(__half2*)(Chi + (size_t)row * Nn + col) = __halves2half2(h0, h1);
                *(__half2*)(Clo + (size_t)row * Nn + col) = __halves2half2(l0, l1);
            }
        }
    }
    #undef ELOADT
}

// ===========================================================================
// Small-CTA 1-pass GEMM: 128 threads (2x2 warps, 64x64 warp tile),
// tile 128x128, BK=64, 3 stages (96KB) -> 2 CTAs/SM.
// MODE 1: acc+bias -> Ch (fp16, unscaled) ; MODE 2: acc+bias -> Cf (fp32)
// ===========================================================================
#define B2LDFRAG(st, s16) do {                                                    \
    _Pragma("unroll")                                                             \
    for (int i_ = 0; i_ < 4; i_++) {                                               \
        ldsm4(ah[i_], (st) + B2OFF_A + swz128(wm * 64 + i_ * 16 + arow, (s16) * 2 + ach)); \
    }                                                                             \
    _Pragma("unroll")                                                             \
    for (int j_ = 0; j_ < 4; j_++) {                                               \
        ldsm4(bh[j_], (st) + B2OFF_B + swz128(wn * 64 + j_ * 16 + brow, (s16) * 2 + bch)); \
    }                                                                             \
} while (0)

#define B2DOMMA() do {                                                            \
    _Pragma("unroll")                                                             \
    for (int i_ = 0; i_ < 4; i_++) {                                               \
        _Pragma("unroll")                                                         \
        for (int j_ = 0; j_ < 8; j_++) {                                           \
            mma16816(acc[i_][j_], ah[i_], &bh[j_ >> 1][(j_ & 1) * 2]);             \
        }                                                                         \
    }                                                                             \
} while (0)

template <int MODE>
__global__ __launch_bounds__(128, 2)
void hmma_gemm_b2(const __half* __restrict__ A, const __half* __restrict__ B,
                  const float* __restrict__ bias, int K, int Nn,
                  __half* __restrict__ Ch, float* __restrict__ Cf)
{
    extern __shared__ __align__(1024) char smem[];
    const uint32_t sb = smem_u32(smem);
    const int tid = threadIdx.x;
    const int lane = tid & 31, wid = tid >> 5;
    const int wm = wid >> 1, wn = wid & 1;           // 2 x 2 warp grid
    const int mrow0 = blockIdx.y * 128;
    const int ncol0 = blockIdx.x * 128;
    const int nt = K / 64;

    #define B2LOADT(s, kt) do {                                                  \
        const uint32_t st_ = sb + (uint32_t)(s) * B2STG;                          \
        _Pragma("unroll")                                                         \
        for (int i_ = 0; i_ < 8; i_++) {                                          \
            const int slot_ = tid + 128 * i_;                                     \
            const int row_ = slot_ >> 3, ch_ = slot_ & 7;                         \
            const size_t go_ = (size_t)(kt) * 64 + ch_ * 8;                       \
            cp16(st_ + B2OFF_A + swz128(row_, ch_),                               \
                 A + (size_t)(mrow0 + row_) * K + go_);                           \
            cp16(st_ + B2OFF_B + swz128(row_, ch_),                               \
                 B + (size_t)(ncol0 + row_) * K + go_);                           \
        }                                                                         \
        CP_COMMIT();                                                              \
    } while (0)

    B2LOADT(0, 0);
    B2LOADT(1, 1);

    float acc[4][8][4];
    #pragma unroll
    for (int i = 0; i < 4; i++) {
        #pragma unroll
        for (int j = 0; j < 8; j++) {
            #pragma unroll
            for (int q = 0; q < 4; q++) { acc[i][j][q] = 0.0f; }
        }
    }

    const int arow = (lane & 7) | (((lane >> 3) & 1) << 3);
    const int ach  = lane >> 4;
    const int brow = (lane & 7) | (((lane >> 4) & 1) << 3);
    const int bch  = (lane >> 3) & 1;

    uint32_t ah[4][4], bh[4][4];

    for (int kt = 0; kt < nt; kt++) {
        if (kt + 1 < nt) { CP_WAIT(1); } else { CP_WAIT(0); }
        __syncthreads();
        if (kt + 2 < nt) { B2LOADT((kt + 2) % 3, kt + 2); }

        const uint32_t st = sb + (uint32_t)(kt % 3) * B2STG;
        #pragma unroll
        for (int s16 = 0; s16 < 4; s16++) {
            B2LDFRAG(st, s16);
            B2DOMMA();
        }
    }

    // epilogue
    #pragma unroll
    for (int i = 0; i < 4; i++) {
        const int rb = mrow0 + wm * 64 + i * 16 + (lane >> 2);
        #pragma unroll
        for (int h = 0; h < 2; h++) {
            const int row = rb + h * 8;
            #pragma unroll
            for (int j = 0; j < 8; j++) {
                const int col = ncol0 + wn * 64 + j * 8 + (lane & 3) * 2;
                const float2 b2 = *(const float2*)(bias + col);
                float v0 = acc[i][j][h * 2 + 0] + b2.x;
                float v1 = acc[i][j][h * 2 + 1] + b2.y;
                if (MODE == 1) {
                    *(__half2*)(Ch + (size_t)row * Nn + col) =
                        __halves2half2(__float2half_rn(v0), __float2half_rn(v1));
                } else {
                    *(float2*)(Cf + (size_t)row * Nn + col) = make_float2(v0, v1);
                }
            }
        }
    }
    #undef B2LOADT
}

// ===========================================================================
// Grouped expert GEMM (1-pass small-CTA): A rows via g_perm;
// epilogue: g_uh[tok] = fp16(uh_raw[tok]*s1[tok] + (acc + b_e)*s0[tok])
// ===========================================================================
__global__ __launch_bounds__(128, 2)
void hmma_gemm_grouped_b2(const float* __restrict__ bexp)
{
    extern __shared__ __align__(1024) char smem[];
    const int e = blockIdx.z;
    const int cnt = g_counts[e];
    const int rowBase = blockIdx.y * 128;
    if (rowBase >= cnt) return;

    const uint32_t sb = smem_u32(smem);
    const int tid = threadIdx.x;
    const int lane = tid & 31, wid = tid >> 5;
    const int wm = wid >> 1, wn = wid & 1;
    const int ncol0 = blockIdx.x * 128;
    const int nt = HID / 64;
    int* rmap = (int*)(smem + B2_RMAP);

    {
        int i = rowBase + tid;
        if (i > cnt - 1) i = cnt - 1;
        rmap[tid] = g_perm[e * N_TOK + i];
    }
    __syncthreads();

    const __half* B = g_Whi + W_EXP_OFF + (size_t)e * HID * HID;

    size_t ga[8];
    #pragma unroll
    for (int i = 0; i < 8; i++) {
        ga[i] = (size_t)rmap[(tid + 128 * i) >> 3] * HID;
    }

    #define G2LOADT(s, kt) do {                                                  \
        const uint32_t st_ = sb + (uint32_t)(s) * B2STG;                          \
        _Pragma("unroll")                                                         \
        for (int i_ = 0; i_ < 8; i_++) {                                          \
            const int slot_ = tid + 128 * i_;                                     \
            const int row_ = slot_ >> 3, ch_ = slot_ & 7;                         \
            const size_t go_ = (size_t)(kt) * 64 + ch_ * 8;                       \
            cp16(st_ + B2OFF_A + swz128(row_, ch_), g_hhi + ga[i_] + go_);        \
            cp16(st_ + B2OFF_B + swz128(row_, ch_),                               \
                 B + (size_t)(ncol0 + row_) * HID + go_);                         \
        }                                                                         \
        CP_COMMIT();                                                              \
    } while (0)

    G2LOADT(0, 0);
    G2LOADT(1, 1);

    float acc[4][8][4];
    #pragma unroll
    for (int i = 0; i < 4; i++) {
        #pragma unroll
        for (int j = 0; j < 8; j++) {
            #pragma unroll
            for (int q = 0; q < 4; q++) { acc[i][j][q] = 0.0f; }
        }
    }

    const int arow = (lane & 7) | (((lane >> 3) & 1) << 3);
    const int ach  = lane >> 4;
    const int brow = (lane & 7) | (((lane >> 4) & 1) << 3);
    const int bch  = (lane >> 3) & 1;

    uint32_t ah[4][4], bh[4][4];

    for (int kt = 0; kt < nt; kt++) {
        if (kt + 1 < nt) { CP_WAIT(1); } else { CP_WAIT(0); }
        __syncthreads();
        if (kt + 2 < nt) { G2LOADT((kt + 2) % 3, kt + 2); }

        const uint32_t st = sb + (uint32_t)(kt % 3) * B2STG;
        #pragma unroll
        for (int s16 = 0; s16 < 4; s16++) {
            B2LDFRAG(st, s16);
            B2DOMMA();
        }
    }

    #pragma unroll
    for (int i = 0; i < 4; i++) {
        const int lb = wm * 64 + i * 16 + (lane >> 2);
        #pragma unroll
        for (int h = 0; h < 2; h++) {
            const int li = lb + h * 8;
            if (rowBase + li >= cnt) continue;
            const int tok = rmap[li];
            const float s0 = g_s0[tok];
            const float s1 = g_s1[tok];
            #pragma unroll
            for (int j = 0; j < 8; j++) {
                const int col = ncol0 + wn * 64 + j * 8 + (lane & 3) * 2;
                const float2 b2 = *(const float2*)(bexp + e * HID + col);
                float2 u2 = __half22float2(*(const __half2*)(g_uh + (size_t)tok * HID + col));
                float v0 = u2.x * s1 + (acc[i][j][h * 2 + 0] + b2.x) * s0;
                float v1 = u2.y * s1 + (acc[i][j][h * 2 + 1] + b2.y) * s0;
                *(__half2*)(g_uh + (size_t)tok * HID + col) =
                    __halves2half2(__float2half_rn(v0), __float2half_rn(v1));
            }
        }
    }
    #undef G2LOADT
}

// ---------------------------------------------------------------------------
extern "C" void kernel_launch(void* const* d_in, const int* in_sizes, int n_in,
                              void* d_out, int out_size)
{
    const float* x        = (const float*)d_in[0];
    const float* enc_W    = (const float*)d_in[1];
    const float* enc_b    = (const float*)d_in[2];
    const float* gate_W   = (const float*)d_in[3];
    const float* expert_W = (const float*)d_in[4];
    const float* expert_b = (const float*)d_in[5];
    const float* res_W    = (const float*)d_in[6];
    const float* res_b    = (const float*)d_in[7];
    const float* coef_W   = (const float*)d_in[8];
    const float* coef_b   = (const float*)d_in[9];
    const float* dec_W    = (const float*)d_in[10];
    const float* dec_b    = (const float*)d_in[11];
    float* out = (float*)d_out;

    __half *xhi, *xlo, *hhi, *hlo, *uh, *whi, *wlo;
    cudaGetSymbolAddress((void**)&xhi, g_xhi);
    cudaGetSymbolAddress((void**)&xlo, g_xlo);
    cudaGetSymbolAddress((void**)&hhi, g_hhi);
    cudaGetSymbolAddress((void**)&hlo, g_hlo);
    cudaGetSymbolAddress((void**)&uh,  g_uh);
    cudaGetSymbolAddress((void**)&whi, g_Whi);
    cudaGetSymbolAddress((void**)&wlo, g_Wlo);

    cudaFuncSetAttribute((const void*)hmma_gemm_enc2,       cudaFuncAttributeMaxDynamicSharedMemorySize, ESMEM_TOT);
    cudaFuncSetAttribute((const void*)hmma_gemm_b2<1>,      cudaFuncAttributeMaxDynamicSharedMemorySize, B2SMEM_TOT);
    cudaFuncSetAttribute((const void*)hmma_gemm_b2<2>,      cudaFuncAttributeMaxDynamicSharedMemorySize, B2SMEM_TOT);
    cudaFuncSetAttribute((const void*)hmma_gemm_grouped_b2, cudaFuncAttributeMaxDynamicSharedMemorySize, B2SMEM_TOT);

    // side stream + events (lazy init; host-side only)
    static cudaStream_t s2 = nullptr;
    static cudaEvent_t evF = nullptr, evJ = nullptr, evE = nullptr, evG = nullptr, evT = nullptr;
    if (!s2) {
        cudaStreamCreateWithFlags(&s2, cudaStreamNonBlocking);
        cudaEventCreateWithFlags(&evF, cudaEventDisableTiming);
        cudaEventCreateWithFlags(&evJ, cudaEventDisableTiming);
        cudaEventCreateWithFlags(&evE, cudaEventDisableTiming);
        cudaEventCreateWithFlags(&evG, cudaEventDisableTiming);
        cudaEventCreateWithFlags(&evT, cudaEventDisableTiming);
    }

    // launch 1: conv_x (main) — also zeroes g_counts
    conv_x_kernel<<<(N_TOK * IN_DIM) / 1024, 256>>>(x);

    // fork side stream: enc transpose + res transpose
    cudaEventRecord(evF, 0);
    cudaStreamWaitEvent(s2, evF, 0);
    transpose_conv<<<dim3(HID/32, IN_DIM/32, 1), dim3(32, 8), 0, s2>>>(enc_W, whi + W_ENC_OFF, wlo, IN_DIM, HID);
    cudaEventRecord(evT, s2);
    transpose_conv<<<dim3(HID/32, HID/32, 1),    dim3(32, 8), 0, s2>>>(res_W, whi + W_RES_OFF, nullptr, HID, HID);

    // launch 4 (profiled): enc GEMM (2 CTA/SM) — waits for enc transpose
    cudaStreamWaitEvent(0, evT, 0);
    hmma_gemm_enc2<<<dim3(HID/128, N_TOK/128), 128, ESMEM_TOT>>>(
        xhi, xlo, whi + W_ENC_OFF, wlo,
        enc_b, IN_DIM, HID, hhi, hlo);
    cudaEventRecord(evE, 0);

    // remaining weight transposes on side stream (overlap enc execution)
    transpose_conv<<<dim3(HID/32, HID/32, NEXP), dim3(32, 8), 0, s2>>>(expert_W, whi + W_EXP_OFF, nullptr, HID, HID);
    transpose_conv<<<dim3(IN_DIM/32, HID/32, 1), dim3(32, 8), 0, s2>>>(dec_W,    whi + W_DEC_OFF, nullptr, HID, IN_DIM);
    cudaEventRecord(evJ, s2);

    // gating on side stream, concurrent with res GEMM
    cudaStreamWaitEvent(s2, evE, 0);
    gating_kernel<<<N_TOK, 128, 0, s2>>>(gate_W, coef_W, coef_b);
    cudaEventRecord(evG, s2);

    // join weight transposes, then res (unscaled) on main stream
    cudaStreamWaitEvent(0, evJ, 0);

    // uh_raw = h @ res_W + res_b : 1-pass 128x128 (2 CTA/SM) -> fp16
    hmma_gemm_b2<1><<<dim3(HID/128, N_TOK/128), 128, B2SMEM_TOT>>>(
        hhi, whi + W_RES_OFF, res_b, HID, HID, uh, nullptr);

    // join gating, then grouped: uh = uh_raw*s1 + (h @ W_e + b_e)*s0
    cudaStreamWaitEvent(0, evG, 0);
    hmma_gemm_grouped_b2<<<dim3(HID/128, N_TOK/128, NEXP), 128, B2SMEM_TOT>>>(expert_b);

    // out = uh @ dec_W + dec_b : 1-pass 128x128 (2 CTA/SM) -> fp32
    hmma_gemm_b2<2><<<dim3(IN_DIM/128, N_TOK/128), 128, B2SMEM_TOT>>>(
        uh, whi + W_DEC_OFF, dec_b, HID, IN_DIM, nullptr, out);
}

// round 16
// speedup vs baseline: 6.4815x; 1.0510x over previous
#include <cuda_runtime.h>
#include <cuda_fp16.h>
#include <cuda.h>
#include <cstdint>
#include <math.h>

#define N_TOK  16384
#define IN_DIM 1024
#define HID    2048
#define NEXP   8
#define TAU    0.004f

// ---- device scratch (globals: allocation-free) ----
__device__ __align__(128) __half g_xhi[(size_t)N_TOK * IN_DIM];
__device__ __align__(128) __half g_xlo[(size_t)N_TOK * IN_DIM];
__device__ __align__(128) __half g_hhi[(size_t)N_TOK * HID];
__device__ __align__(128) __half g_hlo[(size_t)N_TOK * HID];
__device__ __align__(128) __half g_uh[(size_t)N_TOK * HID];
__device__ __align__(128) __half g_dh[(size_t)N_TOK * HID];   // repair Δh

#define W_ENC_OFF 0
#define W_RES_OFF (2048*1024)
#define W_EXP_OFF (W_RES_OFF + 2048*2048)
#define W_DEC_OFF (W_EXP_OFF + 8*2048*2048)
#define W_TOTAL   (W_DEC_OFF + 1024*2048)
__device__ __align__(128) __half g_Whi[(size_t)W_TOTAL];
__device__ __align__(128) __half g_Wlo[(size_t)IN_DIM * HID];  // enc lo only

__device__ int   g_perm[NEXP * N_TOK];
__device__ int   g_counts[NEXP];
__device__ float g_s0[N_TOK];
__device__ float g_s1[N_TOK];
__device__ int   g_flag[N_TOK];
__device__ int   g_nflag;
__device__ float g_vlog[(size_t)N_TOK * 8];
__device__ float g_cf0[N_TOK];

// ---- enc small-CTA SMEM (2-pass): 3 stages x (Ah,Bh,Bl each 8KB) = 72KB
#define ESTG 24576
#define EOFF_AH 0
#define EOFF_BH 8192
#define EOFF_BL 16384
#define ESMEM_TOT (3 * ESTG + 128)

// ---- small-CTA 1-pass tile (128x128, 128 thr, 2 CTA/SM): 3 x 32KB ----
#define B2STG 32768
#define B2OFF_A 0
#define B2OFF_B 16384
#define B2_RMAP (3 * B2STG)
#define B2SMEM_TOT (3 * B2STG + 640)

// ---- PTX helpers ----
__device__ __forceinline__ uint32_t smem_u32(const void* p) {
    uint32_t r;
    asm("{ .reg .u64 t; cvta.to.shared.u64 t, %1; cvt.u32.u64 %0, t; }" : "=r"(r) : "l"(p));
    return r;
}
__device__ __forceinline__ void cp16(uint32_t s, const void* g) {
    asm volatile("cp.async.cg.shared.global [%0], [%1], 16;" :: "r"(s), "l"(g));
}
#define CP_COMMIT() asm volatile("cp.async.commit_group;" ::: "memory")
#define CP_WAIT(n)  asm volatile("cp.async.wait_group %0;" :: "n"(n) : "memory")

__device__ __forceinline__ void ldsm4(uint32_t* r, uint32_t a) {
    asm volatile("ldmatrix.sync.aligned.m8n8.x4.shared.b16 {%0,%1,%2,%3}, [%4];"
                 : "=r"(r[0]), "=r"(r[1]), "=r"(r[2]), "=r"(r[3]) : "r"(a));
}
__device__ __forceinline__ void mma16816(float* c, const uint32_t* a, const uint32_t* b) {
    asm volatile(
        "mma.sync.aligned.m16n8k16.row.col.f32.f16.f16.f32 "
        "{%0,%1,%2,%3}, {%4,%5,%6,%7}, {%8,%9}, {%0,%1,%2,%3};"
        : "+f"(c[0]), "+f"(c[1]), "+f"(c[2]), "+f"(c[3])
        : "r"(a[0]), "r"(a[1]), "r"(a[2]), "r"(a[3]), "r"(b[0]), "r"(b[1]));
}

__device__ __forceinline__ uint32_t swz128(int row, int chunk) {
    return (uint32_t)(row * 128 + ((chunk ^ (row & 7)) * 16));
}
__device__ __forceinline__ uint32_t swz64(int row, int chunk) {
    return (uint32_t)(row * 64 + ((chunk ^ ((row >> 1) & 3)) * 16));
}

__device__ __forceinline__ void splitf(float v, __half& h, __half& l) {
    h = __float2half_rn(v);
    l = __float2half_rn(v - __half2float(h));
}

// ---- small kernels ----
__global__ __launch_bounds__(256) void conv_x_kernel(const float* __restrict__ x) {
    if (blockIdx.x == 0 && threadIdx.x < NEXP) { g_counts[threadIdx.x] = 0; }
    if (blockIdx.x == 0 && threadIdx.x == NEXP) { g_nflag = 0; }
    size_t i = ((size_t)blockIdx.x * 256 + threadIdx.x) * 4;
    float4 v = *(const float4*)(x + i);
    __half hb[4], lb[4];
    splitf(v.x, hb[0], lb[0]); splitf(v.y, hb[1], lb[1]);
    splitf(v.z, hb[2], lb[2]); splitf(v.w, hb[3], lb[3]);
    *(uint2*)(g_xhi + i) = *(uint2*)hb;
    *(uint2*)(g_xlo + i) = *(uint2*)lb;
}

// src [K,N] fp32 (batched over z) -> dst [N,K] fp16 hi (+lo), vectorized stores
__global__ __launch_bounds__(256)
void transpose_conv(const float* __restrict__ src, __half* __restrict__ dhi,
                    __half* __restrict__ dlo, int K, int N)
{
    __shared__ float t[32][33];
    const size_t zoff = (size_t)blockIdx.z * K * N;
    const int n0 = blockIdx.x * 32, k0 = blockIdx.y * 32;
    const int tx = threadIdx.x, ty = threadIdx.y;
    #pragma unroll
    for (int i = 0; i < 4; i++) {
        t[ty + i*8][tx] = src[zoff + (size_t)(k0 + ty + i*8) * N + n0 + tx];
    }
    __syncthreads();
    const int tid = ty * 32 + tx;
    const int nl = tid >> 3;
    const int kl = (tid & 7) * 4;
    __half h4[4], l4[4];
    #pragma unroll
    for (int q = 0; q < 4; q++) {
        splitf(t[kl + q][nl], h4[q], l4[q]);
    }
    const size_t di = zoff + (size_t)(n0 + nl) * K + k0 + kl;
    *(uint2*)(dhi + di) = *(uint2*)h4;
    if (dlo) { *(uint2*)(dlo + di) = *(uint2*)l4; }
}

// ---- gating with margin flagging (2-pass h) ----
__global__ __launch_bounds__(128)
void gating2p_kernel(const float* __restrict__ gate_W, const float* __restrict__ coef_W,
                     const float* __restrict__ coef_b)
{
    const int n = blockIdx.x;
    const int t = threadIdx.x;
    float acc[10];
    #pragma unroll
    for (int j = 0; j < 10; j++) { acc[j] = 0.0f; }

    const __half* hh = g_hhi + (size_t)n * HID;
    const __half* hl = g_hlo + (size_t)n * HID;
    for (int k = t; k < HID; k += 128) {
        const float hv = __half2float(hh[k]) + __half2float(hl[k]);
        #pragma unroll
        for (int j = 0; j < 8; j++) { acc[j] += hv * gate_W[k * 8 + j]; }
        acc[8] += hv * coef_W[k * 2 + 0];
        acc[9] += hv * coef_W[k * 2 + 1];
    }
    #pragma unroll
    for (int j = 0; j < 10; j++) {
        #pragma unroll
        for (int o = 16; o > 0; o >>= 1) {
            acc[j] += __shfl_down_sync(0xffffffffu, acc[j], o);
        }
    }

    __shared__ float red[4][10];
    const int warp = t >> 5, lane = t & 31;
    if (lane == 0) {
        #pragma unroll
        for (int j = 0; j < 10; j++) { red[warp][j] = acc[j]; }
    }
    __syncthreads();

    if (t == 0) {
        float v[10];
        #pragma unroll
        for (int j = 0; j < 10; j++) {
            v[j] = red[0][j] + red[1][j] + red[2][j] + red[3][j];
        }
        float lmax = v[0]; int idx = 0;
        #pragma unroll
        for (int j = 1; j < 8; j++) {
            if (v[j] > lmax) { lmax = v[j]; idx = j; }
        }
        float second = -1e30f;
        #pragma unroll
        for (int j = 0; j < 8; j++) {
            if (j != idx && v[j] > second) { second = v[j]; }
        }
        // coef softmax (unaffected by repair)
        const float c0 = v[8] + coef_b[0];
        const float c1 = v[9] + coef_b[1];
        const float cm = fmaxf(c0, c1);
        const float e0 = expf(c0 - cm), e1 = expf(c1 - cm);
        const float inv = 1.0f / (e0 + e1);
        const float coef0 = e0 * inv;
        g_s1[n] = e1 * inv;

        if (lmax - second > TAU) {
            float s = 0.0f;
            #pragma unroll
            for (int j = 0; j < 8; j++) { s += expf(v[j] - lmax); }
            g_s0[n] = (1.0f / s) * coef0;
            const int pos = atomicAdd(&g_counts[idx], 1);
            g_perm[idx * N_TOK + pos] = n;
        } else {
            g_cf0[n] = coef0;
            #pragma unroll
            for (int j = 0; j < 8; j++) { g_vlog[(size_t)n * 8 + j] = v[j]; }
            const int pos = atomicAdd(&g_nflag, 1);
            g_flag[pos] = n;
        }
    }
}

// ---- regate: exact logits for flagged tokens, then bucket ----
__global__ __launch_bounds__(128)
void regate_kernel(const float* __restrict__ gate_W)
{
    const int fi = blockIdx.x;
    if (fi >= g_nflag) return;
    const int tok = g_flag[fi];
    const int t = threadIdx.x;

    float acc[8];
    #pragma unroll
    for (int j = 0; j < 8; j++) { acc[j] = 0.0f; }

    const __half* hh = g_hhi + (size_t)tok * HID;
    const __half* hl = g_hlo + (size_t)tok * HID;
    const __half* dh = g_dh + (size_t)fi * HID;
    for (int k = t; k < HID; k += 128) {
        const float hv = __half2float(hh[k]) + __half2float(hl[k]);
        if (hv > 0.0f) {
            const float d = __half2float(dh[k]);
            #pragma unroll
            for (int j = 0; j < 8; j++) { acc[j] += d * gate_W[k * 8 + j]; }
        }
    }
    #pragma unroll
    for (int j = 0; j < 8; j++) {
        #pragma unroll
        for (int o = 16; o > 0; o >>= 1) {
            acc[j] += __shfl_down_sync(0xffffffffu, acc[j], o);
        }
    }
    __shared__ float red[4][8];
    const int warp = t >> 5, lane = t & 31;
    if (lane == 0) {
        #pragma unroll
        for (int j = 0; j < 8; j++) { red[warp][j] = acc[j]; }
    }
    __syncthreads();
    if (t == 0) {
        float v[8];
        #pragma unroll
        for (int j = 0; j < 8; j++) {
            v[j] = g_vlog[(size_t)tok * 8 + j]
                 + red[0][j] + red[1][j] + red[2][j] + red[3][j];
        }
        float lmax = v[0]; int idx = 0;
        #pragma unroll
        for (int j = 1; j < 8; j++) {
            if (v[j] > lmax) { lmax = v[j]; idx = j; }
        }
        float s = 0.0f;
        #pragma unroll
        for (int j = 0; j < 8; j++) { s += expf(v[j] - lmax); }
        g_s0[tok] = (1.0f / s) * g_cf0[tok];
        const int pos = atomicAdd(&g_counts[idx], 1);
        g_perm[idx * N_TOK + pos] = tok;
    }
}

// ===========================================================================
// ENC kernel (small-CTA, 2-pass): 128 threads (2x2 warps, 64x64 warp tile),
// tile 128x128, BK=32 (64B-row swizzle), 3 stages (72KB) -> 2 CTAs/SM.
// Passes: Ah*Bh + Ah*Bl. (Missing Al*Bh term repaired in gating path.)
// ===========================================================================
__global__ __launch_bounds__(128, 2)
void hmma_gemm_enc2(const __half* __restrict__ Ahi,
                    const __half* __restrict__ Bhi, const __half* __restrict__ Blo,
                    const float* __restrict__ bias, int K, int Nn,
                    __half* __restrict__ Chi, __half* __restrict__ Clo)
{
    extern __shared__ __align__(1024) char smem[];
    const uint32_t sb = smem_u32(smem);
    const int tid = threadIdx.x;
    const int lane = tid & 31, wid = tid >> 5;
    const int wm = wid >> 1, wn = wid & 1;           // 2 x 2 warp grid
    const int mrow0 = blockIdx.y * 128;
    const int ncol0 = blockIdx.x * 128;
    const int nt = K / 32;

    #define ELOADT(s, kt) do {                                                   \
        const uint32_t st_ = sb + (uint32_t)(s) * ESTG;                           \
        _Pragma("unroll")                                                         \
        for (int i_ = 0; i_ < 4; i_++) {                                          \
            const int slot_ = tid + 128 * i_;                                     \
            const int row_ = slot_ >> 2, ch_ = slot_ & 3;                         \
            const uint32_t sw_ = swz64(row_, ch_);                                \
            const size_t go_ = (size_t)(kt) * 32 + ch_ * 8;                       \
            cp16(st_ + EOFF_AH + sw_, Ahi + (size_t)(mrow0 + row_) * K + go_);    \
            cp16(st_ + EOFF_BH + sw_, Bhi + (size_t)(ncol0 + row_) * K + go_);    \
            cp16(st_ + EOFF_BL + sw_, Blo + (size_t)(ncol0 + row_) * K + go_);    \
        }                                                                         \
        CP_COMMIT();                                                              \
    } while (0)

    ELOADT(0, 0);
    ELOADT(1, 1);

    float acc[4][8][4];
    #pragma unroll
    for (int i = 0; i < 4; i++) {
        #pragma unroll
        for (int j = 0; j < 8; j++) {
            #pragma unroll
            for (int q = 0; q < 4; q++) { acc[i][j][q] = 0.0f; }
        }
    }

    const int arow = (lane & 7) | (((lane >> 3) & 1) << 3);
    const int ach  = lane >> 4;
    const int brow = (lane & 7) | (((lane >> 4) & 1) << 3);
    const int bch  = (lane >> 3) & 1;

    uint32_t ah[4][4], bh[4][4], bl[4][4];

    for (int kt = 0; kt < nt; kt++) {
        if (kt + 1 < nt) { CP_WAIT(1); } else { CP_WAIT(0); }
        __syncthreads();
        if (kt + 2 < nt) { ELOADT((kt + 2) % 3, kt + 2); }

        const uint32_t st = sb + (uint32_t)(kt % 3) * ESTG;
        #pragma unroll
        for (int s16 = 0; s16 < 2; s16++) {
            #pragma unroll
            for (int i = 0; i < 4; i++) {
                const uint32_t a = swz64(wm * 64 + i * 16 + arow, s16 * 2 + ach);
                ldsm4(ah[i], st + EOFF_AH + a);
            }
            #pragma unroll
            for (int j = 0; j < 4; j++) {
                const uint32_t b = swz64(wn * 64 + j * 16 + brow, s16 * 2 + bch);
                ldsm4(bh[j], st + EOFF_BH + b);
                ldsm4(bl[j], st + EOFF_BL + b);
            }
            #pragma unroll
            for (int i = 0; i < 4; i++) {
                #pragma unroll
                for (int j = 0; j < 8; j++) {
                    mma16816(acc[i][j], ah[i], &bh[j >> 1][(j & 1) * 2]);
                    mma16816(acc[i][j], ah[i], &bl[j >> 1][(j & 1) * 2]);
                }
            }
        }
    }

    // epilogue: relu + split -> Chi/Clo
    #pragma unroll
    for (int i = 0; i < 4; i++) {
        const int rb = mrow0 + wm * 64 + i * 16 + (lane >> 2);
        #pragma unroll
        for (int h = 0; h < 2; h++) {
            const int row = rb + h * 8;
            #pragma unroll
            for (int j = 0; j < 8; j++) {
                const int col = ncol0 + wn * 64 + j * 8 + (lane & 3) * 2;
                const float2 b2 = *(const float2*)(bias + col);
                float v0 = fmaxf(acc[i][j][h * 2 + 0] + b2.x, 0.0f);
                float v1 = fmaxf(acc[i][j][h * 2 + 1] + b2.y, 0.0f);
                __half h0, l0, h1, l1;
                splitf(v0, h0, l0); splitf(v1, h1, l1);
                *(__half2*)(Chi + (size_t)row * Nn + col) = __halves2half2(h0, h1);
                *(__half2*)(Clo + (size_t)row * Nn + col) = __halves2half2(l0, l1);
            }
        }
    }
    #undef ELOADT
}

// ===========================================================================
// Small-CTA 1-pass GEMM: 128 threads (2x2 warps, 64x64 warp tile),
// tile 128x128, BK=64, 3 stages (96KB) -> 2 CTAs/SM.
// MODE 1: acc+bias -> Ch (fp16, unscaled) ; MODE 2: acc+bias -> Cf (fp32)
// ===========================================================================
#define B2LDFRAG(st, s16) do {                                                    \
    _Pragma("unroll")                                                             \
    for (int i_ = 0; i_ < 4; i_++) {                                               \
        ldsm4(ah[i_], (st) + B2OFF_A + swz128(wm * 64 + i_ * 16 + arow, (s16) * 2 + ach)); \
    }                                                                             \
    _Pragma("unroll")                                                             \
    for (int j_ = 0; j_ < 4; j_++) {                                               \
        ldsm4(bh[j_], (st) + B2OFF_B + swz128(wn * 64 + j_ * 16 + brow, (s16) * 2 + bch)); \
    }                                                                             \
} while (0)

#define B2DOMMA() do {                                                            \
    _Pragma("unroll")                                                             \
    for (int i_ = 0; i_ < 4; i_++) {                                               \
        _Pragma("unroll")                                                         \
        for (int j_ = 0; j_ < 8; j_++) {                                           \
            mma16816(acc[i_][j_], ah[i_], &bh[j_ >> 1][(j_ & 1) * 2]);             \
        }                                                                         \
    }                                                                             \
} while (0)

template <int MODE>
__global__ __launch_bounds__(128, 2)
void hmma_gemm_b2(const __half* __restrict__ A, const __half* __restrict__ B,
                  const float* __restrict__ bias, int K, int Nn,
                  __half* __restrict__ Ch, float* __restrict__ Cf)
{
    extern __shared__ __align__(1024) char smem[];
    const uint32_t sb = smem_u32(smem);
    const int tid = threadIdx.x;
    const int lane = tid & 31, wid = tid >> 5;
    const int wm = wid >> 1, wn = wid & 1;
    const int mrow0 = blockIdx.y * 128;
    const int ncol0 = blockIdx.x * 128;
    const int nt = K / 64;

    #define B2LOADT(s, kt) do {                                                  \
        const uint32_t st_ = sb + (uint32_t)(s) * B2STG;                          \
        _Pragma("unroll")                                                         \
        for (int i_ = 0; i_ < 8; i_++) {                                          \
            const int slot_ = tid + 128 * i_;                                     \
            const int row_ = slot_ >> 3, ch_ = slot_ & 7;                         \
            const size_t go_ = (size_t)(kt) * 64 + ch_ * 8;                       \
            cp16(st_ + B2OFF_A + swz128(row_, ch_),                               \
                 A + (size_t)(mrow0 + row_) * K + go_);                           \
            cp16(st_ + B2OFF_B + swz128(row_, ch_),                               \
                 B + (size_t)(ncol0 + row_) * K + go_);                           \
        }                                                                         \
        CP_COMMIT();                                                              \
    } while (0)

    B2LOADT(0, 0);
    B2LOADT(1, 1);

    float acc[4][8][4];
    #pragma unroll
    for (int i = 0; i < 4; i++) {
        #pragma unroll
        for (int j = 0; j < 8; j++) {
            #pragma unroll
            for (int q = 0; q < 4; q++) { acc[i][j][q] = 0.0f; }
        }
    }

    const int arow = (lane & 7) | (((lane >> 3) & 1) << 3);
    const int ach  = lane >> 4;
    const int brow = (lane & 7) | (((lane >> 4) & 1) << 3);
    const int bch  = (lane >> 3) & 1;

    uint32_t ah[4][4], bh[4][4];

    for (int kt = 0; kt < nt; kt++) {
        if (kt + 1 < nt) { CP_WAIT(1); } else { CP_WAIT(0); }
        __syncthreads();
        if (kt + 2 < nt) { B2LOADT((kt + 2) % 3, kt + 2); }

        const uint32_t st = sb + (uint32_t)(kt % 3) * B2STG;
        #pragma unroll
        for (int s16 = 0; s16 < 4; s16++) {
            B2LDFRAG(st, s16);
            B2DOMMA();
        }
    }

    #pragma unroll
    for (int i = 0; i < 4; i++) {
        const int rb = mrow0 + wm * 64 + i * 16 + (lane >> 2);
        #pragma unroll
        for (int h = 0; h < 2; h++) {
            const int row = rb + h * 8;
            #pragma unroll
            for (int j = 0; j < 8; j++) {
                const int col = ncol0 + wn * 64 + j * 8 + (lane & 3) * 2;
                const float2 b2 = *(const float2*)(bias + col);
                float v0 = acc[i][j][h * 2 + 0] + b2.x;
                float v1 = acc[i][j][h * 2 + 1] + b2.y;
                if (MODE == 1) {
                    *(__half2*)(Ch + (size_t)row * Nn + col) =
                        __halves2half2(__float2half_rn(v0), __float2half_rn(v1));
                } else {
                    *(float2*)(Cf + (size_t)row * Nn + col) = make_float2(v0, v1);
                }
            }
        }
    }
    #undef B2LOADT
}

// ===========================================================================
// Grouped expert GEMM (1-pass small-CTA): A rows via g_perm;
// epilogue: g_uh[tok] = fp16(uh_raw[tok]*s1[tok] + (acc + b_e)*s0[tok])
// ===========================================================================
__global__ __launch_bounds__(128, 2)
void hmma_gemm_grouped_b2(const float* __restrict__ bexp)
{
    extern __shared__ __align__(1024) char smem[];
    const int e = blockIdx.z;
    const int cnt = g_counts[e];
    const int rowBase = blockIdx.y * 128;
    if (rowBase >= cnt) return;

    const uint32_t sb = smem_u32(smem);
    const int tid = threadIdx.x;
    const int lane = tid & 31, wid = tid >> 5;
    const int wm = wid >> 1, wn = wid & 1;
    const int ncol0 = blockIdx.x * 128;
    const int nt = HID / 64;
    int* rmap = (int*)(smem + B2_RMAP);

    {
        int i = rowBase + tid;
        if (i > cnt - 1) i = cnt - 1;
        rmap[tid] = g_perm[e * N_TOK + i];
    }
    __syncthreads();

    const __half* B = g_Whi + W_EXP_OFF + (size_t)e * HID * HID;

    size_t ga[8];
    #pragma unroll
    for (int i = 0; i < 8; i++) {
        ga[i] = (size_t)rmap[(tid + 128 * i) >> 3] * HID;
    }

    #define G2LOADT(s, kt) do {                                                  \
        const uint32_t st_ = sb + (uint32_t)(s) * B2STG;                          \
        _Pragma("unroll")                                                         \
        for (int i_ = 0; i_ < 8; i_++) {                                          \
            const int slot_ = tid + 128 * i_;                                     \
            const int row_ = slot_ >> 3, ch_ = slot_ & 7;                         \
            const size_t go_ = (size_t)(kt) * 64 + ch_ * 8;                       \
            cp16(st_ + B2OFF_A + swz128(row_, ch_), g_hhi + ga[i_] + go_);        \
            cp16(st_ + B2OFF_B + swz128(row_, ch_),                               \
                 B + (size_t)(ncol0 + row_) * HID + go_);                         \
        }                                                                         \
        CP_COMMIT();                                                              \
    } while (0)

    G2LOADT(0, 0);
    G2LOADT(1, 1);

    float acc[4][8][4];
    #pragma unroll
    for (int i = 0; i < 4; i++) {
        #pragma unroll
        for (int j = 0; j < 8; j++) {
            #pragma unroll
            for (int q = 0; q < 4; q++) { acc[i][j][q] = 0.0f; }
        }
    }

    const int arow = (lane & 7) | (((lane >> 3) & 1) << 3);
    const int ach  = lane >> 4;
    const int brow = (lane & 7) | (((lane >> 4) & 1) << 3);
    const int bch  = (lane >> 3) & 1;

    uint32_t ah[4][4], bh[4][4];

    for (int kt = 0; kt < nt; kt++) {
        if (kt + 1 < nt) { CP_WAIT(1); } else { CP_WAIT(0); }
        __syncthreads();
        if (kt + 2 < nt) { G2LOADT((kt + 2) % 3, kt + 2); }

        const uint32_t st = sb + (uint32_t)(kt % 3) * B2STG;
        #pragma unroll
        for (int s16 = 0; s16 < 4; s16++) {
            B2LDFRAG(st, s16);
            B2DOMMA();
        }
    }

    #pragma unroll
    for (int i = 0; i < 4; i++) {
        const int lb = wm * 64 + i * 16 + (lane >> 2);
        #pragma unroll
        for (int h = 0; h < 2; h++) {
            const int li = lb + h * 8;
            if (rowBase + li >= cnt) continue;
            const int tok = rmap[li];
            const float s0 = g_s0[tok];
            const float s1 = g_s1[tok];
            #pragma unroll
            for (int j = 0; j < 8; j++) {
                const int col = ncol0 + wn * 64 + j * 8 + (lane & 3) * 2;
                const float2 b2 = *(const float2*)(bexp + e * HID + col);
                float2 u2 = __half22float2(*(const __half2*)(g_uh + (size_t)tok * HID + col));
                float v0 = u2.x * s1 + (acc[i][j][h * 2 + 0] + b2.x) * s0;
                float v1 = u2.y * s1 + (acc[i][j][h * 2 + 1] + b2.y) * s0;
                *(__half2*)(g_uh + (size_t)tok * HID + col) =
                    __halves2half2(__float2half_rn(v0), __float2half_rn(v1));
            }
        }
    }
    #undef G2LOADT
}

// ===========================================================================
// Flag-repair GEMM: Δh[fi,:] = xlo[g_flag[fi],:] @ enc_Whi^T, fp16 out.
// Same skeleton as grouped (gather A rows), B = enc Whi [HID, IN_DIM].
// ===========================================================================
__global__ __launch_bounds__(128, 2)
void hmma_gemm_flag()
{
    extern __shared__ __align__(1024) char smem[];
    const int F = g_nflag;
    const int rowBase = blockIdx.y * 128;
    if (rowBase >= F) return;

    const uint32_t sb = smem_u32(smem);
    const int tid = threadIdx.x;
    const int lane = tid & 31, wid = tid >> 5;
    const int wm = wid >> 1, wn = wid & 1;
    const int ncol0 = blockIdx.x * 128;
    const int nt = IN_DIM / 64;
    int* rmap = (int*)(smem + B2_RMAP);

    {
        int i = rowBase + tid;
        if (i > F - 1) i = F - 1;
        rmap[tid] = g_flag[i];
    }
    __syncthreads();

    const __half* B = g_Whi + W_ENC_OFF;

    size_t ga[8];
    #pragma unroll
    for (int i = 0; i < 8; i++) {
        ga[i] = (size_t)rmap[(tid + 128 * i) >> 3] * IN_DIM;
    }

    #define FLOADT(s, kt) do {                                                   \
        const uint32_t st_ = sb + (uint32_t)(s) * B2STG;                          \
        _Pragma("unroll")                                                         \
        for (int i_ = 0; i_ < 8; i_++) {                                          \
            const int slot_ = tid + 128 * i_;                                     \
            const int row_ = slot_ >> 3, ch_ = slot_ & 7;                         \
            const size_t go_ = (size_t)(kt) * 64 + ch_ * 8;                       \
            cp16(st_ + B2OFF_A + swz128(row_, ch_), g_xlo + ga[i_] + go_);        \
            cp16(st_ + B2OFF_B + swz128(row_, ch_),                               \
                 B + (size_t)(ncol0 + row_) * IN_DIM + go_);                      \
        }                                                                         \
        CP_COMMIT();                                                              \
    } while (0)

    FLOADT(0, 0);
    FLOADT(1, 1);

    float acc[4][8][4];
    #pragma unroll
    for (int i = 0; i < 4; i++) {
        #pragma unroll
        for (int j = 0; j < 8; j++) {
            #pragma unroll
            for (int q = 0; q < 4; q++) { acc[i][j][q] = 0.0f; }
        }
    }

    const int arow = (lane & 7) | (((lane >> 3) & 1) << 3);
    const int ach  = lane >> 4;
    const int brow = (lane & 7) | (((lane >> 4) & 1) << 3);
    const int bch  = (lane >> 3) & 1;

    uint32_t ah[4][4], bh[4][4];

    for (int kt = 0; kt < nt; kt++) {
        if (kt + 1 < nt) { CP_WAIT(1); } else { CP_WAIT(0); }
        __syncthreads();
        if (kt + 2 < nt) { FLOADT((kt + 2) % 3, kt + 2); }

        const uint32_t st = sb + (uint32_t)(kt % 3) * B2STG;
        #pragma unroll
        for (int s16 = 0; s16 < 4; s16++) {
            B2LDFRAG(st, s16);
            B2DOMMA();
        }
    }

    #pragma unroll
    for (int i = 0; i < 4; i++) {
        const int lb = wm * 64 + i * 16 + (lane >> 2);
        #pragma unroll
        for (int h = 0; h < 2; h++) {
            const int li = lb + h * 8;
            if (rowBase + li >= F) continue;
            const size_t fo = (size_t)(rowBase + li) * HID;
            #pragma unroll
            for (int j = 0; j < 8; j++) {
                const int col = ncol0 + wn * 64 + j * 8 + (lane & 3) * 2;
                *(__half2*)(g_dh + fo + col) =
                    __halves2half2(__float2half_rn(acc[i][j][h * 2 + 0]),
                                   __float2half_rn(acc[i][j][h * 2 + 1]));
            }
        }
    }
    #undef FLOADT
}

// ---------------------------------------------------------------------------
extern "C" void kernel_launch(void* const* d_in, const int* in_sizes, int n_in,
                              void* d_out, int out_size)
{
    const float* x        = (const float*)d_in[0];
    const float* enc_W    = (const float*)d_in[1];
    const float* enc_b    = (const float*)d_in[2];
    const float* gate_W   = (const float*)d_in[3];
    const float* expert_W = (const float*)d_in[4];
    const float* expert_b = (const float*)d_in[5];
    const float* res_W    = (const float*)d_in[6];
    const float* res_b    = (const float*)d_in[7];
    const float* coef_W   = (const float*)d_in[8];
    const float* coef_b   = (const float*)d_in[9];
    const float* dec_W    = (const float*)d_in[10];
    const float* dec_b    = (const float*)d_in[11];
    float* out = (float*)d_out;

    __half *xhi, *xlo, *hhi, *hlo, *uh, *whi, *wlo;
    cudaGetSymbolAddress((void**)&xhi, g_xhi);
    cudaGetSymbolAddress((void**)&xlo, g_xlo);
    cudaGetSymbolAddress((void**)&hhi, g_hhi);
    cudaGetSymbolAddress((void**)&hlo, g_hlo);
    cudaGetSymbolAddress((void**)&uh,  g_uh);
    cudaGetSymbolAddress((void**)&whi, g_Whi);
    cudaGetSymbolAddress((void**)&wlo, g_Wlo);

    cudaFuncSetAttribute((const void*)hmma_gemm_enc2,       cudaFuncAttributeMaxDynamicSharedMemorySize, ESMEM_TOT);
    cudaFuncSetAttribute((const void*)hmma_gemm_b2<1>,      cudaFuncAttributeMaxDynamicSharedMemorySize, B2SMEM_TOT);
    cudaFuncSetAttribute((const void*)hmma_gemm_b2<2>,      cudaFuncAttributeMaxDynamicSharedMemorySize, B2SMEM_TOT);
    cudaFuncSetAttribute((const void*)hmma_gemm_grouped_b2, cudaFuncAttributeMaxDynamicSharedMemorySize, B2SMEM_TOT);
    cudaFuncSetAttribute((const void*)hmma_gemm_flag,       cudaFuncAttributeMaxDynamicSharedMemorySize, B2SMEM_TOT);

    // side stream + events (lazy init; host-side only)
    static cudaStream_t s2 = nullptr;
    static cudaEvent_t evF = nullptr, evJ = nullptr, evE = nullptr, evG = nullptr, evT = nullptr;
    if (!s2) {
        cudaStreamCreateWithFlags(&s2, cudaStreamNonBlocking);
        cudaEventCreateWithFlags(&evF, cudaEventDisableTiming);
        cudaEventCreateWithFlags(&evJ, cudaEventDisableTiming);
        cudaEventCreateWithFlags(&evE, cudaEventDisableTiming);
        cudaEventCreateWithFlags(&evG, cudaEventDisableTiming);
        cudaEventCreateWithFlags(&evT, cudaEventDisableTiming);
    }

    // fork side stream immediately: enc transpose runs concurrent with conv_x
    cudaEventRecord(evF, 0);
    cudaStreamWaitEvent(s2, evF, 0);
    transpose_conv<<<dim3(HID/32, IN_DIM/32, 1), dim3(32, 8), 0, s2>>>(enc_W, whi + W_ENC_OFF, wlo, IN_DIM, HID);
    cudaEventRecord(evT, s2);
    transpose_conv<<<dim3(HID/32, HID/32, 1),    dim3(32, 8), 0, s2>>>(res_W, whi + W_RES_OFF, nullptr, HID, HID);

    // main stream: x split (+ zero counts/flags)
    conv_x_kernel<<<(N_TOK * IN_DIM) / 1024, 256>>>(x);

    // enc GEMM (2-pass, 2 CTA/SM) — waits for enc transpose
    cudaStreamWaitEvent(0, evT, 0);
    hmma_gemm_enc2<<<dim3(HID/128, N_TOK/128), 128, ESMEM_TOT>>>(
        xhi, whi + W_ENC_OFF, wlo,
        enc_b, IN_DIM, HID, hhi, hlo);
    cudaEventRecord(evE, 0);

    // remaining weight transposes on side stream (overlap enc execution)
    transpose_conv<<<dim3(HID/32, HID/32, NEXP), dim3(32, 8), 0, s2>>>(expert_W, whi + W_EXP_OFF, nullptr, HID, HID);
    transpose_conv<<<dim3(IN_DIM/32, HID/32, 1), dim3(32, 8), 0, s2>>>(dec_W,    whi + W_DEC_OFF, nullptr, HID, IN_DIM);
    cudaEventRecord(evJ, s2);

    // gating chain on side stream (concurrent with res GEMM):
    // gating2p -> flag GEMM (Δh) -> regate (exact argmax for flagged)
    cudaStreamWaitEvent(s2, evE, 0);
    gating2p_kernel<<<N_TOK, 128, 0, s2>>>(gate_W, coef_W, coef_b);
    hmma_gemm_flag<<<dim3(HID/128, N_TOK/128), 128, B2SMEM_TOT, s2>>>();
    regate_kernel<<<N_TOK, 128, 0, s2>>>(gate_W);
    cudaEventRecord(evG, s2);

    // join weight transposes, then res (unscaled) on main stream
    cudaStreamWaitEvent(0, evJ, 0);

    // uh_raw = h @ res_W + res_b : 1-pass 128x128 (2 CTA/SM) -> fp16
    hmma_gemm_b2<1><<<dim3(HID/128, N_TOK/128), 128, B2SMEM_TOT>>>(
        hhi, whi + W_RES_OFF, res_b, HID, HID, uh, nullptr);

    // join gating chain, then grouped: uh = uh_raw*s1 + (h @ W_e + b_e)*s0
    cudaStreamWaitEvent(0, evG, 0);
    hmma_gemm_grouped_b2<<<dim3(HID/128, N_TOK/128, NEXP), 128, B2SMEM_TOT>>>(expert_b);

    // out = uh @ dec_W + dec_b : 1-pass 128x128 (2 CTA/SM) -> fp32
    hmma_gemm_b2<2><<<dim3(IN_DIM/128, N_TOK/128), 128, B2SMEM_TOT>>>(
        uh, whi + W_DEC_OFF, dec_b, HID, IN_DIM, nullptr, out);
}

// round 17
// speedup vs baseline: 6.9620x; 1.0741x over previous
#include <cuda_runtime.h>
#include <cuda_fp16.h>
#include <cuda.h>
#include <cstdint>
#include <math.h>

#define N_TOK  16384
#define IN_DIM 1024
#define HID    2048
#define NEXP   8
#define TAU    0.004f

// ---- device scratch (globals: allocation-free) ----
__device__ __align__(128) __half g_xhi[(size_t)N_TOK * IN_DIM];
__device__ __align__(128) __half g_xlo[(size_t)N_TOK * IN_DIM];
__device__ __align__(128) __half g_hhi[(size_t)N_TOK * HID];
__device__ __align__(128) __half g_hlo[(size_t)N_TOK * HID];
__device__ __align__(128) __half g_uh[(size_t)N_TOK * HID];
__device__ __align__(128) __half g_dh[(size_t)N_TOK * HID];   // repair Δh

#define W_ENC_OFF 0
#define W_RES_OFF (2048*1024)
#define W_EXP_OFF (W_RES_OFF + 2048*2048)
#define W_DEC_OFF (W_EXP_OFF + 8*2048*2048)
#define W_TOTAL   (W_DEC_OFF + 1024*2048)
__device__ __align__(128) __half g_Whi[(size_t)W_TOTAL];
__device__ __align__(128) __half g_Wlo[(size_t)IN_DIM * HID];  // enc lo only

__device__ int   g_perm[NEXP * N_TOK];
__device__ int   g_counts[NEXP];
__device__ float g_s0[N_TOK];
__device__ float g_s1[N_TOK];
__device__ int   g_flag[N_TOK];
__device__ int   g_nflag;
__device__ float g_vlog[(size_t)N_TOK * 8];
__device__ float g_cf0[N_TOK];

// ---- small-CTA tile (128x128, 128 thr, 2 CTA/SM): 3 x 32KB ----
#define B2STG 32768
#define B2OFF_A 0
#define B2OFF_B 16384
#define B2_RMAP (3 * B2STG)
#define B2SMEM_TOT (3 * B2STG + 640)

// ---- PTX helpers ----
__device__ __forceinline__ uint32_t smem_u32(const void* p) {
    uint32_t r;
    asm("{ .reg .u64 t; cvta.to.shared.u64 t, %1; cvt.u32.u64 %0, t; }" : "=r"(r) : "l"(p));
    return r;
}
__device__ __forceinline__ void cp16(uint32_t s, const void* g) {
    asm volatile("cp.async.cg.shared.global [%0], [%1], 16;" :: "r"(s), "l"(g));
}
#define CP_COMMIT() asm volatile("cp.async.commit_group;" ::: "memory")
#define CP_WAIT(n)  asm volatile("cp.async.wait_group %0;" :: "n"(n) : "memory")

__device__ __forceinline__ void ldsm4(uint32_t* r, uint32_t a) {
    asm volatile("ldmatrix.sync.aligned.m8n8.x4.shared.b16 {%0,%1,%2,%3}, [%4];"
                 : "=r"(r[0]), "=r"(r[1]), "=r"(r[2]), "=r"(r[3]) : "r"(a));
}
__device__ __forceinline__ void mma16816(float* c, const uint32_t* a, const uint32_t* b) {
    asm volatile(
        "mma.sync.aligned.m16n8k16.row.col.f32.f16.f16.f32 "
        "{%0,%1,%2,%3}, {%4,%5,%6,%7}, {%8,%9}, {%0,%1,%2,%3};"
        : "+f"(c[0]), "+f"(c[1]), "+f"(c[2]), "+f"(c[3])
        : "r"(a[0]), "r"(a[1]), "r"(a[2]), "r"(a[3]), "r"(b[0]), "r"(b[1]));
}

__device__ __forceinline__ uint32_t swz128(int row, int chunk) {
    return (uint32_t)(row * 128 + ((chunk ^ (row & 7)) * 16));
}

__device__ __forceinline__ void splitf(float v, __half& h, __half& l) {
    h = __float2half_rn(v);
    l = __float2half_rn(v - __half2float(h));
}

// ---- small kernels ----
__global__ __launch_bounds__(256) void conv_x_kernel(const float* __restrict__ x) {
    if (blockIdx.x == 0 && threadIdx.x < NEXP) { g_counts[threadIdx.x] = 0; }
    if (blockIdx.x == 0 && threadIdx.x == NEXP) { g_nflag = 0; }
    size_t i = ((size_t)blockIdx.x * 256 + threadIdx.x) * 4;
    float4 v = *(const float4*)(x + i);
    __half hb[4], lb[4];
    splitf(v.x, hb[0], lb[0]); splitf(v.y, hb[1], lb[1]);
    splitf(v.z, hb[2], lb[2]); splitf(v.w, hb[3], lb[3]);
    *(uint2*)(g_xhi + i) = *(uint2*)hb;
    *(uint2*)(g_xlo + i) = *(uint2*)lb;
}

// src [K,N] fp32 (batched over z) -> dst [N,K] fp16 hi (+lo), vectorized stores
__global__ __launch_bounds__(256)
void transpose_conv(const float* __restrict__ src, __half* __restrict__ dhi,
                    __half* __restrict__ dlo, int K, int N)
{
    __shared__ float t[32][33];
    const size_t zoff = (size_t)blockIdx.z * K * N;
    const int n0 = blockIdx.x * 32, k0 = blockIdx.y * 32;
    const int tx = threadIdx.x, ty = threadIdx.y;
    #pragma unroll
    for (int i = 0; i < 4; i++) {
        t[ty + i*8][tx] = src[zoff + (size_t)(k0 + ty + i*8) * N + n0 + tx];
    }
    __syncthreads();
    const int tid = ty * 32 + tx;
    const int nl = tid >> 3;
    const int kl = (tid & 7) * 4;
    __half h4[4], l4[4];
    #pragma unroll
    for (int q = 0; q < 4; q++) {
        splitf(t[kl + q][nl], h4[q], l4[q]);
    }
    const size_t di = zoff + (size_t)(n0 + nl) * K + k0 + kl;
    *(uint2*)(dhi + di) = *(uint2*)h4;
    if (dlo) { *(uint2*)(dlo + di) = *(uint2*)l4; }
}

// ---- gating with margin flagging (1-pass h) ----
__global__ __launch_bounds__(128)
void gating2p_kernel(const float* __restrict__ gate_W, const float* __restrict__ coef_W,
                     const float* __restrict__ coef_b)
{
    const int n = blockIdx.x;
    const int t = threadIdx.x;
    float acc[10];
    #pragma unroll
    for (int j = 0; j < 10; j++) { acc[j] = 0.0f; }

    const __half* hh = g_hhi + (size_t)n * HID;
    const __half* hl = g_hlo + (size_t)n * HID;
    for (int k = t; k < HID; k += 128) {
        const float hv = __half2float(hh[k]) + __half2float(hl[k]);
        #pragma unroll
        for (int j = 0; j < 8; j++) { acc[j] += hv * gate_W[k * 8 + j]; }
        acc[8] += hv * coef_W[k * 2 + 0];
        acc[9] += hv * coef_W[k * 2 + 1];
    }
    #pragma unroll
    for (int j = 0; j < 10; j++) {
        #pragma unroll
        for (int o = 16; o > 0; o >>= 1) {
            acc[j] += __shfl_down_sync(0xffffffffu, acc[j], o);
        }
    }

    __shared__ float red[4][10];
    const int warp = t >> 5, lane = t & 31;
    if (lane == 0) {
        #pragma unroll
        for (int j = 0; j < 10; j++) { red[warp][j] = acc[j]; }
    }
    __syncthreads();

    if (t == 0) {
        float v[10];
        #pragma unroll
        for (int j = 0; j < 10; j++) {
            v[j] = red[0][j] + red[1][j] + red[2][j] + red[3][j];
        }
        float lmax = v[0]; int idx = 0;
        #pragma unroll
        for (int j = 1; j < 8; j++) {
            if (v[j] > lmax) { lmax = v[j]; idx = j; }
        }
        float second = -1e30f;
        #pragma unroll
        for (int j = 0; j < 8; j++) {
            if (j != idx && v[j] > second) { second = v[j]; }
        }
        const float c0 = v[8] + coef_b[0];
        const float c1 = v[9] + coef_b[1];
        const float cm = fmaxf(c0, c1);
        const float e0 = expf(c0 - cm), e1 = expf(c1 - cm);
        const float inv = 1.0f / (e0 + e1);
        const float coef0 = e0 * inv;
        g_s1[n] = e1 * inv;

        if (lmax - second > TAU) {
            float s = 0.0f;
            #pragma unroll
            for (int j = 0; j < 8; j++) { s += expf(v[j] - lmax); }
            g_s0[n] = (1.0f / s) * coef0;
            const int pos = atomicAdd(&g_counts[idx], 1);
            g_perm[idx * N_TOK + pos] = n;
        } else {
            g_cf0[n] = coef0;
            #pragma unroll
            for (int j = 0; j < 8; j++) { g_vlog[(size_t)n * 8 + j] = v[j]; }
            const int pos = atomicAdd(&g_nflag, 1);
            g_flag[pos] = n;
        }
    }
}

// ---- regate: corrected logits for flagged tokens, then bucket ----
__global__ __launch_bounds__(128)
void regate_kernel(const float* __restrict__ gate_W)
{
    const int fi = blockIdx.x;
    if (fi >= g_nflag) return;
    const int tok = g_flag[fi];
    const int t = threadIdx.x;

    float acc[8];
    #pragma unroll
    for (int j = 0; j < 8; j++) { acc[j] = 0.0f; }

    const __half* hh = g_hhi + (size_t)tok * HID;
    const __half* hl = g_hlo + (size_t)tok * HID;
    const __half* dh = g_dh + (size_t)fi * HID;
    for (int k = t; k < HID; k += 128) {
        const float hv = __half2float(hh[k]) + __half2float(hl[k]);
        if (hv > 0.0f) {
            const float d = __half2float(dh[k]);
            #pragma unroll
            for (int j = 0; j < 8; j++) { acc[j] += d * gate_W[k * 8 + j]; }
        }
    }
    #pragma unroll
    for (int j = 0; j < 8; j++) {
        #pragma unroll
        for (int o = 16; o > 0; o >>= 1) {
            acc[j] += __shfl_down_sync(0xffffffffu, acc[j], o);
        }
    }
    __shared__ float red[4][8];
    const int warp = t >> 5, lane = t & 31;
    if (lane == 0) {
        #pragma unroll
        for (int j = 0; j < 8; j++) { red[warp][j] = acc[j]; }
    }
    __syncthreads();
    if (t == 0) {
        float v[8];
        #pragma unroll
        for (int j = 0; j < 8; j++) {
            v[j] = g_vlog[(size_t)tok * 8 + j]
                 + red[0][j] + red[1][j] + red[2][j] + red[3][j];
        }
        float lmax = v[0]; int idx = 0;
        #pragma unroll
        for (int j = 1; j < 8; j++) {
            if (v[j] > lmax) { lmax = v[j]; idx = j; }
        }
        float s = 0.0f;
        #pragma unroll
        for (int j = 0; j < 8; j++) { s += expf(v[j] - lmax); }
        g_s0[tok] = (1.0f / s) * g_cf0[tok];
        const int pos = atomicAdd(&g_counts[idx], 1);
        g_perm[idx * N_TOK + pos] = tok;
    }
}

// ===========================================================================
// Small-CTA 1-pass GEMM: 128 threads (2x2 warps, 64x64 warp tile),
// tile 128x128, BK=64, 3 stages (96KB) -> 2 CTAs/SM.
// MODE 0: relu(acc+bias) -> split Chi/Clo (enc)
// MODE 1: acc+bias -> Ch (fp16, unscaled)
// MODE 2: acc+bias -> Cf (fp32)
// ===========================================================================
#define B2LDFRAG(st, s16) do {                                                    \
    _Pragma("unroll")                                                             \
    for (int i_ = 0; i_ < 4; i_++) {                                               \
        ldsm4(ah[i_], (st) + B2OFF_A + swz128(wm * 64 + i_ * 16 + arow, (s16) * 2 + ach)); \
    }                                                                             \
    _Pragma("unroll")                                                             \
    for (int j_ = 0; j_ < 4; j_++) {                                               \
        ldsm4(bh[j_], (st) + B2OFF_B + swz128(wn * 64 + j_ * 16 + brow, (s16) * 2 + bch)); \
    }                                                                             \
} while (0)

#define B2DOMMA() do {                                                            \
    _Pragma("unroll")                                                             \
    for (int i_ = 0; i_ < 4; i_++) {                                               \
        _Pragma("unroll")                                                         \
        for (int j_ = 0; j_ < 8; j_++) {                                           \
            mma16816(acc[i_][j_], ah[i_], &bh[j_ >> 1][(j_ & 1) * 2]);             \
        }                                                                         \
    }                                                                             \
} while (0)

template <int MODE>
__global__ __launch_bounds__(128, 2)
void hmma_gemm_b2(const __half* __restrict__ A, const __half* __restrict__ B,
                  const float* __restrict__ bias, int K, int Nn,
                  __half* __restrict__ Ch, __half* __restrict__ Cl,
                  float* __restrict__ Cf)
{
    extern __shared__ __align__(1024) char smem[];
    const uint32_t sb = smem_u32(smem);
    const int tid = threadIdx.x;
    const int lane = tid & 31, wid = tid >> 5;
    const int wm = wid >> 1, wn = wid & 1;
    const int mrow0 = blockIdx.y * 128;
    const int ncol0 = blockIdx.x * 128;
    const int nt = K / 64;

    #define B2LOADT(s, kt) do {                                                  \
        const uint32_t st_ = sb + (uint32_t)(s) * B2STG;                          \
        _Pragma("unroll")                                                         \
        for (int i_ = 0; i_ < 8; i_++) {                                          \
            const int slot_ = tid + 128 * i_;                                     \
            const int row_ = slot_ >> 3, ch_ = slot_ & 7;                         \
            const size_t go_ = (size_t)(kt) * 64 + ch_ * 8;                       \
            cp16(st_ + B2OFF_A + swz128(row_, ch_),                               \
                 A + (size_t)(mrow0 + row_) * K + go_);                           \
            cp16(st_ + B2OFF_B + swz128(row_, ch_),                               \
                 B + (size_t)(ncol0 + row_) * K + go_);                           \
        }                                                                         \
        CP_COMMIT();                                                              \
    } while (0)

    B2LOADT(0, 0);
    B2LOADT(1, 1);

    float acc[4][8][4];
    #pragma unroll
    for (int i = 0; i < 4; i++) {
        #pragma unroll
        for (int j = 0; j < 8; j++) {
            #pragma unroll
            for (int q = 0; q < 4; q++) { acc[i][j][q] = 0.0f; }
        }
    }

    const int arow = (lane & 7) | (((lane >> 3) & 1) << 3);
    const int ach  = lane >> 4;
    const int brow = (lane & 7) | (((lane >> 4) & 1) << 3);
    const int bch  = (lane >> 3) & 1;

    uint32_t ah[4][4], bh[4][4];

    for (int kt = 0; kt < nt; kt++) {
        if (kt + 1 < nt) { CP_WAIT(1); } else { CP_WAIT(0); }
        __syncthreads();
        if (kt + 2 < nt) { B2LOADT((kt + 2) % 3, kt + 2); }

        const uint32_t st = sb + (uint32_t)(kt % 3) * B2STG;
        #pragma unroll
        for (int s16 = 0; s16 < 4; s16++) {
            B2LDFRAG(st, s16);
            B2DOMMA();
        }
    }

    #pragma unroll
    for (int i = 0; i < 4; i++) {
        const int rb = mrow0 + wm * 64 + i * 16 + (lane >> 2);
        #pragma unroll
        for (int h = 0; h < 2; h++) {
            const int row = rb + h * 8;
            #pragma unroll
            for (int j = 0; j < 8; j++) {
                const int col = ncol0 + wn * 64 + j * 8 + (lane & 3) * 2;
                const float2 b2 = *(const float2*)(bias + col);
                float v0 = acc[i][j][h * 2 + 0] + b2.x;
                float v1 = acc[i][j][h * 2 + 1] + b2.y;
                if (MODE == 0) {
                    v0 = fmaxf(v0, 0.0f); v1 = fmaxf(v1, 0.0f);
                    __half h0, l0, h1, l1;
                    splitf(v0, h0, l0); splitf(v1, h1, l1);
                    *(__half2*)(Ch + (size_t)row * Nn + col) = __halves2half2(h0, h1);
                    *(__half2*)(Cl + (size_t)row * Nn + col) = __halves2half2(l0, l1);
                } else if (MODE == 1) {
                    *(__half2*)(Ch + (size_t)row * Nn + col) =
                        __halves2half2(__float2half_rn(v0), __float2half_rn(v1));
                } else {
                    *(float2*)(Cf + (size_t)row * Nn + col) = make_float2(v0, v1);
                }
            }
        }
    }
    #undef B2LOADT
}

// ===========================================================================
// Grouped expert GEMM (1-pass small-CTA): A rows via g_perm;
// epilogue: g_uh[tok] = fp16(uh_raw[tok]*s1[tok] + (acc + b_e)*s0[tok])
// ===========================================================================
__global__ __launch_bounds__(128, 2)
void hmma_gemm_grouped_b2(const float* __restrict__ bexp)
{
    extern __shared__ __align__(1024) char smem[];
    const int e = blockIdx.z;
    const int cnt = g_counts[e];
    const int rowBase = blockIdx.y * 128;
    if (rowBase >= cnt) return;

    const uint32_t sb = smem_u32(smem);
    const int tid = threadIdx.x;
    const int lane = tid & 31, wid = tid >> 5;
    const int wm = wid >> 1, wn = wid & 1;
    const int ncol0 = blockIdx.x * 128;
    const int nt = HID / 64;
    int* rmap = (int*)(smem + B2_RMAP);

    {
        int i = rowBase + tid;
        if (i > cnt - 1) i = cnt - 1;
        rmap[tid] = g_perm[e * N_TOK + i];
    }
    __syncthreads();

    const __half* B = g_Whi + W_EXP_OFF + (size_t)e * HID * HID;

    size_t ga[8];
    #pragma unroll
    for (int i = 0; i < 8; i++) {
        ga[i] = (size_t)rmap[(tid + 128 * i) >> 3] * HID;
    }

    #define G2LOADT(s, kt) do {                                                  \
        const uint32_t st_ = sb + (uint32_t)(s) * B2STG;                          \
        _Pragma("unroll")                                                         \
        for (int i_ = 0; i_ < 8; i_++) {                                          \
            const int slot_ = tid + 128 * i_;                                     \
            const int row_ = slot_ >> 3, ch_ = slot_ & 7;                         \
            const size_t go_ = (size_t)(kt) * 64 + ch_ * 8;                       \
            cp16(st_ + B2OFF_A + swz128(row_, ch_), g_hhi + ga[i_] + go_);        \
            cp16(st_ + B2OFF_B + swz128(row_, ch_),                               \
                 B + (size_t)(ncol0 + row_) * HID + go_);                         \
        }                                                                         \
        CP_COMMIT();                                                              \
    } while (0)

    G2LOADT(0, 0);
    G2LOADT(1, 1);

    float acc[4][8][4];
    #pragma unroll
    for (int i = 0; i < 4; i++) {
        #pragma unroll
        for (int j = 0; j < 8; j++) {
            #pragma unroll
            for (int q = 0; q < 4; q++) { acc[i][j][q] = 0.0f; }
        }
    }

    const int arow = (lane & 7) | (((lane >> 3) & 1) << 3);
    const int ach  = lane >> 4;
    const int brow = (lane & 7) | (((lane >> 4) & 1) << 3);
    const int bch  = (lane >> 3) & 1;

    uint32_t ah[4][4], bh[4][4];

    for (int kt = 0; kt < nt; kt++) {
        if (kt + 1 < nt) { CP_WAIT(1); } else { CP_WAIT(0); }
        __syncthreads();
        if (kt + 2 < nt) { G2LOADT((kt + 2) % 3, kt + 2); }

        const uint32_t st = sb + (uint32_t)(kt % 3) * B2STG;
        #pragma unroll
        for (int s16 = 0; s16 < 4; s16++) {
            B2LDFRAG(st, s16);
            B2DOMMA();
        }
    }

    #pragma unroll
    for (int i = 0; i < 4; i++) {
        const int lb = wm * 64 + i * 16 + (lane >> 2);
        #pragma unroll
        for (int h = 0; h < 2; h++) {
            const int li = lb + h * 8;
            if (rowBase + li >= cnt) continue;
            const int tok = rmap[li];
            const float s0 = g_s0[tok];
            const float s1 = g_s1[tok];
            #pragma unroll
            for (int j = 0; j < 8; j++) {
                const int col = ncol0 + wn * 64 + j * 8 + (lane & 3) * 2;
                const float2 b2 = *(const float2*)(bexp + e * HID + col);
                float2 u2 = __half22float2(*(const __half2*)(g_uh + (size_t)tok * HID + col));
                float v0 = u2.x * s1 + (acc[i][j][h * 2 + 0] + b2.x) * s0;
                float v1 = u2.y * s1 + (acc[i][j][h * 2 + 1] + b2.y) * s0;
                *(__half2*)(g_uh + (size_t)tok * HID + col) =
                    __halves2half2(__float2half_rn(v0), __float2half_rn(v1));
            }
        }
    }
    #undef G2LOADT
}

// ===========================================================================
// Flag-repair GEMM (two-phase): Δh[fi,:] = xlo[f]@Whi_enc^T + xhi[f]@Wlo^T.
// Gathered A rows via g_flag; total K = 2*IN_DIM (phase switch at kt=16).
// ===========================================================================
__global__ __launch_bounds__(128, 2)
void hmma_gemm_flag()
{
    extern __shared__ __align__(1024) char smem[];
    const int F = g_nflag;
    const int rowBase = blockIdx.y * 128;
    if (rowBase >= F) return;

    const uint32_t sb = smem_u32(smem);
    const int tid = threadIdx.x;
    const int lane = tid & 31, wid = tid >> 5;
    const int wm = wid >> 1, wn = wid & 1;
    const int ncol0 = blockIdx.x * 128;
    const int nt = 2 * (IN_DIM / 64);   // 32: phase 0 = xlo@Whi, phase 1 = xhi@Wlo
    int* rmap = (int*)(smem + B2_RMAP);

    {
        int i = rowBase + tid;
        if (i > F - 1) i = F - 1;
        rmap[tid] = g_flag[i];
    }
    __syncthreads();

    size_t ga[8];
    #pragma unroll
    for (int i = 0; i < 8; i++) {
        ga[i] = (size_t)rmap[(tid + 128 * i) >> 3] * IN_DIM;
    }

    #define FLOADT(s, kt) do {                                                   \
        const uint32_t st_ = sb + (uint32_t)(s) * B2STG;                          \
        const __half* Ab_ = ((kt) < 16) ? g_xlo : g_xhi;                          \
        const __half* Bb_ = ((kt) < 16) ? (g_Whi + W_ENC_OFF) : g_Wlo;            \
        const int kk_ = (kt) & 15;                                                \
        _Pragma("unroll")                                                         \
        for (int i_ = 0; i_ < 8; i_++) {                                          \
            const int slot_ = tid + 128 * i_;                                     \
            const int row_ = slot_ >> 3, ch_ = slot_ & 7;                         \
            const size_t go_ = (size_t)kk_ * 64 + ch_ * 8;                        \
            cp16(st_ + B2OFF_A + swz128(row_, ch_), Ab_ + ga[i_] + go_);          \
            cp16(st_ + B2OFF_B + swz128(row_, ch_),                               \
                 Bb_ + (size_t)(ncol0 + row_) * IN_DIM + go_);                    \
        }                                                                         \
        CP_COMMIT();                                                              \
    } while (0)

    FLOADT(0, 0);
    FLOADT(1, 1);

    float acc[4][8][4];
    #pragma unroll
    for (int i = 0; i < 4; i++) {
        #pragma unroll
        for (int j = 0; j < 8; j++) {
            #pragma unroll
            for (int q = 0; q < 4; q++) { acc[i][j][q] = 0.0f; }
        }
    }

    const int arow = (lane & 7) | (((lane >> 3) & 1) << 3);
    const int ach  = lane >> 4;
    const int brow = (lane & 7) | (((lane >> 4) & 1) << 3);
    const int bch  = (lane >> 3) & 1;

    uint32_t ah[4][4], bh[4][4];

    for (int kt = 0; kt < nt; kt++) {
        if (kt + 1 < nt) { CP_WAIT(1); } else { CP_WAIT(0); }
        __syncthreads();
        if (kt + 2 < nt) { FLOADT((kt + 2) % 3, kt + 2); }

        const uint32_t st = sb + (uint32_t)(kt % 3) * B2STG;
        #pragma unroll
        for (int s16 = 0; s16 < 4; s16++) {
            B2LDFRAG(st, s16);
            B2DOMMA();
        }
    }

    #pragma unroll
    for (int i = 0; i < 4; i++) {
        const int lb = wm * 64 + i * 16 + (lane >> 2);
        #pragma unroll
        for (int h = 0; h < 2; h++) {
            const int li = lb + h * 8;
            if (rowBase + li >= F) continue;
            const size_t fo = (size_t)(rowBase + li) * HID;
            #pragma unroll
            for (int j = 0; j < 8; j++) {
                const int col = ncol0 + wn * 64 + j * 8 + (lane & 3) * 2;
                *(__half2*)(g_dh + fo + col) =
                    __halves2half2(__float2half_rn(acc[i][j][h * 2 + 0]),
                                   __float2half_rn(acc[i][j][h * 2 + 1]));
            }
        }
    }
    #undef FLOADT
}

// ---------------------------------------------------------------------------
extern "C" void kernel_launch(void* const* d_in, const int* in_sizes, int n_in,
                              void* d_out, int out_size)
{
    const float* x        = (const float*)d_in[0];
    const float* enc_W    = (const float*)d_in[1];
    const float* enc_b    = (const float*)d_in[2];
    const float* gate_W   = (const float*)d_in[3];
    const float* expert_W = (const float*)d_in[4];
    const float* expert_b = (const float*)d_in[5];
    const float* res_W    = (const float*)d_in[6];
    const float* res_b    = (const float*)d_in[7];
    const float* coef_W   = (const float*)d_in[8];
    const float* coef_b   = (const float*)d_in[9];
    const float* dec_W    = (const float*)d_in[10];
    const float* dec_b    = (const float*)d_in[11];
    float* out = (float*)d_out;

    __half *xhi, *xlo, *hhi, *hlo, *uh, *whi, *wlo;
    cudaGetSymbolAddress((void**)&xhi, g_xhi);
    cudaGetSymbolAddress((void**)&xlo, g_xlo);
    cudaGetSymbolAddress((void**)&hhi, g_hhi);
    cudaGetSymbolAddress((void**)&hlo, g_hlo);
    cudaGetSymbolAddress((void**)&uh,  g_uh);
    cudaGetSymbolAddress((void**)&whi, g_Whi);
    cudaGetSymbolAddress((void**)&wlo, g_Wlo);

    cudaFuncSetAttribute((const void*)hmma_gemm_b2<0>,      cudaFuncAttributeMaxDynamicSharedMemorySize, B2SMEM_TOT);
    cudaFuncSetAttribute((const void*)hmma_gemm_b2<1>,      cudaFuncAttributeMaxDynamicSharedMemorySize, B2SMEM_TOT);
    cudaFuncSetAttribute((const void*)hmma_gemm_b2<2>,      cudaFuncAttributeMaxDynamicSharedMemorySize, B2SMEM_TOT);
    cudaFuncSetAttribute((const void*)hmma_gemm_grouped_b2, cudaFuncAttributeMaxDynamicSharedMemorySize, B2SMEM_TOT);
    cudaFuncSetAttribute((const void*)hmma_gemm_flag,       cudaFuncAttributeMaxDynamicSharedMemorySize, B2SMEM_TOT);

    // side stream + events (lazy init; host-side only)
    static cudaStream_t s2 = nullptr;
    static cudaEvent_t evF = nullptr, evJ = nullptr, evE = nullptr, evG = nullptr, evT = nullptr;
    if (!s2) {
        cudaStreamCreateWithFlags(&s2, cudaStreamNonBlocking);
        cudaEventCreateWithFlags(&evF, cudaEventDisableTiming);
        cudaEventCreateWithFlags(&evJ, cudaEventDisableTiming);
        cudaEventCreateWithFlags(&evE, cudaEventDisableTiming);
        cudaEventCreateWithFlags(&evG, cudaEventDisableTiming);
        cudaEventCreateWithFlags(&evT, cudaEventDisableTiming);
    }

    // fork side stream immediately: enc transpose runs concurrent with conv_x
    cudaEventRecord(evF, 0);
    cudaStreamWaitEvent(s2, evF, 0);
    transpose_conv<<<dim3(HID/32, IN_DIM/32, 1), dim3(32, 8), 0, s2>>>(enc_W, whi + W_ENC_OFF, wlo, IN_DIM, HID);
    cudaEventRecord(evT, s2);
    transpose_conv<<<dim3(HID/32, HID/32, 1),    dim3(32, 8), 0, s2>>>(res_W, whi + W_RES_OFF, nullptr, HID, HID);

    // main stream: x split (+ zero counts/flags)
    conv_x_kernel<<<(N_TOK * IN_DIM) / 1024, 256>>>(x);

    // enc GEMM (1-pass xhi@Whi, 2 CTA/SM) — waits for enc transpose
    cudaStreamWaitEvent(0, evT, 0);
    hmma_gemm_b2<0><<<dim3(HID/128, N_TOK/128), 128, B2SMEM_TOT>>>(
        xhi, whi + W_ENC_OFF, enc_b, IN_DIM, HID, hhi, hlo, nullptr);
    cudaEventRecord(evE, 0);

    // remaining weight transposes on side stream (overlap enc execution)
    transpose_conv<<<dim3(HID/32, HID/32, NEXP), dim3(32, 8), 0, s2>>>(expert_W, whi + W_EXP_OFF, nullptr, HID, HID);
    transpose_conv<<<dim3(IN_DIM/32, HID/32, 1), dim3(32, 8), 0, s2>>>(dec_W,    whi + W_DEC_OFF, nullptr, HID, IN_DIM);
    cudaEventRecord(evJ, s2);

    // gating chain on side stream (concurrent with res GEMM):
    // gating2p -> flag GEMM (Δh, two-phase) -> regate (corrected argmax)
    cudaStreamWaitEvent(s2, evE, 0);
    gating2p_kernel<<<N_TOK, 128, 0, s2>>>(gate_W, coef_W, coef_b);
    hmma_gemm_flag<<<dim3(HID/128, N_TOK/128), 128, B2SMEM_TOT, s2>>>();
    regate_kernel<<<N_TOK, 128, 0, s2>>>(gate_W);
    cudaEventRecord(evG, s2);

    // join weight transposes, then res (unscaled) on main stream
    cudaStreamWaitEvent(0, evJ, 0);

    // uh_raw = h @ res_W + res_b : 1-pass 128x128 (2 CTA/SM) -> fp16
    hmma_gemm_b2<1><<<dim3(HID/128, N_TOK/128), 128, B2SMEM_TOT>>>(
        hhi, whi + W_RES_OFF, res_b, HID, HID, uh, nullptr, nullptr);

    // join gating chain, then grouped: uh = uh_raw*s1 + (h @ W_e + b_e)*s0
    cudaStreamWaitEvent(0, evG, 0);
    hmma_gemm_grouped_b2<<<dim3(HID/128, N_TOK/128, NEXP), 128, B2SMEM_TOT>>>(expert_b);

    // out = uh @ dec_W + dec_b : 1-pass 128x128 (2 CTA/SM) -> fp32
    hmma_gemm_b2<2><<<dim3(IN_DIM/128, N_TOK/128), 128, B2SMEM_TOT>>>(
        uh, whi + W_DEC_OFF, dec_b, HID, IN_DIM, nullptr, nullptr, out);
}